// round 1
// baseline (speedup 1.0000x reference)
#include <cuda_runtime.h>
#include <cuda_bf16.h>
#include <math.h>

typedef unsigned long long ull;

#define NMAX 50000
#define EMAX 1600000

// ---------------- device scratch (no allocations allowed) ----------------
__device__ float g_tx1[(size_t)NMAX * 128];
__device__ float g_tx2[(size_t)NMAX * 128];
__device__ float g_ha[(size_t)NMAX * 64];
__device__ float g_hb[(size_t)NMAX * 64];
__device__ float g_z[(size_t)NMAX * 256];
__device__ float g_norm[EMAX];
__device__ float g_deg[NMAX];
__device__ float g_w2f[128 * 128];
__device__ float g_b2f[128];
__device__ float g_cw2[256 * 2];
__device__ float g_cb2[2];

// ---------------- f32x2 helpers (sm_103a packed fp32 FMA) ----------------
__device__ __forceinline__ ull pk2(float x, float y) {
    ull r; asm("mov.b64 %0, {%1,%2};" : "=l"(r) : "f"(x), "f"(y)); return r;
}
__device__ __forceinline__ ull fma2(ull a, ull b, ull c) {
    ull d; asm("fma.rn.f32x2 %0, %1, %2, %3;" : "=l"(d) : "l"(a), "l"(b), "l"(c)); return d;
}
__device__ __forceinline__ float2 upk(ull a) {
    float2 v; asm("mov.b64 {%0,%1}, %2;" : "=f"(v.x), "=f"(v.y) : "l"(a)); return v;
}

// ---------------- BN folding kernels ----------------
// PAE: o = bn(relu(z@w1+b1)) @ w2 + b2  ==  relu(z@w1+b1) @ (s[i]*w2[i][j]) + (b2[j] + sum_i t[i]*w2[i][j])
__global__ void fold_pae_kernel(const float* __restrict__ g, const float* __restrict__ b,
                                const float* __restrict__ rm, const float* __restrict__ rv,
                                const float* __restrict__ w2, const float* __restrict__ b2,
                                float* __restrict__ w2f, float* __restrict__ b2f) {
    __shared__ float s[128], t[128];
    int j = threadIdx.x;  // 128 threads
    float sj = g[j] * rsqrtf(rv[j] + 1e-5f);
    s[j] = sj;
    t[j] = b[j] - rm[j] * sj;
    __syncthreads();
    for (int idx = j; idx < 128 * 128; idx += 128) {
        int i = idx >> 7;
        w2f[idx] = s[i] * w2[idx];
    }
    float acc = b2[j];
    for (int i = 0; i < 128; i++) acc += t[i] * w2[i * 128 + j];
    b2f[j] = acc;
}

// classifier: logit = bn(relu(jk@w1+b1)) @ w2 + b2 -> fold bn into w2/b2
__global__ void fold_cls_kernel(const float* __restrict__ g, const float* __restrict__ b,
                                const float* __restrict__ rm, const float* __restrict__ rv,
                                const float* __restrict__ w2, const float* __restrict__ b2,
                                float* __restrict__ cw2, float* __restrict__ cb2) {
    __shared__ float t[256];
    int i = threadIdx.x;  // 256 threads
    float si = g[i] * rsqrtf(rv[i] + 1e-5f);
    t[i] = b[i] - rm[i] * si;
    cw2[2 * i]     = si * w2[2 * i];
    cw2[2 * i + 1] = si * w2[2 * i + 1];
    __syncthreads();
    if (i < 2) {
        float acc = b2[i];
        for (int k = 0; k < 256; k++) acc += t[k] * w2[2 * k + i];
        cb2[i] = acc;
    }
}

// ---------------- PAE main kernel ----------------
// per warp iteration: 4 edges = 8 halves. h[128] per half in smem,
// then o = h @ W2f via f32x2 FMAs (lane owns 4 output columns), cosine reduce.
#define PAE_BLK 256
__global__ void pae_kernel(const float* __restrict__ edgenet,
                           const float* __restrict__ w1, const float* __restrict__ b1,
                           const float* __restrict__ w2f, const float* __restrict__ b2f,
                           float* __restrict__ ew, int E) {
    extern __shared__ float sm[];
    float* s_w2f = sm;             // 16384
    float* s_w1  = sm + 16384;     // 768
    float* s_b1  = sm + 17152;     // 128
    float* s_b2f = sm + 17280;     // 128
    float* s_h   = sm + 17408;     // 8 warps * 1024

    int tid = threadIdx.x;
    for (int i = tid; i < 16384; i += PAE_BLK) s_w2f[i] = w2f[i];
    for (int i = tid; i < 768; i += PAE_BLK) s_w1[i] = w1[i];
    if (tid < 128) { s_b1[tid] = b1[tid]; s_b2f[tid] = b2f[tid]; }
    __syncthreads();

    int lane = tid & 31, wid = tid >> 5;
    float* hw = s_h + wid * 1024;

    float w1r[6][4], b1r[4];
#pragma unroll
    for (int r = 0; r < 4; r++) {
        b1r[r] = s_b1[lane + 32 * r];
#pragma unroll
        for (int k = 0; k < 6; k++) w1r[k][r] = s_w1[k * 128 + lane + 32 * r];
    }
    float4 bv = *(const float4*)(s_b2f + 4 * lane);

    int nGroups = (E + 3) >> 2;
    int gw = blockIdx.x * (PAE_BLK / 32) + wid;
    int stride = gridDim.x * (PAE_BLK / 32);

    for (int gidx = gw; gidx < nGroups; gidx += stride) {
        // ---- compute h for 8 halves ----
#pragma unroll
        for (int hh = 0; hh < 8; ++hh) {
            int e = gidx * 4 + (hh >> 1);
            if (e >= E) e = E - 1;
            const float* zp = edgenet + (size_t)e * 12 + (hh & 1) * 6;
            float zr[6];
#pragma unroll
            for (int k = 0; k < 6; k++) zr[k] = __ldg(zp + k);
#pragma unroll
            for (int r = 0; r < 4; r++) {
                float a = b1r[r];
#pragma unroll
                for (int k = 0; k < 6; k++) a = fmaf(zr[k], w1r[k][r], a);
                hw[hh * 128 + lane + 32 * r] = fmaxf(a, 0.f);
            }
        }
        __syncwarp();

        // ---- o = h @ W2f, lane owns cols 4*lane..4*lane+3 ----
        ull acc[16];
#pragma unroll
        for (int i = 0; i < 16; i++) acc[i] = 0ull;
#pragma unroll 4
        for (int i = 0; i < 128; i++) {
            float4 w = *(const float4*)(s_w2f + i * 128 + (lane << 2));
            ull wl = pk2(w.x, w.y), whp = pk2(w.z, w.w);
#pragma unroll
            for (int hh = 0; hh < 8; hh++) {
                float hv = hw[hh * 128 + i];
                ull hp = pk2(hv, hv);
                acc[2 * hh]     = fma2(hp, wl,  acc[2 * hh]);
                acc[2 * hh + 1] = fma2(hp, whp, acc[2 * hh + 1]);
            }
        }
        __syncwarp();

        // ---- cosine per edge ----
#pragma unroll
        for (int e4 = 0; e4 < 4; e4++) {
            float2 a = upk(acc[4 * e4]);
            float2 bq = upk(acc[4 * e4 + 1]);
            float2 c = upk(acc[4 * e4 + 2]);
            float2 d = upk(acc[4 * e4 + 3]);
            float o1x = a.x + bv.x, o1y = a.y + bv.y, o1z = bq.x + bv.z, o1w = bq.y + bv.w;
            float o2x = c.x + bv.x, o2y = c.y + bv.y, o2z = d.x + bv.z, o2w = d.y + bv.w;
            float pn = o1x * o2x + o1y * o2y + o1z * o2z + o1w * o2w;
            float p1 = o1x * o1x + o1y * o1y + o1z * o1z + o1w * o1w;
            float p2 = o2x * o2x + o2y * o2y + o2z * o2z + o2w * o2w;
#pragma unroll
            for (int off = 16; off; off >>= 1) {
                pn += __shfl_xor_sync(0xffffffffu, pn, off);
                p1 += __shfl_xor_sync(0xffffffffu, p1, off);
                p2 += __shfl_xor_sync(0xffffffffu, p2, off);
            }
            if (lane == 0) {
                int eidx = gidx * 4 + e4;
                if (eidx < E) {
                    float den = fmaxf(sqrtf(p1) * sqrtf(p2), 1e-8f);
                    ew[eidx] = fmaf(pn / den, 0.5f, 0.5f);
                }
            }
        }
    }
}

// ---------------- graph-normalization kernels ----------------
__global__ void deg_kernel(const float* __restrict__ ew, const int* __restrict__ row,
                           float* __restrict__ deg, int E) {
    int e = blockIdx.x * blockDim.x + threadIdx.x;
    if (e < E) atomicAdd(&deg[row[e]], ew[e]);
}

__global__ void dis_kernel(float* __restrict__ deg, int N) {
    int i = blockIdx.x * blockDim.x + threadIdx.x;
    if (i < N) {
        float d = deg[i];
        deg[i] = (d > 0.f) ? rsqrtf(d) : 0.f;
    }
}

__global__ void norm_kernel(const float* __restrict__ ew, const int* __restrict__ row,
                            const int* __restrict__ col, const float* __restrict__ dis,
                            float* __restrict__ nrm, int E) {
    int e = blockIdx.x * blockDim.x + threadIdx.x;
    if (e < E) nrm[e] = -dis[row[e]] * ew[e] * dis[col[e]];
}

// ---------------- SpMM: out[row] += norm * x[col], vector reductions ----------------
__global__ void spmm_kernel(const float* __restrict__ x, float* __restrict__ out,
                            const int* __restrict__ row, const int* __restrict__ col,
                            const float* __restrict__ nrm, int E, int F, int lgF4) {
    int gid = blockIdx.x * blockDim.x + threadIdx.x;
    int e = gid >> lgF4;
    if (e >= E) return;
    int c = gid & ((1 << lgF4) - 1);
    float w = __ldg(nrm + e);
    int cs = __ldg(col + e);
    int rs = __ldg(row + e);
    const float4 xv = *(const float4*)(x + (size_t)cs * F + c * 4);
    float a = w * xv.x, b = w * xv.y, cc = w * xv.z, d = w * xv.w;
    float* dst = out + (size_t)rs * F + c * 4;
    asm volatile("red.global.add.v4.f32 [%0], {%1,%2,%3,%4};"
                 :: "l"(dst), "f"(a), "f"(b), "f"(cc), "f"(d) : "memory");
}

// Tx2 = 2*lhat(Tx1) - Tx0
__global__ void fixup_kernel(float* __restrict__ tx2, const float* __restrict__ tx0, int n) {
    int i = blockIdx.x * blockDim.x + threadIdx.x;
    if (i < n) tx2[i] = 2.f * tx2[i] - tx0[i];
}

// ---------------- dense GEMMs ----------------
// h = relu(Tx0@W0 + Tx1@W1 + Tx2@W2), W = [3][K][64]; write to hbuf and jk columns
__global__ void cheb_gemm(const float* __restrict__ A0, const float* __restrict__ A1,
                          const float* __restrict__ A2, const float* __restrict__ W,
                          int K, int N, float* __restrict__ hout, float* __restrict__ jkout) {
    __shared__ float As[16][64];
    __shared__ float Ws[16][64];
    int tid = threadIdx.x;
    int tx = tid & 15, ty = tid >> 4;
    int r0 = blockIdx.x * 64;
    float acc[4][4] = {};
    const float* Aps[3] = {A0, A1, A2};
    for (int p = 0; p < 3; p++) {
        const float* Ap = Aps[p];
        const float* Wp = W + (size_t)p * K * 64;
        for (int k0 = 0; k0 < K; k0 += 16) {
            __syncthreads();
            for (int i = tid; i < 1024; i += 256) {
                int rr = i >> 4, kk = i & 15;
                int gr = r0 + rr;
                As[kk][rr] = (gr < N) ? Ap[(size_t)gr * K + k0 + kk] : 0.f;
            }
            for (int i = tid; i < 1024; i += 256) {
                int kk = i >> 6, cc = i & 63;
                Ws[kk][cc] = Wp[(size_t)(k0 + kk) * 64 + cc];
            }
            __syncthreads();
#pragma unroll
            for (int kk = 0; kk < 16; kk++) {
                float a0 = As[kk][ty * 4 + 0], a1 = As[kk][ty * 4 + 1];
                float a2 = As[kk][ty * 4 + 2], a3 = As[kk][ty * 4 + 3];
                float w0 = Ws[kk][tx * 4 + 0], w1v = Ws[kk][tx * 4 + 1];
                float w2v = Ws[kk][tx * 4 + 2], w3 = Ws[kk][tx * 4 + 3];
                acc[0][0] += a0 * w0; acc[0][1] += a0 * w1v; acc[0][2] += a0 * w2v; acc[0][3] += a0 * w3;
                acc[1][0] += a1 * w0; acc[1][1] += a1 * w1v; acc[1][2] += a1 * w2v; acc[1][3] += a1 * w3;
                acc[2][0] += a2 * w0; acc[2][1] += a2 * w1v; acc[2][2] += a2 * w2v; acc[2][3] += a2 * w3;
                acc[3][0] += a3 * w0; acc[3][1] += a3 * w1v; acc[3][2] += a3 * w2v; acc[3][3] += a3 * w3;
            }
        }
    }
#pragma unroll
    for (int r = 0; r < 4; r++) {
        int rowi = r0 + ty * 4 + r;
        if (rowi < N) {
#pragma unroll
            for (int c = 0; c < 4; c++) {
                int coli = tx * 4 + c;
                float v = fmaxf(acc[r][c], 0.f);
                hout[(size_t)rowi * 64 + coli] = v;
                jkout[(size_t)rowi * 256 + coli] = v;
            }
        }
    }
}

// z = relu(jk@W1 + b1), K=256, M=256, A stride 256
__global__ void cls_gemm(const float* __restrict__ A, const float* __restrict__ W,
                         const float* __restrict__ bias, int N, float* __restrict__ out) {
    __shared__ float As[16][64];
    __shared__ float Ws[16][64];
    int tid = threadIdx.x;
    int tx = tid & 15, ty = tid >> 4;
    int r0 = blockIdx.x * 64;
    int c0 = blockIdx.y * 64;
    float acc[4][4] = {};
    for (int k0 = 0; k0 < 256; k0 += 16) {
        __syncthreads();
        for (int i = tid; i < 1024; i += 256) {
            int rr = i >> 4, kk = i & 15;
            int gr = r0 + rr;
            As[kk][rr] = (gr < N) ? A[(size_t)gr * 256 + k0 + kk] : 0.f;
        }
        for (int i = tid; i < 1024; i += 256) {
            int kk = i >> 6, cc = i & 63;
            Ws[kk][cc] = W[(size_t)(k0 + kk) * 256 + c0 + cc];
        }
        __syncthreads();
#pragma unroll
        for (int kk = 0; kk < 16; kk++) {
            float a0 = As[kk][ty * 4 + 0], a1 = As[kk][ty * 4 + 1];
            float a2 = As[kk][ty * 4 + 2], a3 = As[kk][ty * 4 + 3];
            float w0 = Ws[kk][tx * 4 + 0], w1v = Ws[kk][tx * 4 + 1];
            float w2v = Ws[kk][tx * 4 + 2], w3 = Ws[kk][tx * 4 + 3];
            acc[0][0] += a0 * w0; acc[0][1] += a0 * w1v; acc[0][2] += a0 * w2v; acc[0][3] += a0 * w3;
            acc[1][0] += a1 * w0; acc[1][1] += a1 * w1v; acc[1][2] += a1 * w2v; acc[1][3] += a1 * w3;
            acc[2][0] += a2 * w0; acc[2][1] += a2 * w1v; acc[2][2] += a2 * w2v; acc[2][3] += a2 * w3;
            acc[3][0] += a3 * w0; acc[3][1] += a3 * w1v; acc[3][2] += a3 * w2v; acc[3][3] += a3 * w3;
        }
    }
#pragma unroll
    for (int r = 0; r < 4; r++) {
        int rowi = r0 + ty * 4 + r;
        if (rowi < N) {
#pragma unroll
            for (int c = 0; c < 4; c++) {
                int coli = c0 + tx * 4 + c;
                out[(size_t)rowi * 256 + coli] = fmaxf(acc[r][c] + bias[coli], 0.f);
            }
        }
    }
}

// logit = z @ cw2 + cb2, one warp per node
__global__ void logit_kernel(const float* __restrict__ z, const float* __restrict__ cw2,
                             const float* __restrict__ cb2, int N, float* __restrict__ out) {
    int gw = (blockIdx.x * blockDim.x + threadIdx.x) >> 5;
    int lane = threadIdx.x & 31;
    if (gw >= N) return;
    const float* zr = z + (size_t)gw * 256;
    float a0 = 0.f, a1 = 0.f;
    for (int i = lane; i < 256; i += 32) {
        float v = zr[i];
        a0 += v * cw2[2 * i];
        a1 += v * cw2[2 * i + 1];
    }
#pragma unroll
    for (int off = 16; off; off >>= 1) {
        a0 += __shfl_xor_sync(0xffffffffu, a0, off);
        a1 += __shfl_xor_sync(0xffffffffu, a1, off);
    }
    if (lane == 0) {
        out[(size_t)gw * 2 + 0] = a0 + cb2[0];
        out[(size_t)gw * 2 + 1] = a1 + cb2[1];
    }
}

// ---------------- launcher ----------------
extern "C" void kernel_launch(void* const* d_in, const int* in_sizes, int n_in,
                              void* d_out, int out_size) {
    const float* features = (const float*)d_in[0];
    const int* edge_index = (const int*)d_in[1];
    const float* edgenet  = (const float*)d_in[2];
    const float* pae_w1 = (const float*)d_in[3];
    const float* pae_b1 = (const float*)d_in[4];
    const float* pae_bn_g = (const float*)d_in[5];
    const float* pae_bn_b = (const float*)d_in[6];
    const float* pae_bn_rm = (const float*)d_in[7];
    const float* pae_bn_rv = (const float*)d_in[8];
    const float* pae_w2 = (const float*)d_in[9];
    const float* pae_b2 = (const float*)d_in[10];
    const float* cheb_w[4] = {(const float*)d_in[11], (const float*)d_in[12],
                              (const float*)d_in[13], (const float*)d_in[14]};
    const float* cls_w1 = (const float*)d_in[15];
    const float* cls_b1 = (const float*)d_in[16];
    const float* cls_bn_g = (const float*)d_in[17];
    const float* cls_bn_b = (const float*)d_in[18];
    const float* cls_bn_rm = (const float*)d_in[19];
    const float* cls_bn_rv = (const float*)d_in[20];
    const float* cls_w2 = (const float*)d_in[21];
    const float* cls_b2 = (const float*)d_in[22];

    int N = in_sizes[0] / 128;
    int E = in_sizes[1] / 2;
    const int* row = edge_index;
    const int* col = edge_index + E;

    float* out = (float*)d_out;
    float* jk = out;
    float* logit = out + (size_t)N * 256;
    float* ew = logit + (size_t)N * 2;

    float *tx1, *tx2, *ha, *hb, *zbuf, *nrm, *deg, *w2f, *b2f, *cw2, *cb2;
    cudaGetSymbolAddress((void**)&tx1, g_tx1);
    cudaGetSymbolAddress((void**)&tx2, g_tx2);
    cudaGetSymbolAddress((void**)&ha, g_ha);
    cudaGetSymbolAddress((void**)&hb, g_hb);
    cudaGetSymbolAddress((void**)&zbuf, g_z);
    cudaGetSymbolAddress((void**)&nrm, g_norm);
    cudaGetSymbolAddress((void**)&deg, g_deg);
    cudaGetSymbolAddress((void**)&w2f, g_w2f);
    cudaGetSymbolAddress((void**)&b2f, g_b2f);
    cudaGetSymbolAddress((void**)&cw2, g_cw2);
    cudaGetSymbolAddress((void**)&cb2, g_cb2);

    cudaFuncSetAttribute(pae_kernel, cudaFuncAttributeMaxDynamicSharedMemorySize, 102400);

    fold_pae_kernel<<<1, 128>>>(pae_bn_g, pae_bn_b, pae_bn_rm, pae_bn_rv, pae_w2, pae_b2, w2f, b2f);
    fold_cls_kernel<<<1, 256>>>(cls_bn_g, cls_bn_b, cls_bn_rm, cls_bn_rv, cls_w2, cls_b2, cw2, cb2);
    cudaMemsetAsync(deg, 0, (size_t)N * sizeof(float));

    pae_kernel<<<304, PAE_BLK, 102400>>>(edgenet, pae_w1, pae_b1, w2f, b2f, ew, E);

    deg_kernel<<<(E + 255) / 256, 256>>>(ew, row, deg, E);
    dis_kernel<<<(N + 255) / 256, 256>>>(deg, N);
    norm_kernel<<<(E + 255) / 256, 256>>>(ew, row, col, deg, nrm, E);

    const float* prev = features;
    int F = 128;
    float* hbufs[2] = {ha, hb};
    for (int l = 0; l < 4; l++) {
        int F4 = F / 4;
        int lg = (F == 128) ? 5 : 4;
        int spmm_blocks = (int)(((size_t)E * F4 + 255) / 256);

        cudaMemsetAsync(tx1, 0, (size_t)N * F * sizeof(float));
        spmm_kernel<<<spmm_blocks, 256>>>(prev, tx1, row, col, nrm, E, F, lg);
        cudaMemsetAsync(tx2, 0, (size_t)N * F * sizeof(float));
        spmm_kernel<<<spmm_blocks, 256>>>(tx1, tx2, row, col, nrm, E, F, lg);
        fixup_kernel<<<(N * F + 255) / 256, 256>>>(tx2, prev, N * F);

        cheb_gemm<<<(N + 63) / 64, 256>>>(prev, tx1, tx2, cheb_w[l], F, N,
                                          hbufs[l & 1], jk + (size_t)l * 64);
        prev = hbufs[l & 1];
        F = 64;
    }

    dim3 g2((N + 63) / 64, 4);
    cls_gemm<<<g2, 256>>>(jk, cls_w1, cls_b1, N, zbuf);
    logit_kernel<<<(N * 32 + 255) / 256, 256>>>(zbuf, cw2, cb2, N, logit);
}

// round 3
// speedup vs baseline: 1.3392x; 1.3392x over previous
#include <cuda_runtime.h>
#include <cuda_bf16.h>
#include <math.h>
#include <stdint.h>

typedef unsigned long long ull;
typedef unsigned int uint;

#define NMAX 50000
#define EMAX 1600000

// ---------------- device scratch (no allocations allowed) ----------------
__device__ float g_tx1[(size_t)NMAX * 128];
__device__ float g_tx2[(size_t)NMAX * 128];
__device__ float g_ha[(size_t)NMAX * 64];
__device__ float g_hb[(size_t)NMAX * 64];
__device__ float g_z[(size_t)NMAX * 256];
__device__ float g_norm[EMAX];
__device__ float g_deg[NMAX];
__device__ __nv_bfloat16 g_w2t_hi[128 * 128];   // W2fT hi, [n][k] row-major
__device__ __nv_bfloat16 g_w2t_lo[128 * 128];   // W2fT lo
__device__ float g_b2f[128];
__device__ float g_cw2[256 * 2];
__device__ float g_cb2[2];

// =================== warp-level bf16 MMA (sm_80+ path, works on base sm_103) ===================
__device__ __forceinline__ void mma16816(float& d0, float& d1, float& d2, float& d3,
                                         uint a0, uint a1, uint a2, uint a3,
                                         uint b0, uint b1) {
    asm volatile(
        "mma.sync.aligned.m16n8k16.row.col.f32.bf16.bf16.f32 "
        "{%0,%1,%2,%3}, {%4,%5,%6,%7}, {%8,%9}, {%0,%1,%2,%3};"
        : "+f"(d0), "+f"(d1), "+f"(d2), "+f"(d3)
        : "r"(a0), "r"(a1), "r"(a2), "r"(a3), "r"(b0), "r"(b1));
}

// =================== BN folding kernels ===================
// PAE: o = bn(relu(z@w1+b1)) @ w2 + b2 == relu(z@w1+b1) @ w2f + b2f.
// Emit w2f TRANSPOSED ([n][k]) split into bf16 hi/lo.
__global__ void fold_pae_kernel(const float* __restrict__ g, const float* __restrict__ b,
                                const float* __restrict__ rm, const float* __restrict__ rv,
                                const float* __restrict__ w2, const float* __restrict__ b2,
                                __nv_bfloat16* __restrict__ wt_hi, __nv_bfloat16* __restrict__ wt_lo,
                                float* __restrict__ b2f) {
    __shared__ float s[128], t[128];
    int j = threadIdx.x;  // 128 threads
    float sj = g[j] * rsqrtf(rv[j] + 1e-5f);
    s[j] = sj;
    t[j] = b[j] - rm[j] * sj;
    __syncthreads();
    for (int idx = j; idx < 128 * 128; idx += 128) {
        int i = idx >> 7, jj = idx & 127;
        float v = s[i] * w2[idx];
        __nv_bfloat16 hi = __float2bfloat16(v);
        wt_hi[jj * 128 + i] = hi;
        wt_lo[jj * 128 + i] = __float2bfloat16(v - __bfloat162float(hi));
    }
    float acc = b2[j];
    for (int i = 0; i < 128; i++) acc += t[i] * w2[i * 128 + j];
    b2f[j] = acc;
}

__global__ void fold_cls_kernel(const float* __restrict__ g, const float* __restrict__ b,
                                const float* __restrict__ rm, const float* __restrict__ rv,
                                const float* __restrict__ w2, const float* __restrict__ b2,
                                float* __restrict__ cw2, float* __restrict__ cb2) {
    __shared__ float t[256];
    int i = threadIdx.x;  // 256 threads
    float si = g[i] * rsqrtf(rv[i] + 1e-5f);
    t[i] = b[i] - rm[i] * si;
    cw2[2 * i]     = si * w2[2 * i];
    cw2[2 * i + 1] = si * w2[2 * i + 1];
    __syncthreads();
    if (i < 2) {
        float acc = b2[i];
        for (int k = 0; k < 256; k++) acc += t[k] * w2[2 * k + i];
        cb2[i] = acc;
    }
}

// =================== PAE mma.sync kernel ===================
// Warp-iteration: 8 edges = 16 halves (M=16). h = relu(z@W1+b1) computed fp32
// directly into A-fragment register slots, split bf16 hi/lo. Per n-tile (N=8,
// 16 tiles): 3 passes x 8 K-steps of m16n8k16 accumulate o = h @ W2fT in fp32.
// Cosine via shfl row-pairing. B fragments pre-staged lane-ordered in SMEM.
//
// SMEM layout (dynamic): [0,65536) B frags as uint4 [hl][nt][k2][lane]
//   (hl in {hi,lo}, nt 0..15, k2 0..3 packs K-steps 2k2,2k2+1, lane 0..31)
//   [65536,68608) W1 [6][128]; [68608,69120) b1; [69120,69632) b2f.
#define PAE_SMEM 69632

__global__ __launch_bounds__(256, 1)
void pae_mma_kernel(const float* __restrict__ edgenet,
                    const float* __restrict__ w1, const float* __restrict__ b1,
                    const __nv_bfloat16* __restrict__ wt_hi, const __nv_bfloat16* __restrict__ wt_lo,
                    const float* __restrict__ b2f,
                    float* __restrict__ ew, int E) {
    extern __shared__ char smraw[];
    uint4* s_bfrag = (uint4*)smraw;
    float* s_w1  = (float*)(smraw + 65536);
    float* s_b1  = (float*)(smraw + 68608);
    float* s_b2f = (float*)(smraw + 69120);

    int tid = threadIdx.x, lane = tid & 31, wid = tid >> 5;

    // ---- stage weights ----
    for (int i = tid; i < 768; i += 256) s_w1[i] = w1[i];
    if (tid < 128) { s_b1[tid] = b1[tid]; s_b2f[tid] = b2f[tid]; }
    // B fragments: uint4 index = ((hl*16 + nt)*4 + k2)*32 + lane
    for (int idx = tid; idx < 4096; idx += 256) {
        int ln = idx & 31;
        int k2 = (idx >> 5) & 3;
        int nt = (idx >> 7) & 15;
        int hl = idx >> 11;
        const __nv_bfloat16* src = hl ? wt_lo : wt_hi;
        int n = nt * 8 + (ln >> 2);
        int kg0 = (2 * k2) * 16 + (ln & 3) * 2;
        const __nv_bfloat16* base = src + n * 128;
        uint4 v;
        v.x = *(const uint*)(base + kg0);
        v.y = *(const uint*)(base + kg0 + 8);
        v.z = *(const uint*)(base + kg0 + 16);
        v.w = *(const uint*)(base + kg0 + 24);
        s_bfrag[idx] = v;
    }
    __syncthreads();

    int r1 = lane >> 2;           // row (half) 0..7; also handles r1+8
    int cq = (lane & 3) * 2;
    int nT = (E + 7) >> 3;

    for (int t = blockIdx.x * 8 + wid; t < nT; t += gridDim.x * 8) {
        int e0 = t * 8;

        // ---- h-stage: build A fragments in registers ----
        int eb = e0 + (r1 >> 1);
        int e_lo = min(eb, E - 1);
        int e_hi = min(eb + 4, E - 1);
        int hf = (r1 & 1) * 6;
        float z1[6], z2[6];
#pragma unroll
        for (int j = 0; j < 6; j++) {
            z1[j] = __ldg(edgenet + (size_t)e_lo * 12 + hf + j);
            z2[j] = __ldg(edgenet + (size_t)e_hi * 12 + hf + j);
        }
        uint Ahi[8][4], Alo[8][4];
#pragma unroll
        for (int k = 0; k < 8; k++) {
#pragma unroll
            for (int hp = 0; hp < 2; hp++) {
                int c = k * 16 + cq + hp * 8;
                float2 bb = *(const float2*)(s_b1 + c);
                float a0 = bb.x, a1 = bb.y, a2 = bb.x, a3 = bb.y;
#pragma unroll
                for (int j = 0; j < 6; j++) {
                    float2 w = *(const float2*)(s_w1 + j * 128 + c);
                    a0 = fmaf(z1[j], w.x, a0);
                    a1 = fmaf(z1[j], w.y, a1);
                    a2 = fmaf(z2[j], w.x, a2);
                    a3 = fmaf(z2[j], w.y, a3);
                }
                a0 = fmaxf(a0, 0.f); a1 = fmaxf(a1, 0.f);
                a2 = fmaxf(a2, 0.f); a3 = fmaxf(a3, 0.f);
                __nv_bfloat162 h1 = __floats2bfloat162_rn(a0, a1);
                __nv_bfloat162 h2 = __floats2bfloat162_rn(a2, a3);
                float2 f1 = __bfloat1622float2(h1);
                float2 f2 = __bfloat1622float2(h2);
                __nv_bfloat162 l1 = __floats2bfloat162_rn(a0 - f1.x, a1 - f1.y);
                __nv_bfloat162 l2 = __floats2bfloat162_rn(a2 - f2.x, a3 - f2.y);
                Ahi[k][hp * 2 + 0] = *(uint*)&h1;
                Ahi[k][hp * 2 + 1] = *(uint*)&h2;
                Alo[k][hp * 2 + 0] = *(uint*)&l1;
                Alo[k][hp * 2 + 1] = *(uint*)&l2;
            }
        }

        // ---- MMA + cosine accumulation over 16 n-tiles ----
        float num_lo = 0.f, ps_lo = 0.f, num_hi = 0.f, ps_hi = 0.f;
#pragma unroll 1
        for (int nt = 0; nt < 16; nt++) {
            const uint4* ph = s_bfrag + (nt * 4) * 32 + lane;          // hi
            const uint4* pl = ph + 16 * 4 * 32;                        // lo
            uint4 bh0 = ph[0], bh1 = ph[32], bh2 = ph[64], bh3 = ph[96];
            uint4 bl0 = pl[0], bl1 = pl[32], bl2 = pl[64], bl3 = pl[96];
            uint bh[16] = {bh0.x, bh0.y, bh0.z, bh0.w, bh1.x, bh1.y, bh1.z, bh1.w,
                           bh2.x, bh2.y, bh2.z, bh2.w, bh3.x, bh3.y, bh3.z, bh3.w};
            uint bl[16] = {bl0.x, bl0.y, bl0.z, bl0.w, bl1.x, bl1.y, bl1.z, bl1.w,
                           bl2.x, bl2.y, bl2.z, bl2.w, bl3.x, bl3.y, bl3.z, bl3.w};
            float dA0 = 0.f, dA1 = 0.f, dA2 = 0.f, dA3 = 0.f;   // hi*hi
            float dB0 = 0.f, dB1 = 0.f, dB2 = 0.f, dB3 = 0.f;   // hi*lo
            float dC0 = 0.f, dC1 = 0.f, dC2 = 0.f, dC3 = 0.f;   // lo*hi
#pragma unroll
            for (int k = 0; k < 8; k++) {
                mma16816(dA0, dA1, dA2, dA3, Ahi[k][0], Ahi[k][1], Ahi[k][2], Ahi[k][3],
                         bh[2 * k], bh[2 * k + 1]);
                mma16816(dB0, dB1, dB2, dB3, Ahi[k][0], Ahi[k][1], Ahi[k][2], Ahi[k][3],
                         bl[2 * k], bl[2 * k + 1]);
                mma16816(dC0, dC1, dC2, dC3, Alo[k][0], Alo[k][1], Alo[k][2], Alo[k][3],
                         bh[2 * k], bh[2 * k + 1]);
            }
            float2 bb = *(const float2*)(s_b2f + nt * 8 + cq);
            float o0 = dA0 + dB0 + dC0 + bb.x;   // row r1, col c
            float o1 = dA1 + dB1 + dC1 + bb.y;   // row r1, col c+1
            float o2 = dA2 + dB2 + dC2 + bb.x;   // row r1+8, col c
            float o3 = dA3 + dB3 + dC3 + bb.y;   // row r1+8, col c+1
            float p0 = __shfl_xor_sync(0xffffffffu, o0, 4);
            float p1 = __shfl_xor_sync(0xffffffffu, o1, 4);
            float p2 = __shfl_xor_sync(0xffffffffu, o2, 4);
            float p3 = __shfl_xor_sync(0xffffffffu, o3, 4);
            num_lo = fmaf(o0, p0, fmaf(o1, p1, num_lo));
            ps_lo  = fmaf(o0, o0, fmaf(o1, o1, ps_lo));
            num_hi = fmaf(o2, p2, fmaf(o3, p3, num_hi));
            ps_hi  = fmaf(o2, o2, fmaf(o3, o3, ps_hi));
        }

        // reduce over the 4 lanes sharing a row
#pragma unroll
        for (int off = 1; off <= 2; off <<= 1) {
            num_lo += __shfl_xor_sync(0xffffffffu, num_lo, off);
            ps_lo  += __shfl_xor_sync(0xffffffffu, ps_lo, off);
            num_hi += __shfl_xor_sync(0xffffffffu, num_hi, off);
            ps_hi  += __shfl_xor_sync(0xffffffffu, ps_hi, off);
        }
        // partner-row |o|^2
        float psp_lo = __shfl_xor_sync(0xffffffffu, ps_lo, 4);
        float psp_hi = __shfl_xor_sync(0xffffffffu, ps_hi, 4);

        if ((lane & 7) == 0) {   // lanes 0,8,16,24: even rows 0,2,4,6
            int eL = lane >> 3;
            int elo = e0 + eL;
            int ehi = e0 + 4 + eL;
            if (elo < E) {
                float den = fmaxf(sqrtf(ps_lo) * sqrtf(psp_lo), 1e-8f);
                ew[elo] = fmaf(num_lo / den, 0.5f, 0.5f);
            }
            if (ehi < E) {
                float den = fmaxf(sqrtf(ps_hi) * sqrtf(psp_hi), 1e-8f);
                ew[ehi] = fmaf(num_hi / den, 0.5f, 0.5f);
            }
        }
    }
}

// =================== graph-normalization kernels ===================
__global__ void deg_kernel(const float* __restrict__ ew, const int* __restrict__ row,
                           float* __restrict__ deg, int E) {
    int e = blockIdx.x * blockDim.x + threadIdx.x;
    if (e < E) atomicAdd(&deg[row[e]], ew[e]);
}

__global__ void dis_kernel(float* __restrict__ deg, int N) {
    int i = blockIdx.x * blockDim.x + threadIdx.x;
    if (i < N) {
        float d = deg[i];
        deg[i] = (d > 0.f) ? rsqrtf(d) : 0.f;
    }
}

__global__ void norm_kernel(const float* __restrict__ ew, const int* __restrict__ row,
                            const int* __restrict__ col, const float* __restrict__ dis,
                            float* __restrict__ nrm, int E) {
    int e = blockIdx.x * blockDim.x + threadIdx.x;
    if (e < E) nrm[e] = -dis[row[e]] * ew[e] * dis[col[e]];
}

// =================== SpMM: out[row] += norm * x[col] ===================
__global__ void spmm_kernel(const float* __restrict__ x, float* __restrict__ out,
                            const int* __restrict__ row, const int* __restrict__ col,
                            const float* __restrict__ nrm, int E, int F, int lgF4) {
    int gid = blockIdx.x * blockDim.x + threadIdx.x;
    int e = gid >> lgF4;
    if (e >= E) return;
    int c = gid & ((1 << lgF4) - 1);
    float w = __ldg(nrm + e);
    int cs = __ldg(col + e);
    int rs = __ldg(row + e);
    const float4 xv = *(const float4*)(x + (size_t)cs * F + c * 4);
    float a = w * xv.x, b = w * xv.y, cc = w * xv.z, d = w * xv.w;
    float* dst = out + (size_t)rs * F + c * 4;
    asm volatile("red.global.add.v4.f32 [%0], {%1,%2,%3,%4};"
                 :: "l"(dst), "f"(a), "f"(b), "f"(cc), "f"(d) : "memory");
}

__global__ void fixup_kernel(float* __restrict__ tx2, const float* __restrict__ tx0, int n) {
    int i = blockIdx.x * blockDim.x + threadIdx.x;
    if (i < n) tx2[i] = 2.f * tx2[i] - tx0[i];
}

// =================== dense GEMMs ===================
__global__ void cheb_gemm(const float* __restrict__ A0, const float* __restrict__ A1,
                          const float* __restrict__ A2, const float* __restrict__ W,
                          int K, int N, float* __restrict__ hout, float* __restrict__ jkout) {
    __shared__ float As[16][64];
    __shared__ float Ws[16][64];
    int tid = threadIdx.x;
    int tx = tid & 15, ty = tid >> 4;
    int r0 = blockIdx.x * 64;
    float acc[4][4] = {};
    const float* Aps[3] = {A0, A1, A2};
    for (int p = 0; p < 3; p++) {
        const float* Ap = Aps[p];
        const float* Wp = W + (size_t)p * K * 64;
        for (int k0 = 0; k0 < K; k0 += 16) {
            __syncthreads();
            for (int i = tid; i < 1024; i += 256) {
                int rr = i >> 4, kk = i & 15;
                int gr = r0 + rr;
                As[kk][rr] = (gr < N) ? Ap[(size_t)gr * K + k0 + kk] : 0.f;
            }
            for (int i = tid; i < 1024; i += 256) {
                int kk = i >> 6, cc = i & 63;
                Ws[kk][cc] = Wp[(size_t)(k0 + kk) * 64 + cc];
            }
            __syncthreads();
#pragma unroll
            for (int kk = 0; kk < 16; kk++) {
                float a0 = As[kk][ty * 4 + 0], a1 = As[kk][ty * 4 + 1];
                float a2 = As[kk][ty * 4 + 2], a3 = As[kk][ty * 4 + 3];
                float w0 = Ws[kk][tx * 4 + 0], w1v = Ws[kk][tx * 4 + 1];
                float w2v = Ws[kk][tx * 4 + 2], w3 = Ws[kk][tx * 4 + 3];
                acc[0][0] += a0 * w0; acc[0][1] += a0 * w1v; acc[0][2] += a0 * w2v; acc[0][3] += a0 * w3;
                acc[1][0] += a1 * w0; acc[1][1] += a1 * w1v; acc[1][2] += a1 * w2v; acc[1][3] += a1 * w3;
                acc[2][0] += a2 * w0; acc[2][1] += a2 * w1v; acc[2][2] += a2 * w2v; acc[2][3] += a2 * w3;
                acc[3][0] += a3 * w0; acc[3][1] += a3 * w1v; acc[3][2] += a3 * w2v; acc[3][3] += a3 * w3;
            }
        }
    }
#pragma unroll
    for (int r = 0; r < 4; r++) {
        int rowi = r0 + ty * 4 + r;
        if (rowi < N) {
#pragma unroll
            for (int c = 0; c < 4; c++) {
                int coli = tx * 4 + c;
                float v = fmaxf(acc[r][c], 0.f);
                hout[(size_t)rowi * 64 + coli] = v;
                jkout[(size_t)rowi * 256 + coli] = v;
            }
        }
    }
}

__global__ void cls_gemm(const float* __restrict__ A, const float* __restrict__ W,
                         const float* __restrict__ bias, int N, float* __restrict__ out) {
    __shared__ float As[16][64];
    __shared__ float Ws[16][64];
    int tid = threadIdx.x;
    int tx = tid & 15, ty = tid >> 4;
    int r0 = blockIdx.x * 64;
    int c0 = blockIdx.y * 64;
    float acc[4][4] = {};
    for (int k0 = 0; k0 < 256; k0 += 16) {
        __syncthreads();
        for (int i = tid; i < 1024; i += 256) {
            int rr = i >> 4, kk = i & 15;
            int gr = r0 + rr;
            As[kk][rr] = (gr < N) ? A[(size_t)gr * 256 + k0 + kk] : 0.f;
        }
        for (int i = tid; i < 1024; i += 256) {
            int kk = i >> 6, cc = i & 63;
            Ws[kk][cc] = W[(size_t)(k0 + kk) * 256 + c0 + cc];
        }
        __syncthreads();
#pragma unroll
        for (int kk = 0; kk < 16; kk++) {
            float a0 = As[kk][ty * 4 + 0], a1 = As[kk][ty * 4 + 1];
            float a2 = As[kk][ty * 4 + 2], a3 = As[kk][ty * 4 + 3];
            float w0 = Ws[kk][tx * 4 + 0], w1v = Ws[kk][tx * 4 + 1];
            float w2v = Ws[kk][tx * 4 + 2], w3 = Ws[kk][tx * 4 + 3];
            acc[0][0] += a0 * w0; acc[0][1] += a0 * w1v; acc[0][2] += a0 * w2v; acc[0][3] += a0 * w3;
            acc[1][0] += a1 * w0; acc[1][1] += a1 * w1v; acc[1][2] += a1 * w2v; acc[1][3] += a1 * w3;
            acc[2][0] += a2 * w0; acc[2][1] += a2 * w1v; acc[2][2] += a2 * w2v; acc[2][3] += a2 * w3;
            acc[3][0] += a3 * w0; acc[3][1] += a3 * w1v; acc[3][2] += a3 * w2v; acc[3][3] += a3 * w3;
        }
    }
#pragma unroll
    for (int r = 0; r < 4; r++) {
        int rowi = r0 + ty * 4 + r;
        if (rowi < N) {
#pragma unroll
            for (int c = 0; c < 4; c++) {
                int coli = c0 + tx * 4 + c;
                out[(size_t)rowi * 256 + coli] = fmaxf(acc[r][c] + bias[coli], 0.f);
            }
        }
    }
}

__global__ void logit_kernel(const float* __restrict__ z, const float* __restrict__ cw2,
                             const float* __restrict__ cb2, int N, float* __restrict__ out) {
    int gw = (blockIdx.x * blockDim.x + threadIdx.x) >> 5;
    int lane = threadIdx.x & 31;
    if (gw >= N) return;
    const float* zr = z + (size_t)gw * 256;
    float a0 = 0.f, a1 = 0.f;
    for (int i = lane; i < 256; i += 32) {
        float v = zr[i];
        a0 += v * cw2[2 * i];
        a1 += v * cw2[2 * i + 1];
    }
#pragma unroll
    for (int off = 16; off; off >>= 1) {
        a0 += __shfl_xor_sync(0xffffffffu, a0, off);
        a1 += __shfl_xor_sync(0xffffffffu, a1, off);
    }
    if (lane == 0) {
        out[(size_t)gw * 2 + 0] = a0 + cb2[0];
        out[(size_t)gw * 2 + 1] = a1 + cb2[1];
    }
}

// =================== launcher ===================
extern "C" void kernel_launch(void* const* d_in, const int* in_sizes, int n_in,
                              void* d_out, int out_size) {
    const float* features = (const float*)d_in[0];
    const int* edge_index = (const int*)d_in[1];
    const float* edgenet  = (const float*)d_in[2];
    const float* pae_w1 = (const float*)d_in[3];
    const float* pae_b1 = (const float*)d_in[4];
    const float* pae_bn_g = (const float*)d_in[5];
    const float* pae_bn_b = (const float*)d_in[6];
    const float* pae_bn_rm = (const float*)d_in[7];
    const float* pae_bn_rv = (const float*)d_in[8];
    const float* pae_w2 = (const float*)d_in[9];
    const float* pae_b2 = (const float*)d_in[10];
    const float* cheb_w[4] = {(const float*)d_in[11], (const float*)d_in[12],
                              (const float*)d_in[13], (const float*)d_in[14]};
    const float* cls_w1 = (const float*)d_in[15];
    const float* cls_b1 = (const float*)d_in[16];
    const float* cls_bn_g = (const float*)d_in[17];
    const float* cls_bn_b = (const float*)d_in[18];
    const float* cls_bn_rm = (const float*)d_in[19];
    const float* cls_bn_rv = (const float*)d_in[20];
    const float* cls_w2 = (const float*)d_in[21];
    const float* cls_b2 = (const float*)d_in[22];

    int N = in_sizes[0] / 128;
    int E = in_sizes[1] / 2;
    const int* row = edge_index;
    const int* col = edge_index + E;

    float* out = (float*)d_out;
    float* jk = out;
    float* logit = out + (size_t)N * 256;
    float* ew = logit + (size_t)N * 2;

    float *tx1, *tx2, *ha, *hb, *zbuf, *nrm, *deg, *b2f, *cw2, *cb2;
    __nv_bfloat16 *wt_hi, *wt_lo;
    cudaGetSymbolAddress((void**)&tx1, g_tx1);
    cudaGetSymbolAddress((void**)&tx2, g_tx2);
    cudaGetSymbolAddress((void**)&ha, g_ha);
    cudaGetSymbolAddress((void**)&hb, g_hb);
    cudaGetSymbolAddress((void**)&zbuf, g_z);
    cudaGetSymbolAddress((void**)&nrm, g_norm);
    cudaGetSymbolAddress((void**)&deg, g_deg);
    cudaGetSymbolAddress((void**)&wt_hi, g_w2t_hi);
    cudaGetSymbolAddress((void**)&wt_lo, g_w2t_lo);
    cudaGetSymbolAddress((void**)&b2f, g_b2f);
    cudaGetSymbolAddress((void**)&cw2, g_cw2);
    cudaGetSymbolAddress((void**)&cb2, g_cb2);

    cudaFuncSetAttribute(pae_mma_kernel, cudaFuncAttributeMaxDynamicSharedMemorySize, PAE_SMEM);

    fold_pae_kernel<<<1, 128>>>(pae_bn_g, pae_bn_b, pae_bn_rm, pae_bn_rv, pae_w2, pae_b2,
                                wt_hi, wt_lo, b2f);
    fold_cls_kernel<<<1, 256>>>(cls_bn_g, cls_bn_b, cls_bn_rm, cls_bn_rv, cls_w2, cls_b2, cw2, cb2);
    cudaMemsetAsync(deg, 0, (size_t)N * sizeof(float));

    pae_mma_kernel<<<148, 256, PAE_SMEM>>>(edgenet, pae_w1, pae_b1, wt_hi, wt_lo, b2f, ew, E);

    deg_kernel<<<(E + 255) / 256, 256>>>(ew, row, deg, E);
    dis_kernel<<<(N + 255) / 256, 256>>>(deg, N);
    norm_kernel<<<(E + 255) / 256, 256>>>(ew, row, col, deg, nrm, E);

    const float* prev = features;
    int F = 128;
    float* hbufs[2] = {ha, hb};
    for (int l = 0; l < 4; l++) {
        int F4 = F / 4;
        int lg = (F == 128) ? 5 : 4;
        int spmm_blocks = (int)(((size_t)E * F4 + 255) / 256);

        cudaMemsetAsync(tx1, 0, (size_t)N * F * sizeof(float));
        spmm_kernel<<<spmm_blocks, 256>>>(prev, tx1, row, col, nrm, E, F, lg);
        cudaMemsetAsync(tx2, 0, (size_t)N * F * sizeof(float));
        spmm_kernel<<<spmm_blocks, 256>>>(tx1, tx2, row, col, nrm, E, F, lg);
        fixup_kernel<<<(N * F + 255) / 256, 256>>>(tx2, prev, N * F);

        cheb_gemm<<<(N + 63) / 64, 256>>>(prev, tx1, tx2, cheb_w[l], F, N,
                                          hbufs[l & 1], jk + (size_t)l * 64);
        prev = hbufs[l & 1];
        F = 64;
    }

    dim3 g2((N + 63) / 64, 4);
    cls_gemm<<<g2, 256>>>(jk, cls_w1, cls_b1, N, zbuf);
    logit_kernel<<<(N * 32 + 255) / 256, 256>>>(zbuf, cw2, cb2, N, logit);
}

// round 4
// speedup vs baseline: 1.8309x; 1.3671x over previous
#include <cuda_runtime.h>
#include <cuda_bf16.h>
#include <math.h>
#include <stdint.h>

typedef unsigned long long ull;
typedef unsigned int uint;

#define NMAX 50000
#define EMAX 1600000

// ---------------- device scratch (no allocations allowed) ----------------
__device__ float g_tx1[(size_t)NMAX * 64];      // s = L(u2)
__device__ float g_tx2[(size_t)NMAX * 64];      // t = L(v)
__device__ float g_u[(size_t)NMAX * 192];       // [u0 | u1 | u2]
__device__ float g_ha[(size_t)NMAX * 64];
__device__ float g_hb[(size_t)NMAX * 64];
__device__ float g_z[(size_t)NMAX * 256];       // zbuf; first N*64 reused as v
__device__ float g_norm[EMAX];
__device__ float g_deg[NMAX];
__device__ __nv_bfloat16 g_w2t_hi[128 * 128];   // PAE W2fT hi, [n][k]
__device__ __nv_bfloat16 g_w2t_lo[128 * 128];   // PAE W2fT lo
__device__ float g_b2f[128];
__device__ float g_cw2[256 * 2];
__device__ float g_cb2[2];
// B fragments for mma GEMMs (uint4 = {hi_b0, hi_b1, lo_b0, lo_b1})
__device__ uint4 g_frag_cheb0[3 * 8 * 256];     // K=128, 192 cols
__device__ uint4 g_frag_cheb1[3 * 4 * 256];     // K=64
__device__ uint4 g_frag_cheb2[3 * 4 * 256];
__device__ uint4 g_frag_cheb3[3 * 4 * 256];
__device__ uint4 g_frag_cls[4 * 16 * 256];      // K=256, 256 cols

// =================== warp-level bf16 MMA ===================
__device__ __forceinline__ void mma16816(float* d,
                                         uint a0, uint a1, uint a2, uint a3,
                                         uint b0, uint b1) {
    asm volatile(
        "mma.sync.aligned.m16n8k16.row.col.f32.bf16.bf16.f32 "
        "{%0,%1,%2,%3}, {%4,%5,%6,%7}, {%8,%9}, {%0,%1,%2,%3};"
        : "+f"(d[0]), "+f"(d[1]), "+f"(d[2]), "+f"(d[3])
        : "r"(a0), "r"(a1), "r"(a2), "r"(a3), "r"(b0), "r"(b1));
}

__device__ __forceinline__ void mma16816s(float& d0, float& d1, float& d2, float& d3,
                                          uint a0, uint a1, uint a2, uint a3,
                                          uint b0, uint b1) {
    asm volatile(
        "mma.sync.aligned.m16n8k16.row.col.f32.bf16.bf16.f32 "
        "{%0,%1,%2,%3}, {%4,%5,%6,%7}, {%8,%9}, {%0,%1,%2,%3};"
        : "+f"(d0), "+f"(d1), "+f"(d2), "+f"(d3)
        : "r"(a0), "r"(a1), "r"(a2), "r"(a3), "r"(b0), "r"(b1));
}

__device__ __forceinline__ void split2(float a, float b, uint& hi, uint& lo) {
    __nv_bfloat162 h = __floats2bfloat162_rn(a, b);
    float2 f = __bfloat1622float2(h);
    __nv_bfloat162 l = __floats2bfloat162_rn(a - f.x, b - f.y);
    hi = *(uint*)&h;
    lo = *(uint*)&l;
}

// =================== BN folding kernels ===================
__global__ void fold_pae_kernel(const float* __restrict__ g, const float* __restrict__ b,
                                const float* __restrict__ rm, const float* __restrict__ rv,
                                const float* __restrict__ w2, const float* __restrict__ b2,
                                __nv_bfloat16* __restrict__ wt_hi, __nv_bfloat16* __restrict__ wt_lo,
                                float* __restrict__ b2f) {
    __shared__ float s[128], t[128];
    int j = threadIdx.x;  // 128 threads
    float sj = g[j] * rsqrtf(rv[j] + 1e-5f);
    s[j] = sj;
    t[j] = b[j] - rm[j] * sj;
    __syncthreads();
    for (int idx = j; idx < 128 * 128; idx += 128) {
        int i = idx >> 7, jj = idx & 127;
        float v = s[i] * w2[idx];
        __nv_bfloat16 hi = __float2bfloat16(v);
        wt_hi[jj * 128 + i] = hi;
        wt_lo[jj * 128 + i] = __float2bfloat16(v - __bfloat162float(hi));
    }
    float acc = b2[j];
    for (int i = 0; i < 128; i++) acc += t[i] * w2[i * 128 + j];
    b2f[j] = acc;
}

__global__ void fold_cls_kernel(const float* __restrict__ g, const float* __restrict__ b,
                                const float* __restrict__ rm, const float* __restrict__ rv,
                                const float* __restrict__ w2, const float* __restrict__ b2,
                                float* __restrict__ cw2, float* __restrict__ cb2) {
    __shared__ float t[256];
    int i = threadIdx.x;  // 256 threads
    float si = g[i] * rsqrtf(rv[i] + 1e-5f);
    t[i] = b[i] - rm[i] * si;
    cw2[2 * i]     = si * w2[2 * i];
    cw2[2 * i + 1] = si * w2[2 * i + 1];
    __syncthreads();
    if (i < 2) {
        float acc = b2[i];
        for (int k = 0; k < 256; k++) acc += t[k] * w2[2 * k + i];
        cb2[i] = acc;
    }
}

// =================== fragment prep kernels ===================
// Generic W (K x Ncols row-major) -> frag[chunk][kt][nt][lane] uint4
__global__ void prep_frag(const float* __restrict__ W, int K, int Ncols, uint4* __restrict__ out) {
    int ktiles = K >> 4;
    int total = (Ncols >> 6) * ktiles * 256;
    int idx = blockIdx.x * 256 + threadIdx.x;
    if (idx >= total) return;
    int lane = idx & 31;
    int nt = (idx >> 5) & 7;
    int rest = idx >> 8;
    int kt = rest % ktiles;
    int chunk = rest / ktiles;
    int n = chunk * 64 + nt * 8 + (lane >> 2);
    int k0 = kt * 16 + (lane & 3) * 2;
    float w00 = W[(size_t)k0 * Ncols + n];
    float w01 = W[(size_t)(k0 + 1) * Ncols + n];
    float w10 = W[(size_t)(k0 + 8) * Ncols + n];
    float w11 = W[(size_t)(k0 + 9) * Ncols + n];
    uint4 v;
    split2(w00, w01, v.x, v.z);
    split2(w10, w11, v.y, v.w);
    out[idx] = v;
}

// Cheb composite Wc[k][n]: n<64: W0-W2 ; 64<=n<128: W1 ; n>=128: W2.  W: [3][K][64]
__global__ void prep_cheb_frag(const float* __restrict__ W, int K, uint4* __restrict__ out) {
    int ktiles = K >> 4;
    int total = 3 * ktiles * 256;
    int idx = blockIdx.x * 256 + threadIdx.x;
    if (idx >= total) return;
    int lane = idx & 31;
    int nt = (idx >> 5) & 7;
    int rest = idx >> 8;
    int kt = rest % ktiles;
    int chunk = rest / ktiles;
    int n = chunk * 64 + nt * 8 + (lane >> 2);
    int k0 = kt * 16 + (lane & 3) * 2;
    int part = n >> 6, nn = n & 63;
    float w[4];
#pragma unroll
    for (int q = 0; q < 4; q++) {
        int k = k0 + (q >> 1) * 8 + (q & 1);
        float v;
        if (part == 0)      v = W[(size_t)k * 64 + nn] - W[(size_t)(2 * K + k) * 64 + nn];
        else if (part == 1) v = W[(size_t)(K + k) * 64 + nn];
        else                v = W[(size_t)(2 * K + k) * 64 + nn];
        w[q] = v;
    }
    uint4 v;
    split2(w[0], w[1], v.x, v.z);
    split2(w[2], w[3], v.y, v.w);
    out[idx] = v;
}

// =================== generic split-bf16 mma GEMM ===================
// C[M x ?] (+bias, relu?) = A[M x K](fp32, lda) @ B ; B given as fragments.
// grid.x = row tiles of 128, grid.y = 64-col chunk. 256 threads (8 warps x 16 rows).
__global__ __launch_bounds__(256)
void gemm_mma(const float* __restrict__ A, int lda, int M,
              const uint4* __restrict__ bfrag, int ktiles,
              const float* __restrict__ bias, int ldc, float* __restrict__ C,
              int relu_flag) {
    extern __shared__ uint4 sB[];   // [ktiles][8][32]
    int tid = threadIdx.x, lane = tid & 31, wid = tid >> 5;
    const uint4* src = bfrag + (size_t)blockIdx.y * ktiles * 256;
    for (int i = tid; i < ktiles * 256; i += 256) sB[i] = src[i];
    __syncthreads();

    int r1 = blockIdx.x * 128 + wid * 16 + (lane >> 2);
    int r2 = r1 + 8;
    int rl1 = min(r1, M - 1), rl2 = min(r2, M - 1);
    int cq = (lane & 3) * 2;
    const float* A1 = A + (size_t)rl1 * lda;
    const float* A2 = A + (size_t)rl2 * lda;

    float acc[8][4];
#pragma unroll
    for (int i = 0; i < 8; i++) { acc[i][0] = acc[i][1] = acc[i][2] = acc[i][3] = 0.f; }

    for (int kt = 0; kt < ktiles; kt++) {
        int k0 = kt * 16 + cq;
        float2 xa = *(const float2*)(A1 + k0);
        float2 xb = *(const float2*)(A2 + k0);
        float2 xc = *(const float2*)(A1 + k0 + 8);
        float2 xd = *(const float2*)(A2 + k0 + 8);
        uint ahi[4], alo[4];
        split2(xa.x, xa.y, ahi[0], alo[0]);
        split2(xb.x, xb.y, ahi[1], alo[1]);
        split2(xc.x, xc.y, ahi[2], alo[2]);
        split2(xd.x, xd.y, ahi[3], alo[3]);

        const uint4* bp = sB + kt * 256 + lane;
        uint4 b[8];
#pragma unroll
        for (int nt = 0; nt < 8; nt++) b[nt] = bp[nt * 32];
#pragma unroll
        for (int nt = 0; nt < 8; nt++)
            mma16816(acc[nt], ahi[0], ahi[1], ahi[2], ahi[3], b[nt].x, b[nt].y);
#pragma unroll
        for (int nt = 0; nt < 8; nt++)
            mma16816(acc[nt], alo[0], alo[1], alo[2], alo[3], b[nt].x, b[nt].y);
#pragma unroll
        for (int nt = 0; nt < 8; nt++)
            mma16816(acc[nt], ahi[0], ahi[1], ahi[2], ahi[3], b[nt].z, b[nt].w);
    }

#pragma unroll
    for (int nt = 0; nt < 8; nt++) {
        int cc = blockIdx.y * 64 + nt * 8 + cq;
        float b0 = 0.f, b1 = 0.f;
        if (bias) { b0 = bias[cc]; b1 = bias[cc + 1]; }
        float v0 = acc[nt][0] + b0, v1 = acc[nt][1] + b1;
        float v2 = acc[nt][2] + b0, v3 = acc[nt][3] + b1;
        if (relu_flag) {
            v0 = fmaxf(v0, 0.f); v1 = fmaxf(v1, 0.f);
            v2 = fmaxf(v2, 0.f); v3 = fmaxf(v3, 0.f);
        }
        if (r1 < M) { float2 o = {v0, v1}; *(float2*)(C + (size_t)r1 * ldc + cc) = o; }
        if (r2 < M) { float2 o = {v2, v3}; *(float2*)(C + (size_t)r2 * ldc + cc) = o; }
    }
}

// =================== PAE mma.sync kernel (unchanged from R3, passing) ===================
#define PAE_SMEM 69632

__global__ __launch_bounds__(256, 1)
void pae_mma_kernel(const float* __restrict__ edgenet,
                    const float* __restrict__ w1, const float* __restrict__ b1,
                    const __nv_bfloat16* __restrict__ wt_hi, const __nv_bfloat16* __restrict__ wt_lo,
                    const float* __restrict__ b2f,
                    float* __restrict__ ew, int E) {
    extern __shared__ char smraw[];
    uint4* s_bfrag = (uint4*)smraw;
    float* s_w1  = (float*)(smraw + 65536);
    float* s_b1  = (float*)(smraw + 68608);
    float* s_b2f = (float*)(smraw + 69120);

    int tid = threadIdx.x, lane = tid & 31, wid = tid >> 5;

    for (int i = tid; i < 768; i += 256) s_w1[i] = w1[i];
    if (tid < 128) { s_b1[tid] = b1[tid]; s_b2f[tid] = b2f[tid]; }
    for (int idx = tid; idx < 4096; idx += 256) {
        int ln = idx & 31;
        int k2 = (idx >> 5) & 3;
        int nt = (idx >> 7) & 15;
        int hl = idx >> 11;
        const __nv_bfloat16* src = hl ? wt_lo : wt_hi;
        int n = nt * 8 + (ln >> 2);
        int kg0 = (2 * k2) * 16 + (ln & 3) * 2;
        const __nv_bfloat16* base = src + n * 128;
        uint4 v;
        v.x = *(const uint*)(base + kg0);
        v.y = *(const uint*)(base + kg0 + 8);
        v.z = *(const uint*)(base + kg0 + 16);
        v.w = *(const uint*)(base + kg0 + 24);
        s_bfrag[idx] = v;
    }
    __syncthreads();

    int r1 = lane >> 2;
    int cq = (lane & 3) * 2;
    int nT = (E + 7) >> 3;

    for (int t = blockIdx.x * 8 + wid; t < nT; t += gridDim.x * 8) {
        int e0 = t * 8;

        int eb = e0 + (r1 >> 1);
        int e_lo = min(eb, E - 1);
        int e_hi = min(eb + 4, E - 1);
        int hf = (r1 & 1) * 6;
        float z1[6], z2[6];
#pragma unroll
        for (int j = 0; j < 6; j++) {
            z1[j] = __ldg(edgenet + (size_t)e_lo * 12 + hf + j);
            z2[j] = __ldg(edgenet + (size_t)e_hi * 12 + hf + j);
        }
        uint Ahi[8][4], Alo[8][4];
#pragma unroll
        for (int k = 0; k < 8; k++) {
#pragma unroll
            for (int hp = 0; hp < 2; hp++) {
                int c = k * 16 + cq + hp * 8;
                float2 bb = *(const float2*)(s_b1 + c);
                float a0 = bb.x, a1 = bb.y, a2 = bb.x, a3 = bb.y;
#pragma unroll
                for (int j = 0; j < 6; j++) {
                    float2 w = *(const float2*)(s_w1 + j * 128 + c);
                    a0 = fmaf(z1[j], w.x, a0);
                    a1 = fmaf(z1[j], w.y, a1);
                    a2 = fmaf(z2[j], w.x, a2);
                    a3 = fmaf(z2[j], w.y, a3);
                }
                a0 = fmaxf(a0, 0.f); a1 = fmaxf(a1, 0.f);
                a2 = fmaxf(a2, 0.f); a3 = fmaxf(a3, 0.f);
                uint h1, l1, h2, l2;
                split2(a0, a1, h1, l1);
                split2(a2, a3, h2, l2);
                Ahi[k][hp * 2 + 0] = h1;
                Ahi[k][hp * 2 + 1] = h2;
                Alo[k][hp * 2 + 0] = l1;
                Alo[k][hp * 2 + 1] = l2;
            }
        }

        float num_lo = 0.f, ps_lo = 0.f, num_hi = 0.f, ps_hi = 0.f;
#pragma unroll 1
        for (int nt = 0; nt < 16; nt++) {
            const uint4* ph = s_bfrag + (nt * 4) * 32 + lane;
            const uint4* pl = ph + 16 * 4 * 32;
            uint4 bh0 = ph[0], bh1 = ph[32], bh2 = ph[64], bh3 = ph[96];
            uint4 bl0 = pl[0], bl1 = pl[32], bl2 = pl[64], bl3 = pl[96];
            uint bh[16] = {bh0.x, bh0.y, bh0.z, bh0.w, bh1.x, bh1.y, bh1.z, bh1.w,
                           bh2.x, bh2.y, bh2.z, bh2.w, bh3.x, bh3.y, bh3.z, bh3.w};
            uint bl[16] = {bl0.x, bl0.y, bl0.z, bl0.w, bl1.x, bl1.y, bl1.z, bl1.w,
                           bl2.x, bl2.y, bl2.z, bl2.w, bl3.x, bl3.y, bl3.z, bl3.w};
            float dA0 = 0.f, dA1 = 0.f, dA2 = 0.f, dA3 = 0.f;
            float dB0 = 0.f, dB1 = 0.f, dB2 = 0.f, dB3 = 0.f;
            float dC0 = 0.f, dC1 = 0.f, dC2 = 0.f, dC3 = 0.f;
#pragma unroll
            for (int k = 0; k < 8; k++) {
                mma16816s(dA0, dA1, dA2, dA3, Ahi[k][0], Ahi[k][1], Ahi[k][2], Ahi[k][3],
                          bh[2 * k], bh[2 * k + 1]);
                mma16816s(dB0, dB1, dB2, dB3, Ahi[k][0], Ahi[k][1], Ahi[k][2], Ahi[k][3],
                          bl[2 * k], bl[2 * k + 1]);
                mma16816s(dC0, dC1, dC2, dC3, Alo[k][0], Alo[k][1], Alo[k][2], Alo[k][3],
                          bh[2 * k], bh[2 * k + 1]);
            }
            float2 bb = *(const float2*)(s_b2f + nt * 8 + cq);
            float o0 = dA0 + dB0 + dC0 + bb.x;
            float o1 = dA1 + dB1 + dC1 + bb.y;
            float o2 = dA2 + dB2 + dC2 + bb.x;
            float o3 = dA3 + dB3 + dC3 + bb.y;
            float p0 = __shfl_xor_sync(0xffffffffu, o0, 4);
            float p1 = __shfl_xor_sync(0xffffffffu, o1, 4);
            float p2 = __shfl_xor_sync(0xffffffffu, o2, 4);
            float p3 = __shfl_xor_sync(0xffffffffu, o3, 4);
            num_lo = fmaf(o0, p0, fmaf(o1, p1, num_lo));
            ps_lo  = fmaf(o0, o0, fmaf(o1, o1, ps_lo));
            num_hi = fmaf(o2, p2, fmaf(o3, p3, num_hi));
            ps_hi  = fmaf(o2, o2, fmaf(o3, o3, ps_hi));
        }

#pragma unroll
        for (int off = 1; off <= 2; off <<= 1) {
            num_lo += __shfl_xor_sync(0xffffffffu, num_lo, off);
            ps_lo  += __shfl_xor_sync(0xffffffffu, ps_lo, off);
            num_hi += __shfl_xor_sync(0xffffffffu, num_hi, off);
            ps_hi  += __shfl_xor_sync(0xffffffffu, ps_hi, off);
        }
        float psp_lo = __shfl_xor_sync(0xffffffffu, ps_lo, 4);
        float psp_hi = __shfl_xor_sync(0xffffffffu, ps_hi, 4);

        if ((lane & 7) == 0) {
            int eL = lane >> 3;
            int elo = e0 + eL;
            int ehi = e0 + 4 + eL;
            if (elo < E) {
                float den = fmaxf(sqrtf(ps_lo) * sqrtf(psp_lo), 1e-8f);
                ew[elo] = fmaf(num_lo / den, 0.5f, 0.5f);
            }
            if (ehi < E) {
                float den = fmaxf(sqrtf(ps_hi) * sqrtf(psp_hi), 1e-8f);
                ew[ehi] = fmaf(num_hi / den, 0.5f, 0.5f);
            }
        }
    }
}

// =================== graph-normalization kernels ===================
__global__ void deg_kernel(const float* __restrict__ ew, const int* __restrict__ row,
                           float* __restrict__ deg, int E) {
    int e = blockIdx.x * blockDim.x + threadIdx.x;
    if (e < E) atomicAdd(&deg[row[e]], ew[e]);
}

__global__ void dis_kernel(float* __restrict__ deg, int N) {
    int i = blockIdx.x * blockDim.x + threadIdx.x;
    if (i < N) {
        float d = deg[i];
        deg[i] = (d > 0.f) ? rsqrtf(d) : 0.f;
    }
}

__global__ void norm_kernel(const float* __restrict__ ew, const int* __restrict__ row,
                            const int* __restrict__ col, const float* __restrict__ dis,
                            float* __restrict__ nrm, int E) {
    int e = blockIdx.x * blockDim.x + threadIdx.x;
    if (e < E) nrm[e] = -dis[row[e]] * ew[e] * dis[col[e]];
}

// =================== SpMM (F=64): out[row] += norm * x[col], vector RED ===================
__global__ void spmm_kernel(const float* __restrict__ x, int ldx, float* __restrict__ out,
                            const int* __restrict__ row, const int* __restrict__ col,
                            const float* __restrict__ nrm, int E) {
    int gid = blockIdx.x * blockDim.x + threadIdx.x;
    int e = gid >> 4;
    if (e >= E) return;
    int c = gid & 15;
    float w = __ldg(nrm + e);
    int cs = __ldg(col + e);
    int rs = __ldg(row + e);
    const float4 xv = *(const float4*)(x + (size_t)cs * ldx + c * 4);
    float a = w * xv.x, b = w * xv.y, cc = w * xv.z, d = w * xv.w;
    float* dst = out + (size_t)rs * 64 + c * 4;
    asm volatile("red.global.add.v4.f32 [%0], {%1,%2,%3,%4};"
                 :: "l"(dst), "f"(a), "f"(b), "f"(cc), "f"(d) : "memory");
}

// v = u1 + 2*s   (u1 = u[:,64:128])
__global__ void v_kernel(const float* __restrict__ u, const float* __restrict__ s,
                         float* __restrict__ v, int n4) {
    int i = blockIdx.x * blockDim.x + threadIdx.x;
    if (i >= n4) return;
    int node = i >> 4, j = (i & 15) * 4;
    float4 uu = *(const float4*)(u + (size_t)node * 192 + 64 + j);
    float4 ss = *(const float4*)(s + (size_t)node * 64 + j);
    float4 r;
    r.x = fmaf(2.f, ss.x, uu.x);
    r.y = fmaf(2.f, ss.y, uu.y);
    r.z = fmaf(2.f, ss.z, uu.z);
    r.w = fmaf(2.f, ss.w, uu.w);
    *(float4*)(v + (size_t)node * 64 + j) = r;
}

// h = relu(u0 + t) -> hbuf and jk slice
__global__ void h_kernel(const float* __restrict__ u, const float* __restrict__ t,
                         float* __restrict__ hbuf, float* __restrict__ jk, int n4) {
    int i = blockIdx.x * blockDim.x + threadIdx.x;
    if (i >= n4) return;
    int node = i >> 4, j = (i & 15) * 4;
    float4 uu = *(const float4*)(u + (size_t)node * 192 + j);
    float4 tt = *(const float4*)(t + (size_t)node * 64 + j);
    float4 r;
    r.x = fmaxf(uu.x + tt.x, 0.f);
    r.y = fmaxf(uu.y + tt.y, 0.f);
    r.z = fmaxf(uu.z + tt.z, 0.f);
    r.w = fmaxf(uu.w + tt.w, 0.f);
    *(float4*)(hbuf + (size_t)node * 64 + j) = r;
    *(float4*)(jk + (size_t)node * 256 + j) = r;
}

__global__ void logit_kernel(const float* __restrict__ z, const float* __restrict__ cw2,
                             const float* __restrict__ cb2, int N, float* __restrict__ out) {
    int gw = (blockIdx.x * blockDim.x + threadIdx.x) >> 5;
    int lane = threadIdx.x & 31;
    if (gw >= N) return;
    const float* zr = z + (size_t)gw * 256;
    float a0 = 0.f, a1 = 0.f;
    for (int i = lane; i < 256; i += 32) {
        float v = zr[i];
        a0 += v * cw2[2 * i];
        a1 += v * cw2[2 * i + 1];
    }
#pragma unroll
    for (int off = 16; off; off >>= 1) {
        a0 += __shfl_xor_sync(0xffffffffu, a0, off);
        a1 += __shfl_xor_sync(0xffffffffu, a1, off);
    }
    if (lane == 0) {
        out[(size_t)gw * 2 + 0] = a0 + cb2[0];
        out[(size_t)gw * 2 + 1] = a1 + cb2[1];
    }
}

// =================== launcher ===================
extern "C" void kernel_launch(void* const* d_in, const int* in_sizes, int n_in,
                              void* d_out, int out_size) {
    const float* features = (const float*)d_in[0];
    const int* edge_index = (const int*)d_in[1];
    const float* edgenet  = (const float*)d_in[2];
    const float* pae_w1 = (const float*)d_in[3];
    const float* pae_b1 = (const float*)d_in[4];
    const float* pae_bn_g = (const float*)d_in[5];
    const float* pae_bn_b = (const float*)d_in[6];
    const float* pae_bn_rm = (const float*)d_in[7];
    const float* pae_bn_rv = (const float*)d_in[8];
    const float* pae_w2 = (const float*)d_in[9];
    const float* pae_b2 = (const float*)d_in[10];
    const float* cheb_w[4] = {(const float*)d_in[11], (const float*)d_in[12],
                              (const float*)d_in[13], (const float*)d_in[14]};
    const float* cls_w1 = (const float*)d_in[15];
    const float* cls_b1 = (const float*)d_in[16];
    const float* cls_bn_g = (const float*)d_in[17];
    const float* cls_bn_b = (const float*)d_in[18];
    const float* cls_bn_rm = (const float*)d_in[19];
    const float* cls_bn_rv = (const float*)d_in[20];
    const float* cls_w2 = (const float*)d_in[21];
    const float* cls_b2 = (const float*)d_in[22];

    int N = in_sizes[0] / 128;
    int E = in_sizes[1] / 2;
    const int* row = edge_index;
    const int* col = edge_index + E;

    float* out = (float*)d_out;
    float* jk = out;
    float* logit = out + (size_t)N * 256;
    float* ew = logit + (size_t)N * 2;

    float *sbuf, *tbuf, *ubuf, *ha, *hb, *zbuf, *nrm, *deg, *b2f, *cw2, *cb2;
    __nv_bfloat16 *wt_hi, *wt_lo;
    uint4 *frag_cheb[4], *frag_cls;
    cudaGetSymbolAddress((void**)&sbuf, g_tx1);
    cudaGetSymbolAddress((void**)&tbuf, g_tx2);
    cudaGetSymbolAddress((void**)&ubuf, g_u);
    cudaGetSymbolAddress((void**)&ha, g_ha);
    cudaGetSymbolAddress((void**)&hb, g_hb);
    cudaGetSymbolAddress((void**)&zbuf, g_z);
    cudaGetSymbolAddress((void**)&nrm, g_norm);
    cudaGetSymbolAddress((void**)&deg, g_deg);
    cudaGetSymbolAddress((void**)&wt_hi, g_w2t_hi);
    cudaGetSymbolAddress((void**)&wt_lo, g_w2t_lo);
    cudaGetSymbolAddress((void**)&b2f, g_b2f);
    cudaGetSymbolAddress((void**)&cw2, g_cw2);
    cudaGetSymbolAddress((void**)&cb2, g_cb2);
    cudaGetSymbolAddress((void**)&frag_cheb[0], g_frag_cheb0);
    cudaGetSymbolAddress((void**)&frag_cheb[1], g_frag_cheb1);
    cudaGetSymbolAddress((void**)&frag_cheb[2], g_frag_cheb2);
    cudaGetSymbolAddress((void**)&frag_cheb[3], g_frag_cheb3);
    cudaGetSymbolAddress((void**)&frag_cls, g_frag_cls);

    float* vbuf = zbuf;   // reuse first N*64 of zbuf as v (zbuf written later)

    cudaFuncSetAttribute(pae_mma_kernel, cudaFuncAttributeMaxDynamicSharedMemorySize, PAE_SMEM);
    cudaFuncSetAttribute(gemm_mma, cudaFuncAttributeMaxDynamicSharedMemorySize, 65536);

    // ---- weight prep ----
    fold_pae_kernel<<<1, 128>>>(pae_bn_g, pae_bn_b, pae_bn_rm, pae_bn_rv, pae_w2, pae_b2,
                                wt_hi, wt_lo, b2f);
    fold_cls_kernel<<<1, 256>>>(cls_bn_g, cls_bn_b, cls_bn_rm, cls_bn_rv, cls_w2, cls_b2, cw2, cb2);
    prep_cheb_frag<<<24, 256>>>(cheb_w[0], 128, frag_cheb[0]);
    prep_cheb_frag<<<12, 256>>>(cheb_w[1], 64, frag_cheb[1]);
    prep_cheb_frag<<<12, 256>>>(cheb_w[2], 64, frag_cheb[2]);
    prep_cheb_frag<<<12, 256>>>(cheb_w[3], 64, frag_cheb[3]);
    prep_frag<<<64, 256>>>(cls_w1, 256, 256, frag_cls);
    cudaMemsetAsync(deg, 0, (size_t)N * sizeof(float));

    // ---- PAE edge weights ----
    pae_mma_kernel<<<148, 256, PAE_SMEM>>>(edgenet, pae_w1, pae_b1, wt_hi, wt_lo, b2f, ew, E);

    deg_kernel<<<(E + 255) / 256, 256>>>(ew, row, deg, E);
    dis_kernel<<<(N + 255) / 256, 256>>>(deg, N);
    norm_kernel<<<(E + 255) / 256, 256>>>(ew, row, col, deg, nrm, E);

    // ---- GCN layers ----
    const float* prev = features;
    int F = 128;
    float* hbufs[2] = {ha, hb};
    int rowTiles = (N + 127) / 128;
    int spmm_blocks = (int)(((size_t)E * 16 + 255) / 256);
    int n4 = N * 16;

    for (int l = 0; l < 4; l++) {
        int ktiles = F >> 4;
        // u = prev @ [W0-W2 | W1 | W2]
        gemm_mma<<<dim3(rowTiles, 3), 256, ktiles * 4096>>>(
            prev, F, N, frag_cheb[l], ktiles, nullptr, 192, ubuf, 0);
        // s = L(u2)
        cudaMemsetAsync(sbuf, 0, (size_t)N * 64 * sizeof(float));
        spmm_kernel<<<spmm_blocks, 256>>>(ubuf + 128, 192, sbuf, row, col, nrm, E);
        // v = u1 + 2s
        v_kernel<<<(n4 + 255) / 256, 256>>>(ubuf, sbuf, vbuf, n4);
        // t = L(v)
        cudaMemsetAsync(tbuf, 0, (size_t)N * 64 * sizeof(float));
        spmm_kernel<<<spmm_blocks, 256>>>(vbuf, 64, tbuf, row, col, nrm, E);
        // h = relu(u0 + t)
        h_kernel<<<(n4 + 255) / 256, 256>>>(ubuf, tbuf, hbufs[l & 1], jk + (size_t)l * 64, n4);
        prev = hbufs[l & 1];
        F = 64;
    }

    // ---- classifier ----
    gemm_mma<<<dim3(rowTiles, 4), 256, 16 * 4096>>>(
        jk, 256, N, frag_cls, 16, cls_b1, 256, zbuf, 1);
    logit_kernel<<<(N * 32 + 255) / 256, 256>>>(zbuf, cw2, cb2, N, logit);
}

// round 5
// speedup vs baseline: 2.2729x; 1.2414x over previous
#include <cuda_runtime.h>
#include <cuda_bf16.h>
#include <math.h>
#include <stdint.h>

typedef unsigned long long ull;
typedef unsigned int uint;

#define NMAX 50000
#define EMAX 1600000

// ---------------- device scratch (no allocations allowed) ----------------
__device__ float g_tx1[(size_t)NMAX * 64];      // s = L(u2)
__device__ float g_tx2[(size_t)NMAX * 64];      // t = L(v)
__device__ float g_u[(size_t)NMAX * 192];       // [u0 | u1 | u2]
__device__ float g_ha[(size_t)NMAX * 64];
__device__ float g_hb[(size_t)NMAX * 64];
__device__ float g_z[(size_t)NMAX * 256];       // zbuf; first N*64 reused as v
__device__ float g_wp[EMAX];                    // ew[e]*dis[col[e]] in CSR order
__device__ float g_dis[NMAX];                   // rsqrt(deg) or 0
__device__ int   g_rowptr[NMAX + 1];
__device__ int   g_cursor[NMAX];
__device__ int   g_cnt[NMAX];
__device__ int   g_ecol[EMAX];                  // col in CSR order
__device__ int   g_eidx[EMAX];                  // original edge id in CSR order
__device__ __nv_bfloat16 g_w2t_hi[128 * 128];   // PAE W2fT hi, [n][k]
__device__ __nv_bfloat16 g_w2t_lo[128 * 128];   // PAE W2fT lo
__device__ float g_b2f[128];
__device__ float g_cw2[256 * 2];
__device__ float g_cb2[2];
// B fragments for mma GEMMs (uint4 = {hi_b0, hi_b1, lo_b0, lo_b1})
__device__ uint4 g_frag_cheb0[3 * 8 * 256];     // K=128, 192 cols
__device__ uint4 g_frag_cheb1[3 * 4 * 256];     // K=64
__device__ uint4 g_frag_cheb2[3 * 4 * 256];
__device__ uint4 g_frag_cheb3[3 * 4 * 256];
__device__ uint4 g_frag_cls[4 * 16 * 256];      // K=256, 256 cols

// =================== warp-level bf16 MMA ===================
__device__ __forceinline__ void mma16816(float* d,
                                         uint a0, uint a1, uint a2, uint a3,
                                         uint b0, uint b1) {
    asm volatile(
        "mma.sync.aligned.m16n8k16.row.col.f32.bf16.bf16.f32 "
        "{%0,%1,%2,%3}, {%4,%5,%6,%7}, {%8,%9}, {%0,%1,%2,%3};"
        : "+f"(d[0]), "+f"(d[1]), "+f"(d[2]), "+f"(d[3])
        : "r"(a0), "r"(a1), "r"(a2), "r"(a3), "r"(b0), "r"(b1));
}

__device__ __forceinline__ void mma16816s(float& d0, float& d1, float& d2, float& d3,
                                          uint a0, uint a1, uint a2, uint a3,
                                          uint b0, uint b1) {
    asm volatile(
        "mma.sync.aligned.m16n8k16.row.col.f32.bf16.bf16.f32 "
        "{%0,%1,%2,%3}, {%4,%5,%6,%7}, {%8,%9}, {%0,%1,%2,%3};"
        : "+f"(d0), "+f"(d1), "+f"(d2), "+f"(d3)
        : "r"(a0), "r"(a1), "r"(a2), "r"(a3), "r"(b0), "r"(b1));
}

__device__ __forceinline__ void split2(float a, float b, uint& hi, uint& lo) {
    __nv_bfloat162 h = __floats2bfloat162_rn(a, b);
    float2 f = __bfloat1622float2(h);
    __nv_bfloat162 l = __floats2bfloat162_rn(a - f.x, b - f.y);
    hi = *(uint*)&h;
    lo = *(uint*)&l;
}

// =================== BN folding kernels ===================
__global__ void fold_pae_kernel(const float* __restrict__ g, const float* __restrict__ b,
                                const float* __restrict__ rm, const float* __restrict__ rv,
                                const float* __restrict__ w2, const float* __restrict__ b2,
                                __nv_bfloat16* __restrict__ wt_hi, __nv_bfloat16* __restrict__ wt_lo,
                                float* __restrict__ b2f) {
    __shared__ float s[128], t[128];
    int j = threadIdx.x;  // 128 threads
    float sj = g[j] * rsqrtf(rv[j] + 1e-5f);
    s[j] = sj;
    t[j] = b[j] - rm[j] * sj;
    __syncthreads();
    for (int idx = j; idx < 128 * 128; idx += 128) {
        int i = idx >> 7, jj = idx & 127;
        float v = s[i] * w2[idx];
        __nv_bfloat16 hi = __float2bfloat16(v);
        wt_hi[jj * 128 + i] = hi;
        wt_lo[jj * 128 + i] = __float2bfloat16(v - __bfloat162float(hi));
    }
    float acc = b2[j];
    for (int i = 0; i < 128; i++) acc += t[i] * w2[i * 128 + j];
    b2f[j] = acc;
}

__global__ void fold_cls_kernel(const float* __restrict__ g, const float* __restrict__ b,
                                const float* __restrict__ rm, const float* __restrict__ rv,
                                const float* __restrict__ w2, const float* __restrict__ b2,
                                float* __restrict__ cw2, float* __restrict__ cb2) {
    __shared__ float t[256];
    int i = threadIdx.x;  // 256 threads
    float si = g[i] * rsqrtf(rv[i] + 1e-5f);
    t[i] = b[i] - rm[i] * si;
    cw2[2 * i]     = si * w2[2 * i];
    cw2[2 * i + 1] = si * w2[2 * i + 1];
    __syncthreads();
    if (i < 2) {
        float acc = b2[i];
        for (int k = 0; k < 256; k++) acc += t[k] * w2[2 * k + i];
        cb2[i] = acc;
    }
}

// =================== fragment prep kernels ===================
__global__ void prep_frag(const float* __restrict__ W, int K, int Ncols, uint4* __restrict__ out) {
    int ktiles = K >> 4;
    int total = (Ncols >> 6) * ktiles * 256;
    int idx = blockIdx.x * 256 + threadIdx.x;
    if (idx >= total) return;
    int lane = idx & 31;
    int nt = (idx >> 5) & 7;
    int rest = idx >> 8;
    int kt = rest % ktiles;
    int chunk = rest / ktiles;
    int n = chunk * 64 + nt * 8 + (lane >> 2);
    int k0 = kt * 16 + (lane & 3) * 2;
    float w00 = W[(size_t)k0 * Ncols + n];
    float w01 = W[(size_t)(k0 + 1) * Ncols + n];
    float w10 = W[(size_t)(k0 + 8) * Ncols + n];
    float w11 = W[(size_t)(k0 + 9) * Ncols + n];
    uint4 v;
    split2(w00, w01, v.x, v.z);
    split2(w10, w11, v.y, v.w);
    out[idx] = v;
}

// Cheb composite Wc[k][n]: n<64: W0-W2 ; 64<=n<128: W1 ; n>=128: W2.  W: [3][K][64]
__global__ void prep_cheb_frag(const float* __restrict__ W, int K, uint4* __restrict__ out) {
    int ktiles = K >> 4;
    int total = 3 * ktiles * 256;
    int idx = blockIdx.x * 256 + threadIdx.x;
    if (idx >= total) return;
    int lane = idx & 31;
    int nt = (idx >> 5) & 7;
    int rest = idx >> 8;
    int kt = rest % ktiles;
    int chunk = rest / ktiles;
    int n = chunk * 64 + nt * 8 + (lane >> 2);
    int k0 = kt * 16 + (lane & 3) * 2;
    int part = n >> 6, nn = n & 63;
    float w[4];
#pragma unroll
    for (int q = 0; q < 4; q++) {
        int k = k0 + (q >> 1) * 8 + (q & 1);
        float v;
        if (part == 0)      v = W[(size_t)k * 64 + nn] - W[(size_t)(2 * K + k) * 64 + nn];
        else if (part == 1) v = W[(size_t)(K + k) * 64 + nn];
        else                v = W[(size_t)(2 * K + k) * 64 + nn];
        w[q] = v;
    }
    uint4 v;
    split2(w[0], w[1], v.x, v.z);
    split2(w[2], w[3], v.y, v.w);
    out[idx] = v;
}

// =================== generic split-bf16 mma GEMM ===================
__global__ __launch_bounds__(256)
void gemm_mma(const float* __restrict__ A, int lda, int M,
              const uint4* __restrict__ bfrag, int ktiles,
              const float* __restrict__ bias, int ldc, float* __restrict__ C,
              int relu_flag) {
    extern __shared__ uint4 sB[];   // [ktiles][8][32]
    int tid = threadIdx.x, lane = tid & 31, wid = tid >> 5;
    const uint4* src = bfrag + (size_t)blockIdx.y * ktiles * 256;
    for (int i = tid; i < ktiles * 256; i += 256) sB[i] = src[i];
    __syncthreads();

    int r1 = blockIdx.x * 128 + wid * 16 + (lane >> 2);
    int r2 = r1 + 8;
    int rl1 = min(r1, M - 1), rl2 = min(r2, M - 1);
    int cq = (lane & 3) * 2;
    const float* A1 = A + (size_t)rl1 * lda;
    const float* A2 = A + (size_t)rl2 * lda;

    float acc[8][4];
#pragma unroll
    for (int i = 0; i < 8; i++) { acc[i][0] = acc[i][1] = acc[i][2] = acc[i][3] = 0.f; }

    for (int kt = 0; kt < ktiles; kt++) {
        int k0 = kt * 16 + cq;
        float2 xa = *(const float2*)(A1 + k0);
        float2 xb = *(const float2*)(A2 + k0);
        float2 xc = *(const float2*)(A1 + k0 + 8);
        float2 xd = *(const float2*)(A2 + k0 + 8);
        uint ahi[4], alo[4];
        split2(xa.x, xa.y, ahi[0], alo[0]);
        split2(xb.x, xb.y, ahi[1], alo[1]);
        split2(xc.x, xc.y, ahi[2], alo[2]);
        split2(xd.x, xd.y, ahi[3], alo[3]);

        const uint4* bp = sB + kt * 256 + lane;
        uint4 b[8];
#pragma unroll
        for (int nt = 0; nt < 8; nt++) b[nt] = bp[nt * 32];
#pragma unroll
        for (int nt = 0; nt < 8; nt++)
            mma16816(acc[nt], ahi[0], ahi[1], ahi[2], ahi[3], b[nt].x, b[nt].y);
#pragma unroll
        for (int nt = 0; nt < 8; nt++)
            mma16816(acc[nt], alo[0], alo[1], alo[2], alo[3], b[nt].x, b[nt].y);
#pragma unroll
        for (int nt = 0; nt < 8; nt++)
            mma16816(acc[nt], ahi[0], ahi[1], ahi[2], ahi[3], b[nt].z, b[nt].w);
    }

#pragma unroll
    for (int nt = 0; nt < 8; nt++) {
        int cc = blockIdx.y * 64 + nt * 8 + cq;
        float b0 = 0.f, b1 = 0.f;
        if (bias) { b0 = bias[cc]; b1 = bias[cc + 1]; }
        float v0 = acc[nt][0] + b0, v1 = acc[nt][1] + b1;
        float v2 = acc[nt][2] + b0, v3 = acc[nt][3] + b1;
        if (relu_flag) {
            v0 = fmaxf(v0, 0.f); v1 = fmaxf(v1, 0.f);
            v2 = fmaxf(v2, 0.f); v3 = fmaxf(v3, 0.f);
        }
        if (r1 < M) { float2 o = {v0, v1}; *(float2*)(C + (size_t)r1 * ldc + cc) = o; }
        if (r2 < M) { float2 o = {v2, v3}; *(float2*)(C + (size_t)r2 * ldc + cc) = o; }
    }
}

// =================== PAE mma.sync kernel (unchanged, passing) ===================
#define PAE_SMEM 69632

__global__ __launch_bounds__(256, 1)
void pae_mma_kernel(const float* __restrict__ edgenet,
                    const float* __restrict__ w1, const float* __restrict__ b1,
                    const __nv_bfloat16* __restrict__ wt_hi, const __nv_bfloat16* __restrict__ wt_lo,
                    const float* __restrict__ b2f,
                    float* __restrict__ ew, int E) {
    extern __shared__ char smraw[];
    uint4* s_bfrag = (uint4*)smraw;
    float* s_w1  = (float*)(smraw + 65536);
    float* s_b1  = (float*)(smraw + 68608);
    float* s_b2f = (float*)(smraw + 69120);

    int tid = threadIdx.x, lane = tid & 31, wid = tid >> 5;

    for (int i = tid; i < 768; i += 256) s_w1[i] = w1[i];
    if (tid < 128) { s_b1[tid] = b1[tid]; s_b2f[tid] = b2f[tid]; }
    for (int idx = tid; idx < 4096; idx += 256) {
        int ln = idx & 31;
        int k2 = (idx >> 5) & 3;
        int nt = (idx >> 7) & 15;
        int hl = idx >> 11;
        const __nv_bfloat16* src = hl ? wt_lo : wt_hi;
        int n = nt * 8 + (ln >> 2);
        int kg0 = (2 * k2) * 16 + (ln & 3) * 2;
        const __nv_bfloat16* base = src + n * 128;
        uint4 v;
        v.x = *(const uint*)(base + kg0);
        v.y = *(const uint*)(base + kg0 + 8);
        v.z = *(const uint*)(base + kg0 + 16);
        v.w = *(const uint*)(base + kg0 + 24);
        s_bfrag[idx] = v;
    }
    __syncthreads();

    int r1 = lane >> 2;
    int cq = (lane & 3) * 2;
    int nT = (E + 7) >> 3;

    for (int t = blockIdx.x * 8 + wid; t < nT; t += gridDim.x * 8) {
        int e0 = t * 8;

        int eb = e0 + (r1 >> 1);
        int e_lo = min(eb, E - 1);
        int e_hi = min(eb + 4, E - 1);
        int hf = (r1 & 1) * 6;
        float z1[6], z2[6];
#pragma unroll
        for (int j = 0; j < 6; j++) {
            z1[j] = __ldg(edgenet + (size_t)e_lo * 12 + hf + j);
            z2[j] = __ldg(edgenet + (size_t)e_hi * 12 + hf + j);
        }
        uint Ahi[8][4], Alo[8][4];
#pragma unroll
        for (int k = 0; k < 8; k++) {
#pragma unroll
            for (int hp = 0; hp < 2; hp++) {
                int c = k * 16 + cq + hp * 8;
                float2 bb = *(const float2*)(s_b1 + c);
                float a0 = bb.x, a1 = bb.y, a2 = bb.x, a3 = bb.y;
#pragma unroll
                for (int j = 0; j < 6; j++) {
                    float2 w = *(const float2*)(s_w1 + j * 128 + c);
                    a0 = fmaf(z1[j], w.x, a0);
                    a1 = fmaf(z1[j], w.y, a1);
                    a2 = fmaf(z2[j], w.x, a2);
                    a3 = fmaf(z2[j], w.y, a3);
                }
                a0 = fmaxf(a0, 0.f); a1 = fmaxf(a1, 0.f);
                a2 = fmaxf(a2, 0.f); a3 = fmaxf(a3, 0.f);
                uint h1, l1, h2, l2;
                split2(a0, a1, h1, l1);
                split2(a2, a3, h2, l2);
                Ahi[k][hp * 2 + 0] = h1;
                Ahi[k][hp * 2 + 1] = h2;
                Alo[k][hp * 2 + 0] = l1;
                Alo[k][hp * 2 + 1] = l2;
            }
        }

        float num_lo = 0.f, ps_lo = 0.f, num_hi = 0.f, ps_hi = 0.f;
#pragma unroll 1
        for (int nt = 0; nt < 16; nt++) {
            const uint4* ph = s_bfrag + (nt * 4) * 32 + lane;
            const uint4* pl = ph + 16 * 4 * 32;
            uint4 bh0 = ph[0], bh1 = ph[32], bh2 = ph[64], bh3 = ph[96];
            uint4 bl0 = pl[0], bl1 = pl[32], bl2 = pl[64], bl3 = pl[96];
            uint bh[16] = {bh0.x, bh0.y, bh0.z, bh0.w, bh1.x, bh1.y, bh1.z, bh1.w,
                           bh2.x, bh2.y, bh2.z, bh2.w, bh3.x, bh3.y, bh3.z, bh3.w};
            uint bl[16] = {bl0.x, bl0.y, bl0.z, bl0.w, bl1.x, bl1.y, bl1.z, bl1.w,
                           bl2.x, bl2.y, bl2.z, bl2.w, bl3.x, bl3.y, bl3.z, bl3.w};
            float dA0 = 0.f, dA1 = 0.f, dA2 = 0.f, dA3 = 0.f;
            float dB0 = 0.f, dB1 = 0.f, dB2 = 0.f, dB3 = 0.f;
            float dC0 = 0.f, dC1 = 0.f, dC2 = 0.f, dC3 = 0.f;
#pragma unroll
            for (int k = 0; k < 8; k++) {
                mma16816s(dA0, dA1, dA2, dA3, Ahi[k][0], Ahi[k][1], Ahi[k][2], Ahi[k][3],
                          bh[2 * k], bh[2 * k + 1]);
                mma16816s(dB0, dB1, dB2, dB3, Ahi[k][0], Ahi[k][1], Ahi[k][2], Ahi[k][3],
                          bl[2 * k], bl[2 * k + 1]);
                mma16816s(dC0, dC1, dC2, dC3, Alo[k][0], Alo[k][1], Alo[k][2], Alo[k][3],
                          bh[2 * k], bh[2 * k + 1]);
            }
            float2 bb = *(const float2*)(s_b2f + nt * 8 + cq);
            float o0 = dA0 + dB0 + dC0 + bb.x;
            float o1 = dA1 + dB1 + dC1 + bb.y;
            float o2 = dA2 + dB2 + dC2 + bb.x;
            float o3 = dA3 + dB3 + dC3 + bb.y;
            float p0 = __shfl_xor_sync(0xffffffffu, o0, 4);
            float p1 = __shfl_xor_sync(0xffffffffu, o1, 4);
            float p2 = __shfl_xor_sync(0xffffffffu, o2, 4);
            float p3 = __shfl_xor_sync(0xffffffffu, o3, 4);
            num_lo = fmaf(o0, p0, fmaf(o1, p1, num_lo));
            ps_lo  = fmaf(o0, o0, fmaf(o1, o1, ps_lo));
            num_hi = fmaf(o2, p2, fmaf(o3, p3, num_hi));
            ps_hi  = fmaf(o2, o2, fmaf(o3, o3, ps_hi));
        }

#pragma unroll
        for (int off = 1; off <= 2; off <<= 1) {
            num_lo += __shfl_xor_sync(0xffffffffu, num_lo, off);
            ps_lo  += __shfl_xor_sync(0xffffffffu, ps_lo, off);
            num_hi += __shfl_xor_sync(0xffffffffu, num_hi, off);
            ps_hi  += __shfl_xor_sync(0xffffffffu, ps_hi, off);
        }
        float psp_lo = __shfl_xor_sync(0xffffffffu, ps_lo, 4);
        float psp_hi = __shfl_xor_sync(0xffffffffu, ps_hi, 4);

        if ((lane & 7) == 0) {
            int eL = lane >> 3;
            int elo = e0 + eL;
            int ehi = e0 + 4 + eL;
            if (elo < E) {
                float den = fmaxf(sqrtf(ps_lo) * sqrtf(psp_lo), 1e-8f);
                ew[elo] = fmaf(num_lo / den, 0.5f, 0.5f);
            }
            if (ehi < E) {
                float den = fmaxf(sqrtf(ps_hi) * sqrtf(psp_hi), 1e-8f);
                ew[ehi] = fmaf(num_hi / den, 0.5f, 0.5f);
            }
        }
    }
}

// =================== CSR build ===================
__global__ void hist_kernel(const int* __restrict__ row, int* __restrict__ cnt, int E) {
    int e = blockIdx.x * blockDim.x + threadIdx.x;
    if (e < E) atomicAdd(&cnt[row[e]], 1);
}

// single block, 1024 threads: exclusive scan of cnt[0..N) into rowptr/cursor, rowptr[N]=E
__global__ void scan_kernel(const int* __restrict__ cnt, int N,
                            int* __restrict__ rowptr, int* __restrict__ cursor) {
    __shared__ int part[1024];
    int t = threadIdx.x;
    int chunk = (N + 1023) / 1024;
    int b = t * chunk, e = min(b + chunk, N);
    int s = 0;
    for (int i = b; i < e; i++) s += cnt[i];
    part[t] = s;
    __syncthreads();
    for (int off = 1; off < 1024; off <<= 1) {
        int v = (t >= off) ? part[t - off] : 0;
        __syncthreads();
        part[t] += v;
        __syncthreads();
    }
    int run = t ? part[t - 1] : 0;
    for (int i = b; i < e; i++) {
        rowptr[i] = run;
        cursor[i] = run;
        run += cnt[i];
    }
    if (t == 1023) rowptr[N] = run;
}

__global__ void scatter_kernel(const int* __restrict__ row, const int* __restrict__ col,
                               int* __restrict__ cursor, int* __restrict__ ecol,
                               int* __restrict__ eidx, int E) {
    int e = blockIdx.x * blockDim.x + threadIdx.x;
    if (e >= E) return;
    int pos = atomicAdd(&cursor[row[e]], 1);
    ecol[pos] = col[e];
    eidx[pos] = e;
}

// dis[r] = deg>0 ? rsqrt(sum_{edges of r} ew) : 0   (warp per row)
__global__ void dis_csr_kernel(const float* __restrict__ ew, const int* __restrict__ rowptr,
                               const int* __restrict__ eidx, float* __restrict__ dis, int N) {
    int warp = (blockIdx.x * blockDim.x + threadIdx.x) >> 5;
    int lane = threadIdx.x & 31;
    if (warp >= N) return;
    int beg = rowptr[warp], end = rowptr[warp + 1];
    float s = 0.f;
    for (int i = beg + lane; i < end; i += 32) s += __ldg(ew + __ldg(eidx + i));
#pragma unroll
    for (int off = 16; off; off >>= 1) s += __shfl_xor_sync(0xffffffffu, s, off);
    if (lane == 0) dis[warp] = (s > 0.f) ? rsqrtf(s) : 0.f;
}

// wp[i] = ew[eidx[i]] * dis[ecol[i]]
__global__ void wp_kernel(const float* __restrict__ ew, const int* __restrict__ eidx,
                          const int* __restrict__ ecol, const float* __restrict__ dis,
                          float* __restrict__ wp, int E) {
    int i = blockIdx.x * blockDim.x + threadIdx.x;
    if (i < E) wp[i] = __ldg(ew + eidx[i]) * __ldg(dis + ecol[i]);
}

// =================== CSR SpMM: out[r] = -dis[r] * sum_i wp[i]*x[ecol[i]]  (F=64) ===================
__global__ __launch_bounds__(256)
void spmm_csr(const float* __restrict__ x, int ldx, float* __restrict__ out,
              const int* __restrict__ rowptr, const int* __restrict__ ecol,
              const float* __restrict__ wp, const float* __restrict__ dis, int N) {
    int warp = (blockIdx.x * blockDim.x + threadIdx.x) >> 5;
    int lane = threadIdx.x & 31;
    if (warp >= N) return;
    int beg = rowptr[warp], end = rowptr[warp + 1];
    int half = lane >> 4;       // 0/1: which edge of the pair
    int cl = lane & 15;         // 16 lanes cover 64 floats as float4
    float4 acc = {0.f, 0.f, 0.f, 0.f};
    for (int i = beg + half; i < end; i += 2) {
        int c = __ldg(ecol + i);
        float w = __ldg(wp + i);
        float4 xv = *(const float4*)(x + (size_t)c * ldx + cl * 4);
        acc.x = fmaf(w, xv.x, acc.x);
        acc.y = fmaf(w, xv.y, acc.y);
        acc.z = fmaf(w, xv.z, acc.z);
        acc.w = fmaf(w, xv.w, acc.w);
    }
    acc.x += __shfl_down_sync(0xffffffffu, acc.x, 16);
    acc.y += __shfl_down_sync(0xffffffffu, acc.y, 16);
    acc.z += __shfl_down_sync(0xffffffffu, acc.z, 16);
    acc.w += __shfl_down_sync(0xffffffffu, acc.w, 16);
    if (half == 0) {
        float sc = -__ldg(dis + warp);
        float4 o = {sc * acc.x, sc * acc.y, sc * acc.z, sc * acc.w};
        *(float4*)(out + (size_t)warp * 64 + cl * 4) = o;
    }
}

// v = u1 + 2*s   (u1 = u[:,64:128])
__global__ void v_kernel(const float* __restrict__ u, const float* __restrict__ s,
                         float* __restrict__ v, int n4) {
    int i = blockIdx.x * blockDim.x + threadIdx.x;
    if (i >= n4) return;
    int node = i >> 4, j = (i & 15) * 4;
    float4 uu = *(const float4*)(u + (size_t)node * 192 + 64 + j);
    float4 ss = *(const float4*)(s + (size_t)node * 64 + j);
    float4 r;
    r.x = fmaf(2.f, ss.x, uu.x);
    r.y = fmaf(2.f, ss.y, uu.y);
    r.z = fmaf(2.f, ss.z, uu.z);
    r.w = fmaf(2.f, ss.w, uu.w);
    *(float4*)(v + (size_t)node * 64 + j) = r;
}

// h = relu(u0 + t) -> hbuf and jk slice
__global__ void h_kernel(const float* __restrict__ u, const float* __restrict__ t,
                         float* __restrict__ hbuf, float* __restrict__ jk, int n4) {
    int i = blockIdx.x * blockDim.x + threadIdx.x;
    if (i >= n4) return;
    int node = i >> 4, j = (i & 15) * 4;
    float4 uu = *(const float4*)(u + (size_t)node * 192 + j);
    float4 tt = *(const float4*)(t + (size_t)node * 64 + j);
    float4 r;
    r.x = fmaxf(uu.x + tt.x, 0.f);
    r.y = fmaxf(uu.y + tt.y, 0.f);
    r.z = fmaxf(uu.z + tt.z, 0.f);
    r.w = fmaxf(uu.w + tt.w, 0.f);
    *(float4*)(hbuf + (size_t)node * 64 + j) = r;
    *(float4*)(jk + (size_t)node * 256 + j) = r;
}

__global__ void logit_kernel(const float* __restrict__ z, const float* __restrict__ cw2,
                             const float* __restrict__ cb2, int N, float* __restrict__ out) {
    int gw = (blockIdx.x * blockDim.x + threadIdx.x) >> 5;
    int lane = threadIdx.x & 31;
    if (gw >= N) return;
    const float* zr = z + (size_t)gw * 256;
    float a0 = 0.f, a1 = 0.f;
    for (int i = lane; i < 256; i += 32) {
        float v = zr[i];
        a0 += v * cw2[2 * i];
        a1 += v * cw2[2 * i + 1];
    }
#pragma unroll
    for (int off = 16; off; off >>= 1) {
        a0 += __shfl_xor_sync(0xffffffffu, a0, off);
        a1 += __shfl_xor_sync(0xffffffffu, a1, off);
    }
    if (lane == 0) {
        out[(size_t)gw * 2 + 0] = a0 + cb2[0];
        out[(size_t)gw * 2 + 1] = a1 + cb2[1];
    }
}

// =================== launcher ===================
extern "C" void kernel_launch(void* const* d_in, const int* in_sizes, int n_in,
                              void* d_out, int out_size) {
    const float* features = (const float*)d_in[0];
    const int* edge_index = (const int*)d_in[1];
    const float* edgenet  = (const float*)d_in[2];
    const float* pae_w1 = (const float*)d_in[3];
    const float* pae_b1 = (const float*)d_in[4];
    const float* pae_bn_g = (const float*)d_in[5];
    const float* pae_bn_b = (const float*)d_in[6];
    const float* pae_bn_rm = (const float*)d_in[7];
    const float* pae_bn_rv = (const float*)d_in[8];
    const float* pae_w2 = (const float*)d_in[9];
    const float* pae_b2 = (const float*)d_in[10];
    const float* cheb_w[4] = {(const float*)d_in[11], (const float*)d_in[12],
                              (const float*)d_in[13], (const float*)d_in[14]};
    const float* cls_w1 = (const float*)d_in[15];
    const float* cls_b1 = (const float*)d_in[16];
    const float* cls_bn_g = (const float*)d_in[17];
    const float* cls_bn_b = (const float*)d_in[18];
    const float* cls_bn_rm = (const float*)d_in[19];
    const float* cls_bn_rv = (const float*)d_in[20];
    const float* cls_w2 = (const float*)d_in[21];
    const float* cls_b2 = (const float*)d_in[22];

    int N = in_sizes[0] / 128;
    int E = in_sizes[1] / 2;
    const int* row = edge_index;
    const int* col = edge_index + E;

    float* out = (float*)d_out;
    float* jk = out;
    float* logit = out + (size_t)N * 256;
    float* ew = logit + (size_t)N * 2;

    float *sbuf, *tbuf, *ubuf, *ha, *hb, *zbuf, *wp, *dis, *b2f, *cw2, *cb2;
    int *rowptr, *cursor, *cnt, *ecol, *eidx;
    __nv_bfloat16 *wt_hi, *wt_lo;
    uint4 *frag_cheb[4], *frag_cls;
    cudaGetSymbolAddress((void**)&sbuf, g_tx1);
    cudaGetSymbolAddress((void**)&tbuf, g_tx2);
    cudaGetSymbolAddress((void**)&ubuf, g_u);
    cudaGetSymbolAddress((void**)&ha, g_ha);
    cudaGetSymbolAddress((void**)&hb, g_hb);
    cudaGetSymbolAddress((void**)&zbuf, g_z);
    cudaGetSymbolAddress((void**)&wp, g_wp);
    cudaGetSymbolAddress((void**)&dis, g_dis);
    cudaGetSymbolAddress((void**)&rowptr, g_rowptr);
    cudaGetSymbolAddress((void**)&cursor, g_cursor);
    cudaGetSymbolAddress((void**)&cnt, g_cnt);
    cudaGetSymbolAddress((void**)&ecol, g_ecol);
    cudaGetSymbolAddress((void**)&eidx, g_eidx);
    cudaGetSymbolAddress((void**)&wt_hi, g_w2t_hi);
    cudaGetSymbolAddress((void**)&wt_lo, g_w2t_lo);
    cudaGetSymbolAddress((void**)&b2f, g_b2f);
    cudaGetSymbolAddress((void**)&cw2, g_cw2);
    cudaGetSymbolAddress((void**)&cb2, g_cb2);
    cudaGetSymbolAddress((void**)&frag_cheb[0], g_frag_cheb0);
    cudaGetSymbolAddress((void**)&frag_cheb[1], g_frag_cheb1);
    cudaGetSymbolAddress((void**)&frag_cheb[2], g_frag_cheb2);
    cudaGetSymbolAddress((void**)&frag_cheb[3], g_frag_cheb3);
    cudaGetSymbolAddress((void**)&frag_cls, g_frag_cls);

    float* vbuf = zbuf;   // reuse first N*64 of zbuf as v (zbuf written later)

    cudaFuncSetAttribute(pae_mma_kernel, cudaFuncAttributeMaxDynamicSharedMemorySize, PAE_SMEM);
    cudaFuncSetAttribute(gemm_mma, cudaFuncAttributeMaxDynamicSharedMemorySize, 65536);

    // ---- CSR build (depends only on edge_index) ----
    cudaMemsetAsync(cnt, 0, (size_t)N * sizeof(int));
    hist_kernel<<<(E + 255) / 256, 256>>>(row, cnt, E);
    scan_kernel<<<1, 1024>>>(cnt, N, rowptr, cursor);
    scatter_kernel<<<(E + 255) / 256, 256>>>(row, col, cursor, ecol, eidx, E);

    // ---- weight prep ----
    fold_pae_kernel<<<1, 128>>>(pae_bn_g, pae_bn_b, pae_bn_rm, pae_bn_rv, pae_w2, pae_b2,
                                wt_hi, wt_lo, b2f);
    fold_cls_kernel<<<1, 256>>>(cls_bn_g, cls_bn_b, cls_bn_rm, cls_bn_rv, cls_w2, cls_b2, cw2, cb2);
    prep_cheb_frag<<<24, 256>>>(cheb_w[0], 128, frag_cheb[0]);
    prep_cheb_frag<<<12, 256>>>(cheb_w[1], 64, frag_cheb[1]);
    prep_cheb_frag<<<12, 256>>>(cheb_w[2], 64, frag_cheb[2]);
    prep_cheb_frag<<<12, 256>>>(cheb_w[3], 64, frag_cheb[3]);
    prep_frag<<<64, 256>>>(cls_w1, 256, 256, frag_cls);

    // ---- PAE edge weights ----
    pae_mma_kernel<<<148, 256, PAE_SMEM>>>(edgenet, pae_w1, pae_b1, wt_hi, wt_lo, b2f, ew, E);

    // ---- graph normalization via CSR ----
    int rowWarpBlocks = (N * 32 + 255) / 256;
    dis_csr_kernel<<<rowWarpBlocks, 256>>>(ew, rowptr, eidx, dis, N);
    wp_kernel<<<(E + 255) / 256, 256>>>(ew, eidx, ecol, dis, wp, E);

    // ---- GCN layers ----
    const float* prev = features;
    int F = 128;
    float* hbufs[2] = {ha, hb};
    int rowTiles = (N + 127) / 128;
    int n4 = N * 16;

    for (int l = 0; l < 4; l++) {
        int ktiles = F >> 4;
        // u = prev @ [W0-W2 | W1 | W2]
        gemm_mma<<<dim3(rowTiles, 3), 256, ktiles * 4096>>>(
            prev, F, N, frag_cheb[l], ktiles, nullptr, 192, ubuf, 0);
        // s = L(u2)
        spmm_csr<<<rowWarpBlocks, 256>>>(ubuf + 128, 192, sbuf, rowptr, ecol, wp, dis, N);
        // v = u1 + 2s
        v_kernel<<<(n4 + 255) / 256, 256>>>(ubuf, sbuf, vbuf, n4);
        // t = L(v)
        spmm_csr<<<rowWarpBlocks, 256>>>(vbuf, 64, tbuf, rowptr, ecol, wp, dis, N);
        // h = relu(u0 + t)
        h_kernel<<<(n4 + 255) / 256, 256>>>(ubuf, tbuf, hbufs[l & 1], jk + (size_t)l * 64, n4);
        prev = hbufs[l & 1];
        F = 64;
    }

    // ---- classifier ----
    gemm_mma<<<dim3(rowTiles, 4), 256, 16 * 4096>>>(
        jk, 256, N, frag_cls, 16, cls_b1, 256, zbuf, 1);
    logit_kernel<<<(N * 32 + 255) / 256, 256>>>(zbuf, cw2, cb2, N, logit);
}

// round 6
// speedup vs baseline: 2.4517x; 1.0786x over previous
#include <cuda_runtime.h>
#include <cuda_bf16.h>
#include <math.h>
#include <stdint.h>

typedef unsigned long long ull;
typedef unsigned int uint;

#define NMAX 50000
#define EMAX 1600000

// ---------------- device scratch (no allocations allowed) ----------------
__device__ float g_v[(size_t)NMAX * 64];        // v = u1 + 2*L(u2)
__device__ float g_u[(size_t)NMAX * 192];       // [u0 | u1 | u2]
__device__ float g_ha[(size_t)NMAX * 64];
__device__ float g_hb[(size_t)NMAX * 64];
__device__ float g_wp[EMAX];                    // ew[e]*dis[col[e]] in CSR order
__device__ float g_dis[NMAX];                   // rsqrt(deg) or 0
__device__ int   g_rowptr[NMAX + 1];
__device__ int   g_cursor[NMAX];
__device__ int   g_cnt[NMAX];
__device__ int   g_ecol[EMAX];                  // col in CSR order
__device__ int   g_eidx[EMAX];                  // original edge id in CSR order
__device__ __nv_bfloat16 g_w2t_hi[128 * 128];   // PAE W2fT hi, [n][k]
__device__ __nv_bfloat16 g_w2t_lo[128 * 128];   // PAE W2fT lo
__device__ float g_b2f[128];
__device__ float g_cw2[256 * 2];
__device__ float g_cb2[2];
// B fragments for mma GEMMs (uint4 = {hi_b0, hi_b1, lo_b0, lo_b1})
__device__ uint4 g_frag_cheb0[3 * 8 * 256];     // K=128, 192 cols
__device__ uint4 g_frag_cheb1[3 * 4 * 256];     // K=64
__device__ uint4 g_frag_cheb2[3 * 4 * 256];
__device__ uint4 g_frag_cheb3[3 * 4 * 256];
__device__ uint4 g_frag_cls[4 * 16 * 256];      // K=256, 256 cols

// =================== warp-level bf16 MMA ===================
__device__ __forceinline__ void mma16816(float* d,
                                         uint a0, uint a1, uint a2, uint a3,
                                         uint b0, uint b1) {
    asm volatile(
        "mma.sync.aligned.m16n8k16.row.col.f32.bf16.bf16.f32 "
        "{%0,%1,%2,%3}, {%4,%5,%6,%7}, {%8,%9}, {%0,%1,%2,%3};"
        : "+f"(d[0]), "+f"(d[1]), "+f"(d[2]), "+f"(d[3])
        : "r"(a0), "r"(a1), "r"(a2), "r"(a3), "r"(b0), "r"(b1));
}

__device__ __forceinline__ void mma16816s(float& d0, float& d1, float& d2, float& d3,
                                          uint a0, uint a1, uint a2, uint a3,
                                          uint b0, uint b1) {
    asm volatile(
        "mma.sync.aligned.m16n8k16.row.col.f32.bf16.bf16.f32 "
        "{%0,%1,%2,%3}, {%4,%5,%6,%7}, {%8,%9}, {%0,%1,%2,%3};"
        : "+f"(d0), "+f"(d1), "+f"(d2), "+f"(d3)
        : "r"(a0), "r"(a1), "r"(a2), "r"(a3), "r"(b0), "r"(b1));
}

__device__ __forceinline__ void split2(float a, float b, uint& hi, uint& lo) {
    __nv_bfloat162 h = __floats2bfloat162_rn(a, b);
    float2 f = __bfloat1622float2(h);
    __nv_bfloat162 l = __floats2bfloat162_rn(a - f.x, b - f.y);
    hi = *(uint*)&h;
    lo = *(uint*)&l;
}

// =================== BN folding kernels ===================
// 129 blocks x 128 threads. Blocks 0..127: output row jj=blk of W2fT (coalesced writes).
// Block 128: b2f.
__global__ void fold_pae_kernel(const float* __restrict__ g, const float* __restrict__ b,
                                const float* __restrict__ rm, const float* __restrict__ rv,
                                const float* __restrict__ w2, const float* __restrict__ b2,
                                __nv_bfloat16* __restrict__ wt_hi, __nv_bfloat16* __restrict__ wt_lo,
                                float* __restrict__ b2f) {
    int j = threadIdx.x;  // 128 threads
    int blk = blockIdx.x;
    if (blk < 128) {
        float sj = g[j] * rsqrtf(rv[j] + 1e-5f);
        int jj = blk;
        float v = sj * __ldg(w2 + (size_t)j * 128 + jj);
        __nv_bfloat16 hi = __float2bfloat16(v);
        wt_hi[jj * 128 + j] = hi;
        wt_lo[jj * 128 + j] = __float2bfloat16(v - __bfloat162float(hi));
    } else {
        __shared__ float t[128];
        float si = g[j] * rsqrtf(rv[j] + 1e-5f);
        t[j] = b[j] - rm[j] * si;
        __syncthreads();
        float acc = b2[j];
#pragma unroll 8
        for (int i = 0; i < 128; i++) acc += t[i] * __ldg(w2 + i * 128 + j);
        b2f[j] = acc;
    }
}

__global__ void fold_cls_kernel(const float* __restrict__ g, const float* __restrict__ b,
                                const float* __restrict__ rm, const float* __restrict__ rv,
                                const float* __restrict__ w2, const float* __restrict__ b2,
                                float* __restrict__ cw2, float* __restrict__ cb2) {
    __shared__ float p0[256], p1[256];
    int i = threadIdx.x;  // 256 threads
    float si = g[i] * rsqrtf(rv[i] + 1e-5f);
    float ti = b[i] - rm[i] * si;
    float w0 = w2[2 * i], w1 = w2[2 * i + 1];
    cw2[2 * i]     = si * w0;
    cw2[2 * i + 1] = si * w1;
    p0[i] = ti * w0;
    p1[i] = ti * w1;
    __syncthreads();
    for (int off = 128; off; off >>= 1) {
        if (i < off) { p0[i] += p0[i + off]; p1[i] += p1[i + off]; }
        __syncthreads();
    }
    if (i == 0) { cb2[0] = b2[0] + p0[0]; cb2[1] = b2[1] + p1[0]; }
}

__global__ void logit_init_kernel(const float* __restrict__ cb2, float* __restrict__ logit, int N) {
    int i = blockIdx.x * blockDim.x + threadIdx.x;
    if (i < N) {
        logit[2 * i]     = cb2[0];
        logit[2 * i + 1] = cb2[1];
    }
}

// =================== fragment prep kernels ===================
__global__ void prep_frag(const float* __restrict__ W, int K, int Ncols, uint4* __restrict__ out) {
    int ktiles = K >> 4;
    int total = (Ncols >> 6) * ktiles * 256;
    int idx = blockIdx.x * 256 + threadIdx.x;
    if (idx >= total) return;
    int lane = idx & 31;
    int nt = (idx >> 5) & 7;
    int rest = idx >> 8;
    int kt = rest % ktiles;
    int chunk = rest / ktiles;
    int n = chunk * 64 + nt * 8 + (lane >> 2);
    int k0 = kt * 16 + (lane & 3) * 2;
    float w00 = W[(size_t)k0 * Ncols + n];
    float w01 = W[(size_t)(k0 + 1) * Ncols + n];
    float w10 = W[(size_t)(k0 + 8) * Ncols + n];
    float w11 = W[(size_t)(k0 + 9) * Ncols + n];
    uint4 v;
    split2(w00, w01, v.x, v.z);
    split2(w10, w11, v.y, v.w);
    out[idx] = v;
}

// Cheb composite Wc[k][n]: n<64: W0-W2 ; 64<=n<128: W1 ; n>=128: W2.  W: [3][K][64]
__device__ __forceinline__ void cheb_frag_body(const float* __restrict__ W, int K,
                                               uint4* __restrict__ out, int idx) {
    int ktiles = K >> 4;
    int lane = idx & 31;
    int nt = (idx >> 5) & 7;
    int rest = idx >> 8;
    int kt = rest % ktiles;
    int chunk = rest / ktiles;
    int n = chunk * 64 + nt * 8 + (lane >> 2);
    int k0 = kt * 16 + (lane & 3) * 2;
    int part = n >> 6, nn = n & 63;
    float w[4];
#pragma unroll
    for (int q = 0; q < 4; q++) {
        int k = k0 + (q >> 1) * 8 + (q & 1);
        float v;
        if (part == 0)      v = W[(size_t)k * 64 + nn] - W[(size_t)(2 * K + k) * 64 + nn];
        else if (part == 1) v = W[(size_t)(K + k) * 64 + nn];
        else                v = W[(size_t)(2 * K + k) * 64 + nn];
        w[q] = v;
    }
    uint4 v;
    split2(w[0], w[1], v.x, v.z);
    split2(w[2], w[3], v.y, v.w);
    out[idx] = v;
}

__global__ void prep_cheb_frag128(const float* __restrict__ W, uint4* __restrict__ out) {
    int idx = blockIdx.x * 256 + threadIdx.x;
    if (idx < 3 * 8 * 256) cheb_frag_body(W, 128, out, idx);
}

__global__ void prep_cheb_frag64x3(const float* __restrict__ W1, const float* __restrict__ W2,
                                   const float* __restrict__ W3,
                                   uint4* __restrict__ o1, uint4* __restrict__ o2,
                                   uint4* __restrict__ o3) {
    int idx = blockIdx.x * 256 + threadIdx.x;
    if (idx >= 3 * 4 * 256) return;
    const float* W = (blockIdx.y == 0) ? W1 : (blockIdx.y == 1) ? W2 : W3;
    uint4* out = (blockIdx.y == 0) ? o1 : (blockIdx.y == 1) ? o2 : o3;
    cheb_frag_body(W, 64, out, idx);
}

// =================== generic split-bf16 mma GEMM (C-writing variant) ===================
__global__ __launch_bounds__(256)
void gemm_mma(const float* __restrict__ A, int lda, int M,
              const uint4* __restrict__ bfrag, int ktiles,
              int ldc, float* __restrict__ C) {
    extern __shared__ uint4 sB[];   // [ktiles][8][32]
    int tid = threadIdx.x, lane = tid & 31, wid = tid >> 5;
    const uint4* src = bfrag + (size_t)blockIdx.y * ktiles * 256;
    for (int i = tid; i < ktiles * 256; i += 256) sB[i] = src[i];
    __syncthreads();

    int r1 = blockIdx.x * 128 + wid * 16 + (lane >> 2);
    int r2 = r1 + 8;
    int rl1 = min(r1, M - 1), rl2 = min(r2, M - 1);
    int cq = (lane & 3) * 2;
    const float* A1 = A + (size_t)rl1 * lda;
    const float* A2 = A + (size_t)rl2 * lda;

    float acc[8][4];
#pragma unroll
    for (int i = 0; i < 8; i++) { acc[i][0] = acc[i][1] = acc[i][2] = acc[i][3] = 0.f; }

    for (int kt = 0; kt < ktiles; kt++) {
        int k0 = kt * 16 + cq;
        float2 xa = *(const float2*)(A1 + k0);
        float2 xb = *(const float2*)(A2 + k0);
        float2 xc = *(const float2*)(A1 + k0 + 8);
        float2 xd = *(const float2*)(A2 + k0 + 8);
        uint ahi[4], alo[4];
        split2(xa.x, xa.y, ahi[0], alo[0]);
        split2(xb.x, xb.y, ahi[1], alo[1]);
        split2(xc.x, xc.y, ahi[2], alo[2]);
        split2(xd.x, xd.y, ahi[3], alo[3]);

        const uint4* bp = sB + kt * 256 + lane;
        uint4 b[8];
#pragma unroll
        for (int nt = 0; nt < 8; nt++) b[nt] = bp[nt * 32];
#pragma unroll
        for (int nt = 0; nt < 8; nt++)
            mma16816(acc[nt], ahi[0], ahi[1], ahi[2], ahi[3], b[nt].x, b[nt].y);
#pragma unroll
        for (int nt = 0; nt < 8; nt++)
            mma16816(acc[nt], alo[0], alo[1], alo[2], alo[3], b[nt].x, b[nt].y);
#pragma unroll
        for (int nt = 0; nt < 8; nt++)
            mma16816(acc[nt], ahi[0], ahi[1], ahi[2], ahi[3], b[nt].z, b[nt].w);
    }

#pragma unroll
    for (int nt = 0; nt < 8; nt++) {
        int cc = blockIdx.y * 64 + nt * 8 + cq;
        if (r1 < M) { float2 o = {acc[nt][0], acc[nt][1]}; *(float2*)(C + (size_t)r1 * ldc + cc) = o; }
        if (r2 < M) { float2 o = {acc[nt][2], acc[nt][3]}; *(float2*)(C + (size_t)r2 * ldc + cc) = o; }
    }
}

// =================== classifier GEMM fused with logit (z never materialized) ===================
__global__ __launch_bounds__(256)
void gemm_mma_cls(const float* __restrict__ A, int lda, int M,
                  const uint4* __restrict__ bfrag, int ktiles,
                  const float* __restrict__ bias, const float* __restrict__ cw2,
                  float* __restrict__ logit) {
    extern __shared__ uint4 sB[];
    int tid = threadIdx.x, lane = tid & 31, wid = tid >> 5;
    const uint4* src = bfrag + (size_t)blockIdx.y * ktiles * 256;
    for (int i = tid; i < ktiles * 256; i += 256) sB[i] = src[i];
    __syncthreads();

    int r1 = blockIdx.x * 128 + wid * 16 + (lane >> 2);
    int r2 = r1 + 8;
    int rl1 = min(r1, M - 1), rl2 = min(r2, M - 1);
    int cq = (lane & 3) * 2;
    const float* A1 = A + (size_t)rl1 * lda;
    const float* A2 = A + (size_t)rl2 * lda;

    float acc[8][4];
#pragma unroll
    for (int i = 0; i < 8; i++) { acc[i][0] = acc[i][1] = acc[i][2] = acc[i][3] = 0.f; }

    for (int kt = 0; kt < ktiles; kt++) {
        int k0 = kt * 16 + cq;
        float2 xa = *(const float2*)(A1 + k0);
        float2 xb = *(const float2*)(A2 + k0);
        float2 xc = *(const float2*)(A1 + k0 + 8);
        float2 xd = *(const float2*)(A2 + k0 + 8);
        uint ahi[4], alo[4];
        split2(xa.x, xa.y, ahi[0], alo[0]);
        split2(xb.x, xb.y, ahi[1], alo[1]);
        split2(xc.x, xc.y, ahi[2], alo[2]);
        split2(xd.x, xd.y, ahi[3], alo[3]);

        const uint4* bp = sB + kt * 256 + lane;
        uint4 b[8];
#pragma unroll
        for (int nt = 0; nt < 8; nt++) b[nt] = bp[nt * 32];
#pragma unroll
        for (int nt = 0; nt < 8; nt++)
            mma16816(acc[nt], ahi[0], ahi[1], ahi[2], ahi[3], b[nt].x, b[nt].y);
#pragma unroll
        for (int nt = 0; nt < 8; nt++)
            mma16816(acc[nt], alo[0], alo[1], alo[2], alo[3], b[nt].x, b[nt].y);
#pragma unroll
        for (int nt = 0; nt < 8; nt++)
            mma16816(acc[nt], ahi[0], ahi[1], ahi[2], ahi[3], b[nt].z, b[nt].w);
    }

    float l0a = 0.f, l1a = 0.f, l0b = 0.f, l1b = 0.f;
#pragma unroll
    for (int nt = 0; nt < 8; nt++) {
        int cc = blockIdx.y * 64 + nt * 8 + cq;
        float b0 = bias[cc], b1 = bias[cc + 1];
        float v0 = fmaxf(acc[nt][0] + b0, 0.f);
        float v1 = fmaxf(acc[nt][1] + b1, 0.f);
        float v2 = fmaxf(acc[nt][2] + b0, 0.f);
        float v3 = fmaxf(acc[nt][3] + b1, 0.f);
        float c00 = cw2[2 * cc], c01 = cw2[2 * cc + 1];
        float c10 = cw2[2 * cc + 2], c11 = cw2[2 * cc + 3];
        l0a = fmaf(v0, c00, fmaf(v1, c10, l0a));
        l1a = fmaf(v0, c01, fmaf(v1, c11, l1a));
        l0b = fmaf(v2, c00, fmaf(v3, c10, l0b));
        l1b = fmaf(v2, c01, fmaf(v3, c11, l1b));
    }
#pragma unroll
    for (int off = 1; off <= 2; off <<= 1) {
        l0a += __shfl_xor_sync(0xffffffffu, l0a, off);
        l1a += __shfl_xor_sync(0xffffffffu, l1a, off);
        l0b += __shfl_xor_sync(0xffffffffu, l0b, off);
        l1b += __shfl_xor_sync(0xffffffffu, l1b, off);
    }
    if ((lane & 3) == 0) {
        if (r1 < M) {
            atomicAdd(&logit[2 * r1], l0a);
            atomicAdd(&logit[2 * r1 + 1], l1a);
        }
        if (r2 < M) {
            atomicAdd(&logit[2 * r2], l0b);
            atomicAdd(&logit[2 * r2 + 1], l1b);
        }
    }
}

// =================== PAE mma.sync kernel (unchanged, passing) ===================
#define PAE_SMEM 69632

__global__ __launch_bounds__(256, 1)
void pae_mma_kernel(const float* __restrict__ edgenet,
                    const float* __restrict__ w1, const float* __restrict__ b1,
                    const __nv_bfloat16* __restrict__ wt_hi, const __nv_bfloat16* __restrict__ wt_lo,
                    const float* __restrict__ b2f,
                    float* __restrict__ ew, int E) {
    extern __shared__ char smraw[];
    uint4* s_bfrag = (uint4*)smraw;
    float* s_w1  = (float*)(smraw + 65536);
    float* s_b1  = (float*)(smraw + 68608);
    float* s_b2f = (float*)(smraw + 69120);

    int tid = threadIdx.x, lane = tid & 31, wid = tid >> 5;

    for (int i = tid; i < 768; i += 256) s_w1[i] = w1[i];
    if (tid < 128) { s_b1[tid] = b1[tid]; s_b2f[tid] = b2f[tid]; }
    for (int idx = tid; idx < 4096; idx += 256) {
        int ln = idx & 31;
        int k2 = (idx >> 5) & 3;
        int nt = (idx >> 7) & 15;
        int hl = idx >> 11;
        const __nv_bfloat16* src = hl ? wt_lo : wt_hi;
        int n = nt * 8 + (ln >> 2);
        int kg0 = (2 * k2) * 16 + (ln & 3) * 2;
        const __nv_bfloat16* base = src + n * 128;
        uint4 v;
        v.x = *(const uint*)(base + kg0);
        v.y = *(const uint*)(base + kg0 + 8);
        v.z = *(const uint*)(base + kg0 + 16);
        v.w = *(const uint*)(base + kg0 + 24);
        s_bfrag[idx] = v;
    }
    __syncthreads();

    int r1 = lane >> 2;
    int cq = (lane & 3) * 2;
    int nT = (E + 7) >> 3;

    for (int t = blockIdx.x * 8 + wid; t < nT; t += gridDim.x * 8) {
        int e0 = t * 8;

        int eb = e0 + (r1 >> 1);
        int e_lo = min(eb, E - 1);
        int e_hi = min(eb + 4, E - 1);
        int hf = (r1 & 1) * 6;
        float z1[6], z2[6];
#pragma unroll
        for (int j = 0; j < 6; j++) {
            z1[j] = __ldg(edgenet + (size_t)e_lo * 12 + hf + j);
            z2[j] = __ldg(edgenet + (size_t)e_hi * 12 + hf + j);
        }
        uint Ahi[8][4], Alo[8][4];
#pragma unroll
        for (int k = 0; k < 8; k++) {
#pragma unroll
            for (int hp = 0; hp < 2; hp++) {
                int c = k * 16 + cq + hp * 8;
                float2 bb = *(const float2*)(s_b1 + c);
                float a0 = bb.x, a1 = bb.y, a2 = bb.x, a3 = bb.y;
#pragma unroll
                for (int j = 0; j < 6; j++) {
                    float2 w = *(const float2*)(s_w1 + j * 128 + c);
                    a0 = fmaf(z1[j], w.x, a0);
                    a1 = fmaf(z1[j], w.y, a1);
                    a2 = fmaf(z2[j], w.x, a2);
                    a3 = fmaf(z2[j], w.y, a3);
                }
                a0 = fmaxf(a0, 0.f); a1 = fmaxf(a1, 0.f);
                a2 = fmaxf(a2, 0.f); a3 = fmaxf(a3, 0.f);
                uint h1, l1, h2, l2;
                split2(a0, a1, h1, l1);
                split2(a2, a3, h2, l2);
                Ahi[k][hp * 2 + 0] = h1;
                Ahi[k][hp * 2 + 1] = h2;
                Alo[k][hp * 2 + 0] = l1;
                Alo[k][hp * 2 + 1] = l2;
            }
        }

        float num_lo = 0.f, ps_lo = 0.f, num_hi = 0.f, ps_hi = 0.f;
#pragma unroll 1
        for (int nt = 0; nt < 16; nt++) {
            const uint4* ph = s_bfrag + (nt * 4) * 32 + lane;
            const uint4* pl = ph + 16 * 4 * 32;
            uint4 bh0 = ph[0], bh1 = ph[32], bh2 = ph[64], bh3 = ph[96];
            uint4 bl0 = pl[0], bl1 = pl[32], bl2 = pl[64], bl3 = pl[96];
            uint bh[16] = {bh0.x, bh0.y, bh0.z, bh0.w, bh1.x, bh1.y, bh1.z, bh1.w,
                           bh2.x, bh2.y, bh2.z, bh2.w, bh3.x, bh3.y, bh3.z, bh3.w};
            uint bl[16] = {bl0.x, bl0.y, bl0.z, bl0.w, bl1.x, bl1.y, bl1.z, bl1.w,
                           bl2.x, bl2.y, bl2.z, bl2.w, bl3.x, bl3.y, bl3.z, bl3.w};
            float dA0 = 0.f, dA1 = 0.f, dA2 = 0.f, dA3 = 0.f;
            float dB0 = 0.f, dB1 = 0.f, dB2 = 0.f, dB3 = 0.f;
            float dC0 = 0.f, dC1 = 0.f, dC2 = 0.f, dC3 = 0.f;
#pragma unroll
            for (int k = 0; k < 8; k++) {
                mma16816s(dA0, dA1, dA2, dA3, Ahi[k][0], Ahi[k][1], Ahi[k][2], Ahi[k][3],
                          bh[2 * k], bh[2 * k + 1]);
                mma16816s(dB0, dB1, dB2, dB3, Ahi[k][0], Ahi[k][1], Ahi[k][2], Ahi[k][3],
                          bl[2 * k], bl[2 * k + 1]);
                mma16816s(dC0, dC1, dC2, dC3, Alo[k][0], Alo[k][1], Alo[k][2], Alo[k][3],
                          bh[2 * k], bh[2 * k + 1]);
            }
            float2 bb = *(const float2*)(s_b2f + nt * 8 + cq);
            float o0 = dA0 + dB0 + dC0 + bb.x;
            float o1 = dA1 + dB1 + dC1 + bb.y;
            float o2 = dA2 + dB2 + dC2 + bb.x;
            float o3 = dA3 + dB3 + dC3 + bb.y;
            float p0 = __shfl_xor_sync(0xffffffffu, o0, 4);
            float p1 = __shfl_xor_sync(0xffffffffu, o1, 4);
            float p2 = __shfl_xor_sync(0xffffffffu, o2, 4);
            float p3 = __shfl_xor_sync(0xffffffffu, o3, 4);
            num_lo = fmaf(o0, p0, fmaf(o1, p1, num_lo));
            ps_lo  = fmaf(o0, o0, fmaf(o1, o1, ps_lo));
            num_hi = fmaf(o2, p2, fmaf(o3, p3, num_hi));
            ps_hi  = fmaf(o2, o2, fmaf(o3, o3, ps_hi));
        }

#pragma unroll
        for (int off = 1; off <= 2; off <<= 1) {
            num_lo += __shfl_xor_sync(0xffffffffu, num_lo, off);
            ps_lo  += __shfl_xor_sync(0xffffffffu, ps_lo, off);
            num_hi += __shfl_xor_sync(0xffffffffu, num_hi, off);
            ps_hi  += __shfl_xor_sync(0xffffffffu, ps_hi, off);
        }
        float psp_lo = __shfl_xor_sync(0xffffffffu, ps_lo, 4);
        float psp_hi = __shfl_xor_sync(0xffffffffu, ps_hi, 4);

        if ((lane & 7) == 0) {
            int eL = lane >> 3;
            int elo = e0 + eL;
            int ehi = e0 + 4 + eL;
            if (elo < E) {
                float den = fmaxf(sqrtf(ps_lo) * sqrtf(psp_lo), 1e-8f);
                ew[elo] = fmaf(num_lo / den, 0.5f, 0.5f);
            }
            if (ehi < E) {
                float den = fmaxf(sqrtf(ps_hi) * sqrtf(psp_hi), 1e-8f);
                ew[ehi] = fmaf(num_hi / den, 0.5f, 0.5f);
            }
        }
    }
}

// =================== CSR build ===================
__global__ void hist_kernel(const int* __restrict__ row, int* __restrict__ cnt, int E) {
    int e = blockIdx.x * blockDim.x + threadIdx.x;
    if (e < E) atomicAdd(&cnt[row[e]], 1);
}

__global__ void scan_kernel(const int* __restrict__ cnt, int N,
                            int* __restrict__ rowptr, int* __restrict__ cursor) {
    __shared__ int part[1024];
    int t = threadIdx.x;
    int chunk = (N + 1023) / 1024;
    int b = t * chunk, e = min(b + chunk, N);
    int s = 0;
    for (int i = b; i < e; i++) s += cnt[i];
    part[t] = s;
    __syncthreads();
    for (int off = 1; off < 1024; off <<= 1) {
        int v = (t >= off) ? part[t - off] : 0;
        __syncthreads();
        part[t] += v;
        __syncthreads();
    }
    int run = t ? part[t - 1] : 0;
    for (int i = b; i < e; i++) {
        rowptr[i] = run;
        cursor[i] = run;
        run += cnt[i];
    }
    if (t == 1023) rowptr[N] = run;
}

__global__ void scatter_kernel(const int* __restrict__ row, const int* __restrict__ col,
                               int* __restrict__ cursor, int* __restrict__ ecol,
                               int* __restrict__ eidx, int E) {
    int e = blockIdx.x * blockDim.x + threadIdx.x;
    if (e >= E) return;
    int pos = atomicAdd(&cursor[row[e]], 1);
    ecol[pos] = col[e];
    eidx[pos] = e;
}

__global__ void dis_csr_kernel(const float* __restrict__ ew, const int* __restrict__ rowptr,
                               const int* __restrict__ eidx, float* __restrict__ dis, int N) {
    int warp = (blockIdx.x * blockDim.x + threadIdx.x) >> 5;
    int lane = threadIdx.x & 31;
    if (warp >= N) return;
    int beg = rowptr[warp], end = rowptr[warp + 1];
    float s = 0.f;
    for (int i = beg + lane; i < end; i += 32) s += __ldg(ew + __ldg(eidx + i));
#pragma unroll
    for (int off = 16; off; off >>= 1) s += __shfl_xor_sync(0xffffffffu, s, off);
    if (lane == 0) dis[warp] = (s > 0.f) ? rsqrtf(s) : 0.f;
}

__global__ void wp_kernel(const float* __restrict__ ew, const int* __restrict__ eidx,
                          const int* __restrict__ ecol, const float* __restrict__ dis,
                          float* __restrict__ wp, int E) {
    int i = blockIdx.x * blockDim.x + threadIdx.x;
    if (i < E) wp[i] = __ldg(ew + eidx[i]) * __ldg(dis + ecol[i]);
}

// =================== fused CSR SpMM pass 1: v = u1 + 2*(-dis)*L'(u2) ===================
__global__ __launch_bounds__(256)
void spmm_v(const float* __restrict__ u,
            const int* __restrict__ rowptr, const int* __restrict__ ecol,
            const float* __restrict__ wp, const float* __restrict__ dis,
            float* __restrict__ v, int N) {
    int warp = (blockIdx.x * blockDim.x + threadIdx.x) >> 5;
    int lane = threadIdx.x & 31;
    if (warp >= N) return;
    int beg = rowptr[warp], end = rowptr[warp + 1];
    int half = lane >> 4;
    int cl = lane & 15;
    float4 acc = {0.f, 0.f, 0.f, 0.f};
    for (int i = beg + half; i < end; i += 2) {
        int c = __ldg(ecol + i);
        float w = __ldg(wp + i);
        float4 xv = *(const float4*)(u + (size_t)c * 192 + 128 + cl * 4);
        acc.x = fmaf(w, xv.x, acc.x);
        acc.y = fmaf(w, xv.y, acc.y);
        acc.z = fmaf(w, xv.z, acc.z);
        acc.w = fmaf(w, xv.w, acc.w);
    }
    acc.x += __shfl_down_sync(0xffffffffu, acc.x, 16);
    acc.y += __shfl_down_sync(0xffffffffu, acc.y, 16);
    acc.z += __shfl_down_sync(0xffffffffu, acc.z, 16);
    acc.w += __shfl_down_sync(0xffffffffu, acc.w, 16);
    if (half == 0) {
        float sc = -2.f * __ldg(dis + warp);
        float4 u1 = *(const float4*)(u + (size_t)warp * 192 + 64 + cl * 4);
        float4 o;
        o.x = fmaf(sc, acc.x, u1.x);
        o.y = fmaf(sc, acc.y, u1.y);
        o.z = fmaf(sc, acc.z, u1.z);
        o.w = fmaf(sc, acc.w, u1.w);
        *(float4*)(v + (size_t)warp * 64 + cl * 4) = o;
    }
}

// =================== fused CSR SpMM pass 2: h = relu(u0 + (-dis)*L'(v)) -> hbuf, jk ===================
__global__ __launch_bounds__(256)
void spmm_h(const float* __restrict__ v, const float* __restrict__ u,
            const int* __restrict__ rowptr, const int* __restrict__ ecol,
            const float* __restrict__ wp, const float* __restrict__ dis,
            float* __restrict__ hbuf, float* __restrict__ jk, int N) {
    int warp = (blockIdx.x * blockDim.x + threadIdx.x) >> 5;
    int lane = threadIdx.x & 31;
    if (warp >= N) return;
    int beg = rowptr[warp], end = rowptr[warp + 1];
    int half = lane >> 4;
    int cl = lane & 15;
    float4 acc = {0.f, 0.f, 0.f, 0.f};
    for (int i = beg + half; i < end; i += 2) {
        int c = __ldg(ecol + i);
        float w = __ldg(wp + i);
        float4 xv = *(const float4*)(v + (size_t)c * 64 + cl * 4);
        acc.x = fmaf(w, xv.x, acc.x);
        acc.y = fmaf(w, xv.y, acc.y);
        acc.z = fmaf(w, xv.z, acc.z);
        acc.w = fmaf(w, xv.w, acc.w);
    }
    acc.x += __shfl_down_sync(0xffffffffu, acc.x, 16);
    acc.y += __shfl_down_sync(0xffffffffu, acc.y, 16);
    acc.z += __shfl_down_sync(0xffffffffu, acc.z, 16);
    acc.w += __shfl_down_sync(0xffffffffu, acc.w, 16);
    if (half == 0) {
        float sc = -__ldg(dis + warp);
        float4 u0 = *(const float4*)(u + (size_t)warp * 192 + cl * 4);
        float4 o;
        o.x = fmaxf(fmaf(sc, acc.x, u0.x), 0.f);
        o.y = fmaxf(fmaf(sc, acc.y, u0.y), 0.f);
        o.z = fmaxf(fmaf(sc, acc.z, u0.z), 0.f);
        o.w = fmaxf(fmaf(sc, acc.w, u0.w), 0.f);
        *(float4*)(hbuf + (size_t)warp * 64 + cl * 4) = o;
        *(float4*)(jk + (size_t)warp * 256 + cl * 4) = o;
    }
}

// =================== launcher ===================
extern "C" void kernel_launch(void* const* d_in, const int* in_sizes, int n_in,
                              void* d_out, int out_size) {
    const float* features = (const float*)d_in[0];
    const int* edge_index = (const int*)d_in[1];
    const float* edgenet  = (const float*)d_in[2];
    const float* pae_w1 = (const float*)d_in[3];
    const float* pae_b1 = (const float*)d_in[4];
    const float* pae_bn_g = (const float*)d_in[5];
    const float* pae_bn_b = (const float*)d_in[6];
    const float* pae_bn_rm = (const float*)d_in[7];
    const float* pae_bn_rv = (const float*)d_in[8];
    const float* pae_w2 = (const float*)d_in[9];
    const float* pae_b2 = (const float*)d_in[10];
    const float* cheb_w[4] = {(const float*)d_in[11], (const float*)d_in[12],
                              (const float*)d_in[13], (const float*)d_in[14]};
    const float* cls_w1 = (const float*)d_in[15];
    const float* cls_b1 = (const float*)d_in[16];
    const float* cls_bn_g = (const float*)d_in[17];
    const float* cls_bn_b = (const float*)d_in[18];
    const float* cls_bn_rm = (const float*)d_in[19];
    const float* cls_bn_rv = (const float*)d_in[20];
    const float* cls_w2 = (const float*)d_in[21];
    const float* cls_b2 = (const float*)d_in[22];

    int N = in_sizes[0] / 128;
    int E = in_sizes[1] / 2;
    const int* row = edge_index;
    const int* col = edge_index + E;

    float* out = (float*)d_out;
    float* jk = out;
    float* logit = out + (size_t)N * 256;
    float* ew = logit + (size_t)N * 2;

    float *vbuf, *ubuf, *ha, *hb, *wp, *dis, *b2f, *cw2, *cb2;
    int *rowptr, *cursor, *cnt, *ecol, *eidx;
    __nv_bfloat16 *wt_hi, *wt_lo;
    uint4 *frag_cheb[4], *frag_cls;
    cudaGetSymbolAddress((void**)&vbuf, g_v);
    cudaGetSymbolAddress((void**)&ubuf, g_u);
    cudaGetSymbolAddress((void**)&ha, g_ha);
    cudaGetSymbolAddress((void**)&hb, g_hb);
    cudaGetSymbolAddress((void**)&wp, g_wp);
    cudaGetSymbolAddress((void**)&dis, g_dis);
    cudaGetSymbolAddress((void**)&rowptr, g_rowptr);
    cudaGetSymbolAddress((void**)&cursor, g_cursor);
    cudaGetSymbolAddress((void**)&cnt, g_cnt);
    cudaGetSymbolAddress((void**)&ecol, g_ecol);
    cudaGetSymbolAddress((void**)&eidx, g_eidx);
    cudaGetSymbolAddress((void**)&wt_hi, g_w2t_hi);
    cudaGetSymbolAddress((void**)&wt_lo, g_w2t_lo);
    cudaGetSymbolAddress((void**)&b2f, g_b2f);
    cudaGetSymbolAddress((void**)&cw2, g_cw2);
    cudaGetSymbolAddress((void**)&cb2, g_cb2);
    cudaGetSymbolAddress((void**)&frag_cheb[0], g_frag_cheb0);
    cudaGetSymbolAddress((void**)&frag_cheb[1], g_frag_cheb1);
    cudaGetSymbolAddress((void**)&frag_cheb[2], g_frag_cheb2);
    cudaGetSymbolAddress((void**)&frag_cheb[3], g_frag_cheb3);
    cudaGetSymbolAddress((void**)&frag_cls, g_frag_cls);

    cudaFuncSetAttribute(pae_mma_kernel, cudaFuncAttributeMaxDynamicSharedMemorySize, PAE_SMEM);
    cudaFuncSetAttribute(gemm_mma, cudaFuncAttributeMaxDynamicSharedMemorySize, 65536);
    cudaFuncSetAttribute(gemm_mma_cls, cudaFuncAttributeMaxDynamicSharedMemorySize, 65536);

    // ---- CSR build ----
    cudaMemsetAsync(cnt, 0, (size_t)N * sizeof(int));
    hist_kernel<<<(E + 255) / 256, 256>>>(row, cnt, E);
    scan_kernel<<<1, 1024>>>(cnt, N, rowptr, cursor);
    scatter_kernel<<<(E + 255) / 256, 256>>>(row, col, cursor, ecol, eidx, E);

    // ---- weight prep ----
    fold_pae_kernel<<<129, 128>>>(pae_bn_g, pae_bn_b, pae_bn_rm, pae_bn_rv, pae_w2, pae_b2,
                                  wt_hi, wt_lo, b2f);
    fold_cls_kernel<<<1, 256>>>(cls_bn_g, cls_bn_b, cls_bn_rm, cls_bn_rv, cls_w2, cls_b2, cw2, cb2);
    prep_cheb_frag128<<<24, 256>>>(cheb_w[0], frag_cheb[0]);
    prep_cheb_frag64x3<<<dim3(12, 3), 256>>>(cheb_w[1], cheb_w[2], cheb_w[3],
                                             frag_cheb[1], frag_cheb[2], frag_cheb[3]);
    prep_frag<<<64, 256>>>(cls_w1, 256, 256, frag_cls);
    logit_init_kernel<<<(N + 255) / 256, 256>>>(cb2, logit, N);

    // ---- PAE edge weights ----
    pae_mma_kernel<<<148, 256, PAE_SMEM>>>(edgenet, pae_w1, pae_b1, wt_hi, wt_lo, b2f, ew, E);

    // ---- graph normalization via CSR ----
    int rowWarpBlocks = (N * 32 + 255) / 256;
    dis_csr_kernel<<<rowWarpBlocks, 256>>>(ew, rowptr, eidx, dis, N);
    wp_kernel<<<(E + 255) / 256, 256>>>(ew, eidx, ecol, dis, wp, E);

    // ---- GCN layers ----
    const float* prev = features;
    int F = 128;
    float* hbufs[2] = {ha, hb};
    int rowTiles = (N + 127) / 128;

    for (int l = 0; l < 4; l++) {
        int ktiles = F >> 4;
        // u = prev @ [W0-W2 | W1 | W2]
        gemm_mma<<<dim3(rowTiles, 3), 256, ktiles * 4096>>>(
            prev, F, N, frag_cheb[l], ktiles, 192, ubuf);
        // v = u1 + 2*L(u2)
        spmm_v<<<rowWarpBlocks, 256>>>(ubuf, rowptr, ecol, wp, dis, vbuf, N);
        // h = relu(u0 + L(v)) -> hbuf, jk
        spmm_h<<<rowWarpBlocks, 256>>>(vbuf, ubuf, rowptr, ecol, wp, dis,
                                       hbufs[l & 1], jk + (size_t)l * 64, N);
        prev = hbufs[l & 1];
        F = 64;
    }

    // ---- classifier fused with logit ----
    gemm_mma_cls<<<dim3(rowTiles, 4), 256, 16 * 4096>>>(
        jk, 256, N, frag_cls, 16, cls_b1, cw2, logit);
}

// round 7
// speedup vs baseline: 2.8263x; 1.1528x over previous
#include <cuda_runtime.h>
#include <cuda_bf16.h>
#include <math.h>
#include <stdint.h>

typedef unsigned long long ull;
typedef unsigned int uint;

#define NMAX 50000
#define EMAX 1600000

// ---------------- device scratch (no allocations allowed) ----------------
__device__ float g_v[(size_t)NMAX * 64];        // v = u1 + 2*L(u2)
__device__ float g_u[(size_t)NMAX * 192];       // [u0 | u1 | u2]
__device__ float g_ha[(size_t)NMAX * 64];
__device__ float g_hb[(size_t)NMAX * 64];
__device__ float g_wp[EMAX];                    // ew[e]*dis[col[e]] in CSR order
__device__ float g_dis[NMAX];                   // rsqrt(deg) or 0
__device__ int   g_rowptr[NMAX + 1];
__device__ int   g_cursor[NMAX];
__device__ int   g_cnt[NMAX];
__device__ int   g_ecol[EMAX];                  // col in CSR order
__device__ int   g_eidx[EMAX];                  // original edge id in CSR order
__device__ __nv_bfloat16 g_w2t_hi[128 * 128];   // PAE W2fT hi, [n][k]
__device__ __nv_bfloat16 g_w2t_lo[128 * 128];   // PAE W2fT lo
__device__ float g_b2f[128];
__device__ float g_cw2[256 * 2];
__device__ float g_cb2[2];
// B fragments for mma GEMMs (uint4 = {hi_b0, hi_b1, lo_b0, lo_b1})
__device__ uint4 g_frag_cheb0[3 * 8 * 256];     // K=128, 192 cols
__device__ uint4 g_frag_cheb1[3 * 4 * 256];     // K=64
__device__ uint4 g_frag_cheb2[3 * 4 * 256];
__device__ uint4 g_frag_cheb3[3 * 4 * 256];
__device__ uint4 g_frag_cls[4 * 16 * 256];      // K=256, 256 cols

// ---------------- side stream + fork/join events (created pre-main, reused) ----------------
static cudaStream_t g_s2 = []() {
    cudaStream_t s; cudaStreamCreateWithFlags(&s, cudaStreamNonBlocking); return s;
}();
static cudaEvent_t g_evF = []() {
    cudaEvent_t e; cudaEventCreateWithFlags(&e, cudaEventDisableTiming); return e;
}();
static cudaEvent_t g_evJ = []() {
    cudaEvent_t e; cudaEventCreateWithFlags(&e, cudaEventDisableTiming); return e;
}();

// =================== warp-level bf16 MMA ===================
__device__ __forceinline__ void mma16816(float* d,
                                         uint a0, uint a1, uint a2, uint a3,
                                         uint b0, uint b1) {
    asm volatile(
        "mma.sync.aligned.m16n8k16.row.col.f32.bf16.bf16.f32 "
        "{%0,%1,%2,%3}, {%4,%5,%6,%7}, {%8,%9}, {%0,%1,%2,%3};"
        : "+f"(d[0]), "+f"(d[1]), "+f"(d[2]), "+f"(d[3])
        : "r"(a0), "r"(a1), "r"(a2), "r"(a3), "r"(b0), "r"(b1));
}

__device__ __forceinline__ void mma16816s(float& d0, float& d1, float& d2, float& d3,
                                          uint a0, uint a1, uint a2, uint a3,
                                          uint b0, uint b1) {
    asm volatile(
        "mma.sync.aligned.m16n8k16.row.col.f32.bf16.bf16.f32 "
        "{%0,%1,%2,%3}, {%4,%5,%6,%7}, {%8,%9}, {%0,%1,%2,%3};"
        : "+f"(d0), "+f"(d1), "+f"(d2), "+f"(d3)
        : "r"(a0), "r"(a1), "r"(a2), "r"(a3), "r"(b0), "r"(b1));
}

__device__ __forceinline__ void mma16808(float* d, uint a0, uint a1, uint b0) {
    asm volatile(
        "mma.sync.aligned.m16n8k8.row.col.f32.bf16.bf16.f32 "
        "{%0,%1,%2,%3}, {%4,%5}, {%6}, {%0,%1,%2,%3};"
        : "+f"(d[0]), "+f"(d[1]), "+f"(d[2]), "+f"(d[3])
        : "r"(a0), "r"(a1), "r"(b0));
}

__device__ __forceinline__ void split2(float a, float b, uint& hi, uint& lo) {
    __nv_bfloat162 h = __floats2bfloat162_rn(a, b);
    float2 f = __bfloat1622float2(h);
    __nv_bfloat162 l = __floats2bfloat162_rn(a - f.x, b - f.y);
    hi = *(uint*)&h;
    lo = *(uint*)&l;
}

// =================== BN folding kernels ===================
__global__ void fold_pae_kernel(const float* __restrict__ g, const float* __restrict__ b,
                                const float* __restrict__ rm, const float* __restrict__ rv,
                                const float* __restrict__ w2, const float* __restrict__ b2,
                                __nv_bfloat16* __restrict__ wt_hi, __nv_bfloat16* __restrict__ wt_lo,
                                float* __restrict__ b2f) {
    int j = threadIdx.x;  // 128 threads
    int blk = blockIdx.x;
    if (blk < 128) {
        float sj = g[j] * rsqrtf(rv[j] + 1e-5f);
        int jj = blk;
        float v = sj * __ldg(w2 + (size_t)j * 128 + jj);
        __nv_bfloat16 hi = __float2bfloat16(v);
        wt_hi[jj * 128 + j] = hi;
        wt_lo[jj * 128 + j] = __float2bfloat16(v - __bfloat162float(hi));
    } else {
        __shared__ float t[128];
        float si = g[j] * rsqrtf(rv[j] + 1e-5f);
        t[j] = b[j] - rm[j] * si;
        __syncthreads();
        float acc = b2[j];
#pragma unroll 8
        for (int i = 0; i < 128; i++) acc += t[i] * __ldg(w2 + i * 128 + j);
        b2f[j] = acc;
    }
}

__global__ void fold_cls_kernel(const float* __restrict__ g, const float* __restrict__ b,
                                const float* __restrict__ rm, const float* __restrict__ rv,
                                const float* __restrict__ w2, const float* __restrict__ b2,
                                float* __restrict__ cw2, float* __restrict__ cb2) {
    __shared__ float p0[256], p1[256];
    int i = threadIdx.x;  // 256 threads
    float si = g[i] * rsqrtf(rv[i] + 1e-5f);
    float ti = b[i] - rm[i] * si;
    float w0 = w2[2 * i], w1 = w2[2 * i + 1];
    cw2[2 * i]     = si * w0;
    cw2[2 * i + 1] = si * w1;
    p0[i] = ti * w0;
    p1[i] = ti * w1;
    __syncthreads();
    for (int off = 128; off; off >>= 1) {
        if (i < off) { p0[i] += p0[i + off]; p1[i] += p1[i + off]; }
        __syncthreads();
    }
    if (i == 0) { cb2[0] = b2[0] + p0[0]; cb2[1] = b2[1] + p1[0]; }
}

__global__ void logit_init_kernel(const float* __restrict__ cb2, float* __restrict__ logit, int N) {
    int i = blockIdx.x * blockDim.x + threadIdx.x;
    if (i < N) {
        logit[2 * i]     = cb2[0];
        logit[2 * i + 1] = cb2[1];
    }
}

// =================== fragment prep kernels ===================
__global__ void prep_frag(const float* __restrict__ W, int K, int Ncols, uint4* __restrict__ out) {
    int ktiles = K >> 4;
    int total = (Ncols >> 6) * ktiles * 256;
    int idx = blockIdx.x * 256 + threadIdx.x;
    if (idx >= total) return;
    int lane = idx & 31;
    int nt = (idx >> 5) & 7;
    int rest = idx >> 8;
    int kt = rest % ktiles;
    int chunk = rest / ktiles;
    int n = chunk * 64 + nt * 8 + (lane >> 2);
    int k0 = kt * 16 + (lane & 3) * 2;
    float w00 = W[(size_t)k0 * Ncols + n];
    float w01 = W[(size_t)(k0 + 1) * Ncols + n];
    float w10 = W[(size_t)(k0 + 8) * Ncols + n];
    float w11 = W[(size_t)(k0 + 9) * Ncols + n];
    uint4 v;
    split2(w00, w01, v.x, v.z);
    split2(w10, w11, v.y, v.w);
    out[idx] = v;
}

// Cheb composite Wc[k][n]: n<64: W0-W2 ; 64<=n<128: W1 ; n>=128: W2.  W: [3][K][64]
__device__ __forceinline__ void cheb_frag_body(const float* __restrict__ W, int K,
                                               uint4* __restrict__ out, int idx) {
    int ktiles = K >> 4;
    int lane = idx & 31;
    int nt = (idx >> 5) & 7;
    int rest = idx >> 8;
    int kt = rest % ktiles;
    int chunk = rest / ktiles;
    int n = chunk * 64 + nt * 8 + (lane >> 2);
    int k0 = kt * 16 + (lane & 3) * 2;
    int part = n >> 6, nn = n & 63;
    float w[4];
#pragma unroll
    for (int q = 0; q < 4; q++) {
        int k = k0 + (q >> 1) * 8 + (q & 1);
        float v;
        if (part == 0)      v = W[(size_t)k * 64 + nn] - W[(size_t)(2 * K + k) * 64 + nn];
        else if (part == 1) v = W[(size_t)(K + k) * 64 + nn];
        else                v = W[(size_t)(2 * K + k) * 64 + nn];
        w[q] = v;
    }
    uint4 v;
    split2(w[0], w[1], v.x, v.z);
    split2(w[2], w[3], v.y, v.w);
    out[idx] = v;
}

__global__ void prep_cheb_frag128(const float* __restrict__ W, uint4* __restrict__ out) {
    int idx = blockIdx.x * 256 + threadIdx.x;
    if (idx < 3 * 8 * 256) cheb_frag_body(W, 128, out, idx);
}

__global__ void prep_cheb_frag64x3(const float* __restrict__ W1, const float* __restrict__ W2,
                                   const float* __restrict__ W3,
                                   uint4* __restrict__ o1, uint4* __restrict__ o2,
                                   uint4* __restrict__ o3) {
    int idx = blockIdx.x * 256 + threadIdx.x;
    if (idx >= 3 * 4 * 256) return;
    const float* W = (blockIdx.y == 0) ? W1 : (blockIdx.y == 1) ? W2 : W3;
    uint4* out = (blockIdx.y == 0) ? o1 : (blockIdx.y == 1) ? o2 : o3;
    cheb_frag_body(W, 64, out, idx);
}

// =================== generic split-bf16 mma GEMM (C-writing variant) ===================
__global__ __launch_bounds__(256)
void gemm_mma(const float* __restrict__ A, int lda, int M,
              const uint4* __restrict__ bfrag, int ktiles,
              int ldc, float* __restrict__ C) {
    extern __shared__ uint4 sB[];   // [ktiles][8][32]
    int tid = threadIdx.x, lane = tid & 31, wid = tid >> 5;
    const uint4* src = bfrag + (size_t)blockIdx.y * ktiles * 256;
    for (int i = tid; i < ktiles * 256; i += 256) sB[i] = src[i];
    __syncthreads();

    int r1 = blockIdx.x * 128 + wid * 16 + (lane >> 2);
    int r2 = r1 + 8;
    int rl1 = min(r1, M - 1), rl2 = min(r2, M - 1);
    int cq = (lane & 3) * 2;
    const float* A1 = A + (size_t)rl1 * lda;
    const float* A2 = A + (size_t)rl2 * lda;

    float acc[8][4];
#pragma unroll
    for (int i = 0; i < 8; i++) { acc[i][0] = acc[i][1] = acc[i][2] = acc[i][3] = 0.f; }

    for (int kt = 0; kt < ktiles; kt++) {
        int k0 = kt * 16 + cq;
        float2 xa = *(const float2*)(A1 + k0);
        float2 xb = *(const float2*)(A2 + k0);
        float2 xc = *(const float2*)(A1 + k0 + 8);
        float2 xd = *(const float2*)(A2 + k0 + 8);
        uint ahi[4], alo[4];
        split2(xa.x, xa.y, ahi[0], alo[0]);
        split2(xb.x, xb.y, ahi[1], alo[1]);
        split2(xc.x, xc.y, ahi[2], alo[2]);
        split2(xd.x, xd.y, ahi[3], alo[3]);

        const uint4* bp = sB + kt * 256 + lane;
        uint4 b[8];
#pragma unroll
        for (int nt = 0; nt < 8; nt++) b[nt] = bp[nt * 32];
#pragma unroll
        for (int nt = 0; nt < 8; nt++)
            mma16816(acc[nt], ahi[0], ahi[1], ahi[2], ahi[3], b[nt].x, b[nt].y);
#pragma unroll
        for (int nt = 0; nt < 8; nt++)
            mma16816(acc[nt], alo[0], alo[1], alo[2], alo[3], b[nt].x, b[nt].y);
#pragma unroll
        for (int nt = 0; nt < 8; nt++)
            mma16816(acc[nt], ahi[0], ahi[1], ahi[2], ahi[3], b[nt].z, b[nt].w);
    }

#pragma unroll
    for (int nt = 0; nt < 8; nt++) {
        int cc = blockIdx.y * 64 + nt * 8 + cq;
        if (r1 < M) { float2 o = {acc[nt][0], acc[nt][1]}; *(float2*)(C + (size_t)r1 * ldc + cc) = o; }
        if (r2 < M) { float2 o = {acc[nt][2], acc[nt][3]}; *(float2*)(C + (size_t)r2 * ldc + cc) = o; }
    }
}

// =================== classifier GEMM fused with logit ===================
__global__ __launch_bounds__(256)
void gemm_mma_cls(const float* __restrict__ A, int lda, int M,
                  const uint4* __restrict__ bfrag, int ktiles,
                  const float* __restrict__ bias, const float* __restrict__ cw2,
                  float* __restrict__ logit) {
    extern __shared__ uint4 sB[];
    int tid = threadIdx.x, lane = tid & 31, wid = tid >> 5;
    const uint4* src = bfrag + (size_t)blockIdx.y * ktiles * 256;
    for (int i = tid; i < ktiles * 256; i += 256) sB[i] = src[i];
    __syncthreads();

    int r1 = blockIdx.x * 128 + wid * 16 + (lane >> 2);
    int r2 = r1 + 8;
    int rl1 = min(r1, M - 1), rl2 = min(r2, M - 1);
    int cq = (lane & 3) * 2;
    const float* A1 = A + (size_t)rl1 * lda;
    const float* A2 = A + (size_t)rl2 * lda;

    float acc[8][4];
#pragma unroll
    for (int i = 0; i < 8; i++) { acc[i][0] = acc[i][1] = acc[i][2] = acc[i][3] = 0.f; }

    for (int kt = 0; kt < ktiles; kt++) {
        int k0 = kt * 16 + cq;
        float2 xa = *(const float2*)(A1 + k0);
        float2 xb = *(const float2*)(A2 + k0);
        float2 xc = *(const float2*)(A1 + k0 + 8);
        float2 xd = *(const float2*)(A2 + k0 + 8);
        uint ahi[4], alo[4];
        split2(xa.x, xa.y, ahi[0], alo[0]);
        split2(xb.x, xb.y, ahi[1], alo[1]);
        split2(xc.x, xc.y, ahi[2], alo[2]);
        split2(xd.x, xd.y, ahi[3], alo[3]);

        const uint4* bp = sB + kt * 256 + lane;
        uint4 b[8];
#pragma unroll
        for (int nt = 0; nt < 8; nt++) b[nt] = bp[nt * 32];
#pragma unroll
        for (int nt = 0; nt < 8; nt++)
            mma16816(acc[nt], ahi[0], ahi[1], ahi[2], ahi[3], b[nt].x, b[nt].y);
#pragma unroll
        for (int nt = 0; nt < 8; nt++)
            mma16816(acc[nt], alo[0], alo[1], alo[2], alo[3], b[nt].x, b[nt].y);
#pragma unroll
        for (int nt = 0; nt < 8; nt++)
            mma16816(acc[nt], ahi[0], ahi[1], ahi[2], ahi[3], b[nt].z, b[nt].w);
    }

    float l0a = 0.f, l1a = 0.f, l0b = 0.f, l1b = 0.f;
#pragma unroll
    for (int nt = 0; nt < 8; nt++) {
        int cc = blockIdx.y * 64 + nt * 8 + cq;
        float b0 = bias[cc], b1 = bias[cc + 1];
        float v0 = fmaxf(acc[nt][0] + b0, 0.f);
        float v1 = fmaxf(acc[nt][1] + b1, 0.f);
        float v2 = fmaxf(acc[nt][2] + b0, 0.f);
        float v3 = fmaxf(acc[nt][3] + b1, 0.f);
        float c00 = cw2[2 * cc], c01 = cw2[2 * cc + 1];
        float c10 = cw2[2 * cc + 2], c11 = cw2[2 * cc + 3];
        l0a = fmaf(v0, c00, fmaf(v1, c10, l0a));
        l1a = fmaf(v0, c01, fmaf(v1, c11, l1a));
        l0b = fmaf(v2, c00, fmaf(v3, c10, l0b));
        l1b = fmaf(v2, c01, fmaf(v3, c11, l1b));
    }
#pragma unroll
    for (int off = 1; off <= 2; off <<= 1) {
        l0a += __shfl_xor_sync(0xffffffffu, l0a, off);
        l1a += __shfl_xor_sync(0xffffffffu, l1a, off);
        l0b += __shfl_xor_sync(0xffffffffu, l0b, off);
        l1b += __shfl_xor_sync(0xffffffffu, l1b, off);
    }
    if ((lane & 3) == 0) {
        if (r1 < M) {
            atomicAdd(&logit[2 * r1], l0a);
            atomicAdd(&logit[2 * r1 + 1], l1a);
        }
        if (r2 < M) {
            atomicAdd(&logit[2 * r2], l0b);
            atomicAdd(&logit[2 * r2 + 1], l1b);
        }
    }
}

// =================== PAE mma.sync kernel (h-stage now on tensor pipe) ===================
// SMEM: [0,65536) W2fT fragments; [65536,69632) W1 k8 B-fragments (uint2 {hi,lo});
//       [69632,70144) b2f.
#define PAE_SMEM 70144

__global__ __launch_bounds__(256, 1)
void pae_mma_kernel(const float* __restrict__ edgenet,
                    const float* __restrict__ w1, const float* __restrict__ b1,
                    const __nv_bfloat16* __restrict__ wt_hi, const __nv_bfloat16* __restrict__ wt_lo,
                    const float* __restrict__ b2f,
                    float* __restrict__ ew, int E) {
    extern __shared__ char smraw[];
    uint4* s_bfrag = (uint4*)smraw;
    uint2* s_w1f = (uint2*)(smraw + 65536);   // [16 ntiles][32 lanes]
    float* s_b2f = (float*)(smraw + 69632);

    int tid = threadIdx.x, lane = tid & 31, wid = tid >> 5;

    if (tid < 128) s_b2f[tid] = b2f[tid];
    // W1 k8 B-fragments: B[k][n] = W1[k][n] (k<6), b1[n] (k==6), 0 (k==7).
    for (int idx = tid; idx < 512; idx += 256) {
        int nt = idx >> 5, ln = idx & 31;
        int n = nt * 8 + (ln >> 2);
        int k0 = (ln & 3) * 2;
        float v0, v1;
        if (k0 < 6) { v0 = __ldg(w1 + k0 * 128 + n); v1 = __ldg(w1 + (k0 + 1) * 128 + n); }
        else        { v0 = __ldg(b1 + n); v1 = 0.f; }
        uint hi, lo;
        split2(v0, v1, hi, lo);
        s_w1f[idx] = make_uint2(hi, lo);
    }
    // W2fT main-GEMM fragments
    for (int idx = tid; idx < 4096; idx += 256) {
        int ln = idx & 31;
        int k2 = (idx >> 5) & 3;
        int nt = (idx >> 7) & 15;
        int hl = idx >> 11;
        const __nv_bfloat16* src = hl ? wt_lo : wt_hi;
        int n = nt * 8 + (ln >> 2);
        int kg0 = (2 * k2) * 16 + (ln & 3) * 2;
        const __nv_bfloat16* base = src + n * 128;
        uint4 v;
        v.x = *(const uint*)(base + kg0);
        v.y = *(const uint*)(base + kg0 + 8);
        v.z = *(const uint*)(base + kg0 + 16);
        v.w = *(const uint*)(base + kg0 + 24);
        s_bfrag[idx] = v;
    }
    __syncthreads();

    int r1 = lane >> 2;
    int cq = (lane & 3) * 2;
    int nT = (E + 7) >> 3;

    for (int t = blockIdx.x * 8 + wid; t < nT; t += gridDim.x * 8) {
        int e0 = t * 8;

        // ---- z A-fragments (k8): rows r1 (edge e_lo half) and r1+8 (edge e_hi half) ----
        int eb = e0 + (r1 >> 1);
        int e_lo = min(eb, E - 1);
        int e_hi = min(eb + 4, E - 1);
        int hf = (r1 & 1) * 6;
        uint zhi0, zlo0, zhi1, zlo1;
        if (cq < 6) {
            float za0 = __ldg(edgenet + (size_t)e_lo * 12 + hf + cq);
            float za1 = __ldg(edgenet + (size_t)e_lo * 12 + hf + cq + 1);
            float zb0 = __ldg(edgenet + (size_t)e_hi * 12 + hf + cq);
            float zb1 = __ldg(edgenet + (size_t)e_hi * 12 + hf + cq + 1);
            split2(za0, za1, zhi0, zlo0);
            split2(zb0, zb1, zhi1, zlo1);
        } else {
            zhi0 = 0x00003f80u;  // (1.0, 0) bf16x2: bias row selector
            zhi1 = 0x00003f80u;
            zlo0 = 0u; zlo1 = 0u;
        }

        // ---- h-stage via m16n8k8 MMAs; D maps directly onto main A-fragment slots ----
        uint Ahi[8][4], Alo[8][4];
#pragma unroll
        for (int j = 0; j < 8; j++) {
            uint2 we = s_w1f[(2 * j) * 32 + lane];
            uint2 wo = s_w1f[(2 * j + 1) * 32 + lane];
            float De[4] = {0.f, 0.f, 0.f, 0.f};
            float Do[4] = {0.f, 0.f, 0.f, 0.f};
            mma16808(De, zhi0, zhi1, we.x);
            mma16808(De, zlo0, zlo1, we.x);
            mma16808(De, zhi0, zhi1, we.y);
            mma16808(Do, zhi0, zhi1, wo.x);
            mma16808(Do, zlo0, zlo1, wo.x);
            mma16808(Do, zhi0, zhi1, wo.y);
            float v0 = fmaxf(De[0], 0.f), v1 = fmaxf(De[1], 0.f);
            float v2 = fmaxf(De[2], 0.f), v3 = fmaxf(De[3], 0.f);
            split2(v0, v1, Ahi[j][0], Alo[j][0]);
            split2(v2, v3, Ahi[j][1], Alo[j][1]);
            v0 = fmaxf(Do[0], 0.f); v1 = fmaxf(Do[1], 0.f);
            v2 = fmaxf(Do[2], 0.f); v3 = fmaxf(Do[3], 0.f);
            split2(v0, v1, Ahi[j][2], Alo[j][2]);
            split2(v2, v3, Ahi[j][3], Alo[j][3]);
        }

        // ---- main MMA + cosine over 16 n-tiles ----
        float num_lo = 0.f, ps_lo = 0.f, num_hi = 0.f, ps_hi = 0.f;
#pragma unroll 1
        for (int nt = 0; nt < 16; nt++) {
            const uint4* ph = s_bfrag + (nt * 4) * 32 + lane;
            const uint4* pl = ph + 16 * 4 * 32;
            uint4 bh0 = ph[0], bh1 = ph[32], bh2 = ph[64], bh3 = ph[96];
            uint4 bl0 = pl[0], bl1 = pl[32], bl2 = pl[64], bl3 = pl[96];
            uint bh[16] = {bh0.x, bh0.y, bh0.z, bh0.w, bh1.x, bh1.y, bh1.z, bh1.w,
                           bh2.x, bh2.y, bh2.z, bh2.w, bh3.x, bh3.y, bh3.z, bh3.w};
            uint bl[16] = {bl0.x, bl0.y, bl0.z, bl0.w, bl1.x, bl1.y, bl1.z, bl1.w,
                           bl2.x, bl2.y, bl2.z, bl2.w, bl3.x, bl3.y, bl3.z, bl3.w};
            float dA0 = 0.f, dA1 = 0.f, dA2 = 0.f, dA3 = 0.f;
            float dB0 = 0.f, dB1 = 0.f, dB2 = 0.f, dB3 = 0.f;
            float dC0 = 0.f, dC1 = 0.f, dC2 = 0.f, dC3 = 0.f;
#pragma unroll
            for (int k = 0; k < 8; k++) {
                mma16816s(dA0, dA1, dA2, dA3, Ahi[k][0], Ahi[k][1], Ahi[k][2], Ahi[k][3],
                          bh[2 * k], bh[2 * k + 1]);
                mma16816s(dB0, dB1, dB2, dB3, Ahi[k][0], Ahi[k][1], Ahi[k][2], Ahi[k][3],
                          bl[2 * k], bl[2 * k + 1]);
                mma16816s(dC0, dC1, dC2, dC3, Alo[k][0], Alo[k][1], Alo[k][2], Alo[k][3],
                          bh[2 * k], bh[2 * k + 1]);
            }
            float2 bb = *(const float2*)(s_b2f + nt * 8 + cq);
            float o0 = dA0 + dB0 + dC0 + bb.x;
            float o1 = dA1 + dB1 + dC1 + bb.y;
            float o2 = dA2 + dB2 + dC2 + bb.x;
            float o3 = dA3 + dB3 + dC3 + bb.y;
            float p0 = __shfl_xor_sync(0xffffffffu, o0, 4);
            float p1 = __shfl_xor_sync(0xffffffffu, o1, 4);
            float p2 = __shfl_xor_sync(0xffffffffu, o2, 4);
            float p3 = __shfl_xor_sync(0xffffffffu, o3, 4);
            num_lo = fmaf(o0, p0, fmaf(o1, p1, num_lo));
            ps_lo  = fmaf(o0, o0, fmaf(o1, o1, ps_lo));
            num_hi = fmaf(o2, p2, fmaf(o3, p3, num_hi));
            ps_hi  = fmaf(o2, o2, fmaf(o3, o3, ps_hi));
        }

#pragma unroll
        for (int off = 1; off <= 2; off <<= 1) {
            num_lo += __shfl_xor_sync(0xffffffffu, num_lo, off);
            ps_lo  += __shfl_xor_sync(0xffffffffu, ps_lo, off);
            num_hi += __shfl_xor_sync(0xffffffffu, num_hi, off);
            ps_hi  += __shfl_xor_sync(0xffffffffu, ps_hi, off);
        }
        float psp_lo = __shfl_xor_sync(0xffffffffu, ps_lo, 4);
        float psp_hi = __shfl_xor_sync(0xffffffffu, ps_hi, 4);

        if ((lane & 7) == 0) {
            int eL = lane >> 3;
            int elo = e0 + eL;
            int ehi = e0 + 4 + eL;
            if (elo < E) {
                float den = fmaxf(sqrtf(ps_lo) * sqrtf(psp_lo), 1e-8f);
                ew[elo] = fmaf(num_lo / den, 0.5f, 0.5f);
            }
            if (ehi < E) {
                float den = fmaxf(sqrtf(ps_hi) * sqrtf(psp_hi), 1e-8f);
                ew[ehi] = fmaf(num_hi / den, 0.5f, 0.5f);
            }
        }
    }
}

// =================== CSR build ===================
__global__ void hist_kernel(const int* __restrict__ row, int* __restrict__ cnt, int E) {
    int e = blockIdx.x * blockDim.x + threadIdx.x;
    if (e < E) atomicAdd(&cnt[row[e]], 1);
}

__global__ void scan_kernel(const int* __restrict__ cnt, int N,
                            int* __restrict__ rowptr, int* __restrict__ cursor) {
    __shared__ int part[1024];
    int t = threadIdx.x;
    int chunk = (N + 1023) / 1024;
    int b = t * chunk, e = min(b + chunk, N);
    int s = 0;
    for (int i = b; i < e; i++) s += cnt[i];
    part[t] = s;
    __syncthreads();
    for (int off = 1; off < 1024; off <<= 1) {
        int v = (t >= off) ? part[t - off] : 0;
        __syncthreads();
        part[t] += v;
        __syncthreads();
    }
    int run = t ? part[t - 1] : 0;
    for (int i = b; i < e; i++) {
        rowptr[i] = run;
        cursor[i] = run;
        run += cnt[i];
    }
    if (t == 1023) rowptr[N] = run;
}

__global__ void scatter_kernel(const int* __restrict__ row, const int* __restrict__ col,
                               int* __restrict__ cursor, int* __restrict__ ecol,
                               int* __restrict__ eidx, int E) {
    int e = blockIdx.x * blockDim.x + threadIdx.x;
    if (e >= E) return;
    int pos = atomicAdd(&cursor[row[e]], 1);
    ecol[pos] = col[e];
    eidx[pos] = e;
}

__global__ void dis_csr_kernel(const float* __restrict__ ew, const int* __restrict__ rowptr,
                               const int* __restrict__ eidx, float* __restrict__ dis, int N) {
    int warp = (blockIdx.x * blockDim.x + threadIdx.x) >> 5;
    int lane = threadIdx.x & 31;
    if (warp >= N) return;
    int beg = rowptr[warp], end = rowptr[warp + 1];
    float s = 0.f;
    for (int i = beg + lane; i < end; i += 32) s += __ldg(ew + __ldg(eidx + i));
#pragma unroll
    for (int off = 16; off; off >>= 1) s += __shfl_xor_sync(0xffffffffu, s, off);
    if (lane == 0) dis[warp] = (s > 0.f) ? rsqrtf(s) : 0.f;
}

__global__ void wp_kernel(const float* __restrict__ ew, const int* __restrict__ eidx,
                          const int* __restrict__ ecol, const float* __restrict__ dis,
                          float* __restrict__ wp, int E) {
    int i = blockIdx.x * blockDim.x + threadIdx.x;
    if (i < E) wp[i] = __ldg(ew + eidx[i]) * __ldg(dis + ecol[i]);
}

// =================== fused CSR SpMM pass 1: v = u1 + 2*(-dis)*L'(u2) ===================
__global__ __launch_bounds__(256)
void spmm_v(const float* __restrict__ u,
            const int* __restrict__ rowptr, const int* __restrict__ ecol,
            const float* __restrict__ wp, const float* __restrict__ dis,
            float* __restrict__ v, int N) {
    int warp = (blockIdx.x * blockDim.x + threadIdx.x) >> 5;
    int lane = threadIdx.x & 31;
    if (warp >= N) return;
    int beg = rowptr[warp], end = rowptr[warp + 1];
    int half = lane >> 4;
    int cl = lane & 15;
    float4 acc = {0.f, 0.f, 0.f, 0.f};
#pragma unroll 4
    for (int i = beg + half; i < end; i += 2) {
        int c = __ldg(ecol + i);
        float w = __ldg(wp + i);
        float4 xv = *(const float4*)(u + (size_t)c * 192 + 128 + cl * 4);
        acc.x = fmaf(w, xv.x, acc.x);
        acc.y = fmaf(w, xv.y, acc.y);
        acc.z = fmaf(w, xv.z, acc.z);
        acc.w = fmaf(w, xv.w, acc.w);
    }
    acc.x += __shfl_down_sync(0xffffffffu, acc.x, 16);
    acc.y += __shfl_down_sync(0xffffffffu, acc.y, 16);
    acc.z += __shfl_down_sync(0xffffffffu, acc.z, 16);
    acc.w += __shfl_down_sync(0xffffffffu, acc.w, 16);
    if (half == 0) {
        float sc = -2.f * __ldg(dis + warp);
        float4 u1 = *(const float4*)(u + (size_t)warp * 192 + 64 + cl * 4);
        float4 o;
        o.x = fmaf(sc, acc.x, u1.x);
        o.y = fmaf(sc, acc.y, u1.y);
        o.z = fmaf(sc, acc.z, u1.z);
        o.w = fmaf(sc, acc.w, u1.w);
        *(float4*)(v + (size_t)warp * 64 + cl * 4) = o;
    }
}

// =================== fused CSR SpMM pass 2: h = relu(u0 + (-dis)*L'(v)) -> hbuf, jk ===================
__global__ __launch_bounds__(256)
void spmm_h(const float* __restrict__ v, const float* __restrict__ u,
            const int* __restrict__ rowptr, const int* __restrict__ ecol,
            const float* __restrict__ wp, const float* __restrict__ dis,
            float* __restrict__ hbuf, float* __restrict__ jk, int N) {
    int warp = (blockIdx.x * blockDim.x + threadIdx.x) >> 5;
    int lane = threadIdx.x & 31;
    if (warp >= N) return;
    int beg = rowptr[warp], end = rowptr[warp + 1];
    int half = lane >> 4;
    int cl = lane & 15;
    float4 acc = {0.f, 0.f, 0.f, 0.f};
#pragma unroll 4
    for (int i = beg + half; i < end; i += 2) {
        int c = __ldg(ecol + i);
        float w = __ldg(wp + i);
        float4 xv = *(const float4*)(v + (size_t)c * 64 + cl * 4);
        acc.x = fmaf(w, xv.x, acc.x);
        acc.y = fmaf(w, xv.y, acc.y);
        acc.z = fmaf(w, xv.z, acc.z);
        acc.w = fmaf(w, xv.w, acc.w);
    }
    acc.x += __shfl_down_sync(0xffffffffu, acc.x, 16);
    acc.y += __shfl_down_sync(0xffffffffu, acc.y, 16);
    acc.z += __shfl_down_sync(0xffffffffu, acc.z, 16);
    acc.w += __shfl_down_sync(0xffffffffu, acc.w, 16);
    if (half == 0) {
        float sc = -__ldg(dis + warp);
        float4 u0 = *(const float4*)(u + (size_t)warp * 192 + cl * 4);
        float4 o;
        o.x = fmaxf(fmaf(sc, acc.x, u0.x), 0.f);
        o.y = fmaxf(fmaf(sc, acc.y, u0.y), 0.f);
        o.z = fmaxf(fmaf(sc, acc.z, u0.z), 0.f);
        o.w = fmaxf(fmaf(sc, acc.w, u0.w), 0.f);
        *(float4*)(hbuf + (size_t)warp * 64 + cl * 4) = o;
        *(float4*)(jk + (size_t)warp * 256 + cl * 4) = o;
    }
}

// =================== launcher ===================
extern "C" void kernel_launch(void* const* d_in, const int* in_sizes, int n_in,
                              void* d_out, int out_size) {
    const float* features = (const float*)d_in[0];
    const int* edge_index = (const int*)d_in[1];
    const float* edgenet  = (const float*)d_in[2];
    const float* pae_w1 = (const float*)d_in[3];
    const float* pae_b1 = (const float*)d_in[4];
    const float* pae_bn_g = (const float*)d_in[5];
    const float* pae_bn_b = (const float*)d_in[6];
    const float* pae_bn_rm = (const float*)d_in[7];
    const float* pae_bn_rv = (const float*)d_in[8];
    const float* pae_w2 = (const float*)d_in[9];
    const float* pae_b2 = (const float*)d_in[10];
    const float* cheb_w[4] = {(const float*)d_in[11], (const float*)d_in[12],
                              (const float*)d_in[13], (const float*)d_in[14]};
    const float* cls_w1 = (const float*)d_in[15];
    const float* cls_b1 = (const float*)d_in[16];
    const float* cls_bn_g = (const float*)d_in[17];
    const float* cls_bn_b = (const float*)d_in[18];
    const float* cls_bn_rm = (const float*)d_in[19];
    const float* cls_bn_rv = (const float*)d_in[20];
    const float* cls_w2 = (const float*)d_in[21];
    const float* cls_b2 = (const float*)d_in[22];

    int N = in_sizes[0] / 128;
    int E = in_sizes[1] / 2;
    const int* row = edge_index;
    const int* col = edge_index + E;

    float* out = (float*)d_out;
    float* jk = out;
    float* logit = out + (size_t)N * 256;
    float* ew = logit + (size_t)N * 2;

    float *vbuf, *ubuf, *ha, *hb, *wp, *dis, *b2f, *cw2, *cb2;
    int *rowptr, *cursor, *cnt, *ecol, *eidx;
    __nv_bfloat16 *wt_hi, *wt_lo;
    uint4 *frag_cheb[4], *frag_cls;
    cudaGetSymbolAddress((void**)&vbuf, g_v);
    cudaGetSymbolAddress((void**)&ubuf, g_u);
    cudaGetSymbolAddress((void**)&ha, g_ha);
    cudaGetSymbolAddress((void**)&hb, g_hb);
    cudaGetSymbolAddress((void**)&wp, g_wp);
    cudaGetSymbolAddress((void**)&dis, g_dis);
    cudaGetSymbolAddress((void**)&rowptr, g_rowptr);
    cudaGetSymbolAddress((void**)&cursor, g_cursor);
    cudaGetSymbolAddress((void**)&cnt, g_cnt);
    cudaGetSymbolAddress((void**)&ecol, g_ecol);
    cudaGetSymbolAddress((void**)&eidx, g_eidx);
    cudaGetSymbolAddress((void**)&wt_hi, g_w2t_hi);
    cudaGetSymbolAddress((void**)&wt_lo, g_w2t_lo);
    cudaGetSymbolAddress((void**)&b2f, g_b2f);
    cudaGetSymbolAddress((void**)&cw2, g_cw2);
    cudaGetSymbolAddress((void**)&cb2, g_cb2);
    cudaGetSymbolAddress((void**)&frag_cheb[0], g_frag_cheb0);
    cudaGetSymbolAddress((void**)&frag_cheb[1], g_frag_cheb1);
    cudaGetSymbolAddress((void**)&frag_cheb[2], g_frag_cheb2);
    cudaGetSymbolAddress((void**)&frag_cheb[3], g_frag_cheb3);
    cudaGetSymbolAddress((void**)&frag_cls, g_frag_cls);

    cudaFuncSetAttribute(pae_mma_kernel, cudaFuncAttributeMaxDynamicSharedMemorySize, PAE_SMEM);
    cudaFuncSetAttribute(gemm_mma, cudaFuncAttributeMaxDynamicSharedMemorySize, 65536);
    cudaFuncSetAttribute(gemm_mma_cls, cudaFuncAttributeMaxDynamicSharedMemorySize, 65536);

    int rowTiles = (N + 127) / 128;
    int rowWarpBlocks = (N * 32 + 255) / 256;

    // ---- fork: side stream does CSR build + weight prep + layer-0 GEMM ----
    cudaEventRecord(g_evF, 0);
    cudaStreamWaitEvent(g_s2, g_evF, 0);

    cudaMemsetAsync(cnt, 0, (size_t)N * sizeof(int), g_s2);
    hist_kernel<<<(E + 255) / 256, 256, 0, g_s2>>>(row, cnt, E);
    scan_kernel<<<1, 1024, 0, g_s2>>>(cnt, N, rowptr, cursor);
    scatter_kernel<<<(E + 255) / 256, 256, 0, g_s2>>>(row, col, cursor, ecol, eidx, E);
    fold_cls_kernel<<<1, 256, 0, g_s2>>>(cls_bn_g, cls_bn_b, cls_bn_rm, cls_bn_rv,
                                         cls_w2, cls_b2, cw2, cb2);
    prep_cheb_frag128<<<24, 256, 0, g_s2>>>(cheb_w[0], frag_cheb[0]);
    prep_cheb_frag64x3<<<dim3(12, 3), 256, 0, g_s2>>>(cheb_w[1], cheb_w[2], cheb_w[3],
                                                      frag_cheb[1], frag_cheb[2], frag_cheb[3]);
    prep_frag<<<64, 256, 0, g_s2>>>(cls_w1, 256, 256, frag_cls);
    logit_init_kernel<<<(N + 255) / 256, 256, 0, g_s2>>>(cb2, logit, N);
    // layer-0 GEMM is graph-independent: u = features @ [W0-W2 | W1 | W2]
    gemm_mma<<<dim3(rowTiles, 3), 256, 8 * 4096, g_s2>>>(
        features, 128, N, frag_cheb[0], 8, 192, ubuf);

    // ---- main stream: PAE ----
    fold_pae_kernel<<<129, 128>>>(pae_bn_g, pae_bn_b, pae_bn_rm, pae_bn_rv, pae_w2, pae_b2,
                                  wt_hi, wt_lo, b2f);
    pae_mma_kernel<<<148, 256, PAE_SMEM>>>(edgenet, pae_w1, pae_b1, wt_hi, wt_lo, b2f, ew, E);

    // ---- join ----
    cudaEventRecord(g_evJ, g_s2);
    cudaStreamWaitEvent(0, g_evJ, 0);

    // ---- graph normalization via CSR ----
    dis_csr_kernel<<<rowWarpBlocks, 256>>>(ew, rowptr, eidx, dis, N);
    wp_kernel<<<(E + 255) / 256, 256>>>(ew, eidx, ecol, dis, wp, E);

    // ---- GCN layers (layer 0's GEMM already done on side stream) ----
    float* hbufs[2] = {ha, hb};
    for (int l = 0; l < 4; l++) {
        if (l > 0) {
            gemm_mma<<<dim3(rowTiles, 3), 256, 4 * 4096>>>(
                hbufs[(l - 1) & 1], 64, N, frag_cheb[l], 4, 192, ubuf);
        }
        spmm_v<<<rowWarpBlocks, 256>>>(ubuf, rowptr, ecol, wp, dis, vbuf, N);
        spmm_h<<<rowWarpBlocks, 256>>>(vbuf, ubuf, rowptr, ecol, wp, dis,
                                       hbufs[l & 1], jk + (size_t)l * 64, N);
    }

    // ---- classifier fused with logit ----
    gemm_mma_cls<<<dim3(rowTiles, 4), 256, 16 * 4096>>>(
        jk, 256, N, frag_cls, 16, cls_b1, cw2, logit);
}

// round 8
// speedup vs baseline: 2.9459x; 1.0423x over previous
#include <cuda_runtime.h>
#include <cuda_bf16.h>
#include <math.h>
#include <stdint.h>

typedef unsigned long long ull;
typedef unsigned int uint;

#define NMAX 50000
#define EMAX 1600000

// ---------------- device scratch (no allocations allowed) ----------------
__device__ float g_v[(size_t)NMAX * 64];        // v = u1 + 2*L(u2)
__device__ float g_u[(size_t)NMAX * 192];       // [u0 | u1 | u2]
__device__ float g_ha[(size_t)NMAX * 64];
__device__ float g_hb[(size_t)NMAX * 64];
__device__ float g_wp[EMAX];                    // ew[e]*dis[col[e]] in CSR order
__device__ float g_dis[NMAX];                   // rsqrt(deg) or 0
__device__ int   g_rowptr[NMAX + 1];
__device__ int   g_cursor[NMAX];
__device__ int   g_cnt[NMAX];
__device__ int   g_ecol[EMAX];                  // col in CSR order
__device__ int   g_eidx[EMAX];                  // original edge id in CSR order
__device__ __nv_bfloat16 g_w2t_hi[128 * 128];   // PAE W2fT hi, [n][k]
__device__ __nv_bfloat16 g_w2t_lo[128 * 128];   // PAE W2fT lo
__device__ float g_b2f[128];
__device__ float g_cw2[256 * 2];
__device__ float g_cb2[2];
// B fragments for mma GEMMs (uint4 = {hi_b0, hi_b1, lo_b0, lo_b1})
__device__ uint4 g_frag_cheb0[3 * 8 * 256];     // K=128, 192 cols
__device__ uint4 g_frag_cheb1[3 * 4 * 256];     // K=64
__device__ uint4 g_frag_cheb2[3 * 4 * 256];
__device__ uint4 g_frag_cheb3[3 * 4 * 256];
__device__ uint4 g_frag_cls[4 * 16 * 256];      // K=256, 256 cols

// ---------------- side stream + fork/join events (created pre-main, reused) ----------------
static cudaStream_t g_s2 = []() {
    cudaStream_t s; cudaStreamCreateWithFlags(&s, cudaStreamNonBlocking); return s;
}();
static cudaEvent_t g_evF = []() {
    cudaEvent_t e; cudaEventCreateWithFlags(&e, cudaEventDisableTiming); return e;
}();
static cudaEvent_t g_evJ = []() {
    cudaEvent_t e; cudaEventCreateWithFlags(&e, cudaEventDisableTiming); return e;
}();

// =================== warp-level bf16 MMA ===================
__device__ __forceinline__ void mma16816(float* d,
                                         uint a0, uint a1, uint a2, uint a3,
                                         uint b0, uint b1) {
    asm volatile(
        "mma.sync.aligned.m16n8k16.row.col.f32.bf16.bf16.f32 "
        "{%0,%1,%2,%3}, {%4,%5,%6,%7}, {%8,%9}, {%0,%1,%2,%3};"
        : "+f"(d[0]), "+f"(d[1]), "+f"(d[2]), "+f"(d[3])
        : "r"(a0), "r"(a1), "r"(a2), "r"(a3), "r"(b0), "r"(b1));
}

__device__ __forceinline__ void mma16816s(float& d0, float& d1, float& d2, float& d3,
                                          uint a0, uint a1, uint a2, uint a3,
                                          uint b0, uint b1) {
    asm volatile(
        "mma.sync.aligned.m16n8k16.row.col.f32.bf16.bf16.f32 "
        "{%0,%1,%2,%3}, {%4,%5,%6,%7}, {%8,%9}, {%0,%1,%2,%3};"
        : "+f"(d0), "+f"(d1), "+f"(d2), "+f"(d3)
        : "r"(a0), "r"(a1), "r"(a2), "r"(a3), "r"(b0), "r"(b1));
}

__device__ __forceinline__ void mma16808(float* d, uint a0, uint a1, uint b0) {
    asm volatile(
        "mma.sync.aligned.m16n8k8.row.col.f32.bf16.bf16.f32 "
        "{%0,%1,%2,%3}, {%4,%5}, {%6}, {%0,%1,%2,%3};"
        : "+f"(d[0]), "+f"(d[1]), "+f"(d[2]), "+f"(d[3])
        : "r"(a0), "r"(a1), "r"(b0));
}

__device__ __forceinline__ void split2(float a, float b, uint& hi, uint& lo) {
    __nv_bfloat162 h = __floats2bfloat162_rn(a, b);
    float2 f = __bfloat1622float2(h);
    __nv_bfloat162 l = __floats2bfloat162_rn(a - f.x, b - f.y);
    hi = *(uint*)&h;
    lo = *(uint*)&l;
}

// =================== BN folding kernels ===================
__global__ void fold_pae_kernel(const float* __restrict__ g, const float* __restrict__ b,
                                const float* __restrict__ rm, const float* __restrict__ rv,
                                const float* __restrict__ w2, const float* __restrict__ b2,
                                __nv_bfloat16* __restrict__ wt_hi, __nv_bfloat16* __restrict__ wt_lo,
                                float* __restrict__ b2f) {
    int j = threadIdx.x;  // 128 threads
    int blk = blockIdx.x;
    if (blk < 128) {
        float sj = g[j] * rsqrtf(rv[j] + 1e-5f);
        int jj = blk;
        float v = sj * __ldg(w2 + (size_t)j * 128 + jj);
        __nv_bfloat16 hi = __float2bfloat16(v);
        wt_hi[jj * 128 + j] = hi;
        wt_lo[jj * 128 + j] = __float2bfloat16(v - __bfloat162float(hi));
    } else {
        __shared__ float t[128];
        float si = g[j] * rsqrtf(rv[j] + 1e-5f);
        t[j] = b[j] - rm[j] * si;
        __syncthreads();
        float acc = b2[j];
#pragma unroll 8
        for (int i = 0; i < 128; i++) acc += t[i] * __ldg(w2 + i * 128 + j);
        b2f[j] = acc;
    }
}

__global__ void fold_cls_kernel(const float* __restrict__ g, const float* __restrict__ b,
                                const float* __restrict__ rm, const float* __restrict__ rv,
                                const float* __restrict__ w2, const float* __restrict__ b2,
                                float* __restrict__ cw2, float* __restrict__ cb2) {
    __shared__ float p0[256], p1[256];
    int i = threadIdx.x;  // 256 threads
    float si = g[i] * rsqrtf(rv[i] + 1e-5f);
    float ti = b[i] - rm[i] * si;
    float w0 = w2[2 * i], w1 = w2[2 * i + 1];
    cw2[2 * i]     = si * w0;
    cw2[2 * i + 1] = si * w1;
    p0[i] = ti * w0;
    p1[i] = ti * w1;
    __syncthreads();
    for (int off = 128; off; off >>= 1) {
        if (i < off) { p0[i] += p0[i + off]; p1[i] += p1[i + off]; }
        __syncthreads();
    }
    if (i == 0) { cb2[0] = b2[0] + p0[0]; cb2[1] = b2[1] + p1[0]; }
}

__global__ void logit_init_kernel(const float* __restrict__ cb2, float* __restrict__ logit, int N) {
    int i = blockIdx.x * blockDim.x + threadIdx.x;
    if (i < N) {
        logit[2 * i]     = cb2[0];
        logit[2 * i + 1] = cb2[1];
    }
}

// =================== fragment prep kernels ===================
__global__ void prep_frag(const float* __restrict__ W, int K, int Ncols, uint4* __restrict__ out) {
    int ktiles = K >> 4;
    int total = (Ncols >> 6) * ktiles * 256;
    int idx = blockIdx.x * 256 + threadIdx.x;
    if (idx >= total) return;
    int lane = idx & 31;
    int nt = (idx >> 5) & 7;
    int rest = idx >> 8;
    int kt = rest % ktiles;
    int chunk = rest / ktiles;
    int n = chunk * 64 + nt * 8 + (lane >> 2);
    int k0 = kt * 16 + (lane & 3) * 2;
    float w00 = W[(size_t)k0 * Ncols + n];
    float w01 = W[(size_t)(k0 + 1) * Ncols + n];
    float w10 = W[(size_t)(k0 + 8) * Ncols + n];
    float w11 = W[(size_t)(k0 + 9) * Ncols + n];
    uint4 v;
    split2(w00, w01, v.x, v.z);
    split2(w10, w11, v.y, v.w);
    out[idx] = v;
}

// Cheb composite Wc[k][n]: n<64: W0-W2 ; 64<=n<128: W1 ; n>=128: W2.  W: [3][K][64]
__device__ __forceinline__ void cheb_frag_body(const float* __restrict__ W, int K,
                                               uint4* __restrict__ out, int idx) {
    int ktiles = K >> 4;
    int lane = idx & 31;
    int nt = (idx >> 5) & 7;
    int rest = idx >> 8;
    int kt = rest % ktiles;
    int chunk = rest / ktiles;
    int n = chunk * 64 + nt * 8 + (lane >> 2);
    int k0 = kt * 16 + (lane & 3) * 2;
    int part = n >> 6, nn = n & 63;
    float w[4];
#pragma unroll
    for (int q = 0; q < 4; q++) {
        int k = k0 + (q >> 1) * 8 + (q & 1);
        float v;
        if (part == 0)      v = W[(size_t)k * 64 + nn] - W[(size_t)(2 * K + k) * 64 + nn];
        else if (part == 1) v = W[(size_t)(K + k) * 64 + nn];
        else                v = W[(size_t)(2 * K + k) * 64 + nn];
        w[q] = v;
    }
    uint4 v;
    split2(w[0], w[1], v.x, v.z);
    split2(w[2], w[3], v.y, v.w);
    out[idx] = v;
}

__global__ void prep_cheb_frag128(const float* __restrict__ W, uint4* __restrict__ out) {
    int idx = blockIdx.x * 256 + threadIdx.x;
    if (idx < 3 * 8 * 256) cheb_frag_body(W, 128, out, idx);
}

__global__ void prep_cheb_frag64x3(const float* __restrict__ W1, const float* __restrict__ W2,
                                   const float* __restrict__ W3,
                                   uint4* __restrict__ o1, uint4* __restrict__ o2,
                                   uint4* __restrict__ o3) {
    int idx = blockIdx.x * 256 + threadIdx.x;
    if (idx >= 3 * 4 * 256) return;
    const float* W = (blockIdx.y == 0) ? W1 : (blockIdx.y == 1) ? W2 : W3;
    uint4* out = (blockIdx.y == 0) ? o1 : (blockIdx.y == 1) ? o2 : o3;
    cheb_frag_body(W, 64, out, idx);
}

// =================== generic split-bf16 mma GEMM (C-writing variant) ===================
__global__ __launch_bounds__(256)
void gemm_mma(const float* __restrict__ A, int lda, int M,
              const uint4* __restrict__ bfrag, int ktiles,
              int ldc, float* __restrict__ C) {
    extern __shared__ uint4 sB[];   // [ktiles][8][32]
    int tid = threadIdx.x, lane = tid & 31, wid = tid >> 5;
    const uint4* src = bfrag + (size_t)blockIdx.y * ktiles * 256;
    for (int i = tid; i < ktiles * 256; i += 256) sB[i] = src[i];
    __syncthreads();

    int r1 = blockIdx.x * 128 + wid * 16 + (lane >> 2);
    int r2 = r1 + 8;
    int rl1 = min(r1, M - 1), rl2 = min(r2, M - 1);
    int cq = (lane & 3) * 2;
    const float* A1 = A + (size_t)rl1 * lda;
    const float* A2 = A + (size_t)rl2 * lda;

    float acc[8][4];
#pragma unroll
    for (int i = 0; i < 8; i++) { acc[i][0] = acc[i][1] = acc[i][2] = acc[i][3] = 0.f; }

    for (int kt = 0; kt < ktiles; kt++) {
        int k0 = kt * 16 + cq;
        float2 xa = *(const float2*)(A1 + k0);
        float2 xb = *(const float2*)(A2 + k0);
        float2 xc = *(const float2*)(A1 + k0 + 8);
        float2 xd = *(const float2*)(A2 + k0 + 8);
        uint ahi[4], alo[4];
        split2(xa.x, xa.y, ahi[0], alo[0]);
        split2(xb.x, xb.y, ahi[1], alo[1]);
        split2(xc.x, xc.y, ahi[2], alo[2]);
        split2(xd.x, xd.y, ahi[3], alo[3]);

        const uint4* bp = sB + kt * 256 + lane;
        uint4 b[8];
#pragma unroll
        for (int nt = 0; nt < 8; nt++) b[nt] = bp[nt * 32];
#pragma unroll
        for (int nt = 0; nt < 8; nt++)
            mma16816(acc[nt], ahi[0], ahi[1], ahi[2], ahi[3], b[nt].x, b[nt].y);
#pragma unroll
        for (int nt = 0; nt < 8; nt++)
            mma16816(acc[nt], alo[0], alo[1], alo[2], alo[3], b[nt].x, b[nt].y);
#pragma unroll
        for (int nt = 0; nt < 8; nt++)
            mma16816(acc[nt], ahi[0], ahi[1], ahi[2], ahi[3], b[nt].z, b[nt].w);
    }

#pragma unroll
    for (int nt = 0; nt < 8; nt++) {
        int cc = blockIdx.y * 64 + nt * 8 + cq;
        if (r1 < M) { float2 o = {acc[nt][0], acc[nt][1]}; *(float2*)(C + (size_t)r1 * ldc + cc) = o; }
        if (r2 < M) { float2 o = {acc[nt][2], acc[nt][3]}; *(float2*)(C + (size_t)r2 * ldc + cc) = o; }
    }
}

// =================== classifier GEMM fused with logit ===================
__global__ __launch_bounds__(256)
void gemm_mma_cls(const float* __restrict__ A, int lda, int M,
                  const uint4* __restrict__ bfrag, int ktiles,
                  const float* __restrict__ bias, const float* __restrict__ cw2,
                  float* __restrict__ logit) {
    extern __shared__ uint4 sB[];
    int tid = threadIdx.x, lane = tid & 31, wid = tid >> 5;
    const uint4* src = bfrag + (size_t)blockIdx.y * ktiles * 256;
    for (int i = tid; i < ktiles * 256; i += 256) sB[i] = src[i];
    __syncthreads();

    int r1 = blockIdx.x * 128 + wid * 16 + (lane >> 2);
    int r2 = r1 + 8;
    int rl1 = min(r1, M - 1), rl2 = min(r2, M - 1);
    int cq = (lane & 3) * 2;
    const float* A1 = A + (size_t)rl1 * lda;
    const float* A2 = A + (size_t)rl2 * lda;

    float acc[8][4];
#pragma unroll
    for (int i = 0; i < 8; i++) { acc[i][0] = acc[i][1] = acc[i][2] = acc[i][3] = 0.f; }

    for (int kt = 0; kt < ktiles; kt++) {
        int k0 = kt * 16 + cq;
        float2 xa = *(const float2*)(A1 + k0);
        float2 xb = *(const float2*)(A2 + k0);
        float2 xc = *(const float2*)(A1 + k0 + 8);
        float2 xd = *(const float2*)(A2 + k0 + 8);
        uint ahi[4], alo[4];
        split2(xa.x, xa.y, ahi[0], alo[0]);
        split2(xb.x, xb.y, ahi[1], alo[1]);
        split2(xc.x, xc.y, ahi[2], alo[2]);
        split2(xd.x, xd.y, ahi[3], alo[3]);

        const uint4* bp = sB + kt * 256 + lane;
        uint4 b[8];
#pragma unroll
        for (int nt = 0; nt < 8; nt++) b[nt] = bp[nt * 32];
#pragma unroll
        for (int nt = 0; nt < 8; nt++)
            mma16816(acc[nt], ahi[0], ahi[1], ahi[2], ahi[3], b[nt].x, b[nt].y);
#pragma unroll
        for (int nt = 0; nt < 8; nt++)
            mma16816(acc[nt], alo[0], alo[1], alo[2], alo[3], b[nt].x, b[nt].y);
#pragma unroll
        for (int nt = 0; nt < 8; nt++)
            mma16816(acc[nt], ahi[0], ahi[1], ahi[2], ahi[3], b[nt].z, b[nt].w);
    }

    float l0a = 0.f, l1a = 0.f, l0b = 0.f, l1b = 0.f;
#pragma unroll
    for (int nt = 0; nt < 8; nt++) {
        int cc = blockIdx.y * 64 + nt * 8 + cq;
        float b0 = bias[cc], b1 = bias[cc + 1];
        float v0 = fmaxf(acc[nt][0] + b0, 0.f);
        float v1 = fmaxf(acc[nt][1] + b1, 0.f);
        float v2 = fmaxf(acc[nt][2] + b0, 0.f);
        float v3 = fmaxf(acc[nt][3] + b1, 0.f);
        float c00 = cw2[2 * cc], c01 = cw2[2 * cc + 1];
        float c10 = cw2[2 * cc + 2], c11 = cw2[2 * cc + 3];
        l0a = fmaf(v0, c00, fmaf(v1, c10, l0a));
        l1a = fmaf(v0, c01, fmaf(v1, c11, l1a));
        l0b = fmaf(v2, c00, fmaf(v3, c10, l0b));
        l1b = fmaf(v2, c01, fmaf(v3, c11, l1b));
    }
#pragma unroll
    for (int off = 1; off <= 2; off <<= 1) {
        l0a += __shfl_xor_sync(0xffffffffu, l0a, off);
        l1a += __shfl_xor_sync(0xffffffffu, l1a, off);
        l0b += __shfl_xor_sync(0xffffffffu, l0b, off);
        l1b += __shfl_xor_sync(0xffffffffu, l1b, off);
    }
    if ((lane & 3) == 0) {
        if (r1 < M) {
            atomicAdd(&logit[2 * r1], l0a);
            atomicAdd(&logit[2 * r1 + 1], l1a);
        }
        if (r2 < M) {
            atomicAdd(&logit[2 * r2], l0b);
            atomicAdd(&logit[2 * r2 + 1], l1b);
        }
    }
}

// =================== PAE mma.sync kernel (M=32 per warp-iter: 2 tiles share B reads) ===================
// SMEM: [0,65536) W2fT fragments; [65536,69632) W1 k8 B-fragments (uint2 {hi,lo});
//       [69632,70144) b2f.
#define PAE_SMEM 70144

__global__ __launch_bounds__(256, 1)
void pae_mma_kernel(const float* __restrict__ edgenet,
                    const float* __restrict__ w1, const float* __restrict__ b1,
                    const __nv_bfloat16* __restrict__ wt_hi, const __nv_bfloat16* __restrict__ wt_lo,
                    const float* __restrict__ b2f,
                    float* __restrict__ ew, int E) {
    extern __shared__ char smraw[];
    uint4* s_bfrag = (uint4*)smraw;
    uint2* s_w1f = (uint2*)(smraw + 65536);   // [16 ntiles][32 lanes]
    float* s_b2f = (float*)(smraw + 69632);

    int tid = threadIdx.x, lane = tid & 31, wid = tid >> 5;

    if (tid < 128) s_b2f[tid] = b2f[tid];
    for (int idx = tid; idx < 512; idx += 256) {
        int nt = idx >> 5, ln = idx & 31;
        int n = nt * 8 + (ln >> 2);
        int k0 = (ln & 3) * 2;
        float v0, v1;
        if (k0 < 6) { v0 = __ldg(w1 + k0 * 128 + n); v1 = __ldg(w1 + (k0 + 1) * 128 + n); }
        else        { v0 = __ldg(b1 + n); v1 = 0.f; }
        uint hi, lo;
        split2(v0, v1, hi, lo);
        s_w1f[idx] = make_uint2(hi, lo);
    }
    for (int idx = tid; idx < 4096; idx += 256) {
        int ln = idx & 31;
        int k2 = (idx >> 5) & 3;
        int nt = (idx >> 7) & 15;
        int hl = idx >> 11;
        const __nv_bfloat16* src = hl ? wt_lo : wt_hi;
        int n = nt * 8 + (ln >> 2);
        int kg0 = (2 * k2) * 16 + (ln & 3) * 2;
        const __nv_bfloat16* base = src + n * 128;
        uint4 v;
        v.x = *(const uint*)(base + kg0);
        v.y = *(const uint*)(base + kg0 + 8);
        v.z = *(const uint*)(base + kg0 + 16);
        v.w = *(const uint*)(base + kg0 + 24);
        s_bfrag[idx] = v;
    }
    __syncthreads();

    int r1 = lane >> 2;
    int cq = (lane & 3) * 2;
    int nT = (E + 15) >> 4;   // 16 edges per warp-iter

    // builds one M=16 tile's A fragments (h = relu(z@W1+b1), split hi/lo)
    auto build_tile = [&](int ebase, uint Ahi[8][4], uint Alo[8][4]) {
        int eb = ebase + (r1 >> 1);
        int e_lo = min(eb, E - 1);
        int e_hi = min(eb + 4, E - 1);
        int hf = (r1 & 1) * 6;
        uint zhi0, zlo0, zhi1, zlo1;
        if (cq < 6) {
            float za0 = __ldg(edgenet + (size_t)e_lo * 12 + hf + cq);
            float za1 = __ldg(edgenet + (size_t)e_lo * 12 + hf + cq + 1);
            float zb0 = __ldg(edgenet + (size_t)e_hi * 12 + hf + cq);
            float zb1 = __ldg(edgenet + (size_t)e_hi * 12 + hf + cq + 1);
            split2(za0, za1, zhi0, zlo0);
            split2(zb0, zb1, zhi1, zlo1);
        } else {
            zhi0 = 0x00003f80u;  // (1.0, 0) bf16x2: bias row selector
            zhi1 = 0x00003f80u;
            zlo0 = 0u; zlo1 = 0u;
        }
#pragma unroll
        for (int j = 0; j < 8; j++) {
            uint2 we = s_w1f[(2 * j) * 32 + lane];
            uint2 wo = s_w1f[(2 * j + 1) * 32 + lane];
            float De[4] = {0.f, 0.f, 0.f, 0.f};
            float Do[4] = {0.f, 0.f, 0.f, 0.f};
            mma16808(De, zhi0, zhi1, we.x);
            mma16808(De, zlo0, zlo1, we.x);
            mma16808(De, zhi0, zhi1, we.y);
            mma16808(Do, zhi0, zhi1, wo.x);
            mma16808(Do, zlo0, zlo1, wo.x);
            mma16808(Do, zhi0, zhi1, wo.y);
            float v0 = fmaxf(De[0], 0.f), v1 = fmaxf(De[1], 0.f);
            float v2 = fmaxf(De[2], 0.f), v3 = fmaxf(De[3], 0.f);
            split2(v0, v1, Ahi[j][0], Alo[j][0]);
            split2(v2, v3, Ahi[j][1], Alo[j][1]);
            v0 = fmaxf(Do[0], 0.f); v1 = fmaxf(Do[1], 0.f);
            v2 = fmaxf(Do[2], 0.f); v3 = fmaxf(Do[3], 0.f);
            split2(v0, v1, Ahi[j][2], Alo[j][2]);
            split2(v2, v3, Ahi[j][3], Alo[j][3]);
        }
    };

    for (int t = blockIdx.x * 8 + wid; t < nT; t += gridDim.x * 8) {
        int e0 = t << 4;

        uint Ahi0[8][4], Alo0[8][4], Ahi1[8][4], Alo1[8][4];
        build_tile(e0, Ahi0, Alo0);        // edges e0   .. e0+7
        build_tile(e0 + 8, Ahi1, Alo1);    // edges e0+8 .. e0+15

        // num/ps: [0]=tile0 rows r1, [1]=tile0 rows r1+8, [2]=tile1 r1, [3]=tile1 r1+8
        float num[4] = {0.f, 0.f, 0.f, 0.f};
        float ps[4]  = {0.f, 0.f, 0.f, 0.f};

#pragma unroll 1
        for (int nt = 0; nt < 16; nt++) {
            const uint4* ph = s_bfrag + (nt * 4) * 32 + lane;
            const uint4* pl = ph + 16 * 4 * 32;
            uint4 bh0 = ph[0], bh1 = ph[32], bh2 = ph[64], bh3 = ph[96];
            uint4 bl0 = pl[0], bl1 = pl[32], bl2 = pl[64], bl3 = pl[96];
            uint bh[16] = {bh0.x, bh0.y, bh0.z, bh0.w, bh1.x, bh1.y, bh1.z, bh1.w,
                           bh2.x, bh2.y, bh2.z, bh2.w, bh3.x, bh3.y, bh3.z, bh3.w};
            uint bl[16] = {bl0.x, bl0.y, bl0.z, bl0.w, bl1.x, bl1.y, bl1.z, bl1.w,
                           bl2.x, bl2.y, bl2.z, bl2.w, bl3.x, bl3.y, bl3.z, bl3.w};
            float2 bb = *(const float2*)(s_b2f + nt * 8 + cq);

            // ---- tile 0 ----
            {
                float dA0 = 0.f, dA1 = 0.f, dA2 = 0.f, dA3 = 0.f;
                float dB0 = 0.f, dB1 = 0.f, dB2 = 0.f, dB3 = 0.f;
                float dC0 = 0.f, dC1 = 0.f, dC2 = 0.f, dC3 = 0.f;
#pragma unroll
                for (int k = 0; k < 8; k++) {
                    mma16816s(dA0, dA1, dA2, dA3, Ahi0[k][0], Ahi0[k][1], Ahi0[k][2], Ahi0[k][3],
                              bh[2 * k], bh[2 * k + 1]);
                    mma16816s(dB0, dB1, dB2, dB3, Ahi0[k][0], Ahi0[k][1], Ahi0[k][2], Ahi0[k][3],
                              bl[2 * k], bl[2 * k + 1]);
                    mma16816s(dC0, dC1, dC2, dC3, Alo0[k][0], Alo0[k][1], Alo0[k][2], Alo0[k][3],
                              bh[2 * k], bh[2 * k + 1]);
                }
                float o0 = dA0 + dB0 + dC0 + bb.x;
                float o1 = dA1 + dB1 + dC1 + bb.y;
                float o2 = dA2 + dB2 + dC2 + bb.x;
                float o3 = dA3 + dB3 + dC3 + bb.y;
                float p0 = __shfl_xor_sync(0xffffffffu, o0, 4);
                float p1 = __shfl_xor_sync(0xffffffffu, o1, 4);
                float p2 = __shfl_xor_sync(0xffffffffu, o2, 4);
                float p3 = __shfl_xor_sync(0xffffffffu, o3, 4);
                num[0] = fmaf(o0, p0, fmaf(o1, p1, num[0]));
                ps[0]  = fmaf(o0, o0, fmaf(o1, o1, ps[0]));
                num[1] = fmaf(o2, p2, fmaf(o3, p3, num[1]));
                ps[1]  = fmaf(o2, o2, fmaf(o3, o3, ps[1]));
            }
            // ---- tile 1 (same B regs) ----
            {
                float dA0 = 0.f, dA1 = 0.f, dA2 = 0.f, dA3 = 0.f;
                float dB0 = 0.f, dB1 = 0.f, dB2 = 0.f, dB3 = 0.f;
                float dC0 = 0.f, dC1 = 0.f, dC2 = 0.f, dC3 = 0.f;
#pragma unroll
                for (int k = 0; k < 8; k++) {
                    mma16816s(dA0, dA1, dA2, dA3, Ahi1[k][0], Ahi1[k][1], Ahi1[k][2], Ahi1[k][3],
                              bh[2 * k], bh[2 * k + 1]);
                    mma16816s(dB0, dB1, dB2, dB3, Ahi1[k][0], Ahi1[k][1], Ahi1[k][2], Ahi1[k][3],
                              bl[2 * k], bl[2 * k + 1]);
                    mma16816s(dC0, dC1, dC2, dC3, Alo1[k][0], Alo1[k][1], Alo1[k][2], Alo1[k][3],
                              bh[2 * k], bh[2 * k + 1]);
                }
                float o0 = dA0 + dB0 + dC0 + bb.x;
                float o1 = dA1 + dB1 + dC1 + bb.y;
                float o2 = dA2 + dB2 + dC2 + bb.x;
                float o3 = dA3 + dB3 + dC3 + bb.y;
                float p0 = __shfl_xor_sync(0xffffffffu, o0, 4);
                float p1 = __shfl_xor_sync(0xffffffffu, o1, 4);
                float p2 = __shfl_xor_sync(0xffffffffu, o2, 4);
                float p3 = __shfl_xor_sync(0xffffffffu, o3, 4);
                num[2] = fmaf(o0, p0, fmaf(o1, p1, num[2]));
                ps[2]  = fmaf(o0, o0, fmaf(o1, o1, ps[2]));
                num[3] = fmaf(o2, p2, fmaf(o3, p3, num[3]));
                ps[3]  = fmaf(o2, o2, fmaf(o3, o3, ps[3]));
            }
        }

#pragma unroll
        for (int off = 1; off <= 2; off <<= 1) {
#pragma unroll
            for (int q = 0; q < 4; q++) {
                num[q] += __shfl_xor_sync(0xffffffffu, num[q], off);
                ps[q]  += __shfl_xor_sync(0xffffffffu, ps[q], off);
            }
        }
        float psp[4];
#pragma unroll
        for (int q = 0; q < 4; q++) psp[q] = __shfl_xor_sync(0xffffffffu, ps[q], 4);

        if ((lane & 7) == 0) {
            int eL = lane >> 3;
            int ebase[4] = {e0 + eL, e0 + 4 + eL, e0 + 8 + eL, e0 + 12 + eL};
#pragma unroll
            for (int q = 0; q < 4; q++) {
                int e = ebase[q];
                if (e < E) {
                    float den = fmaxf(sqrtf(ps[q]) * sqrtf(psp[q]), 1e-8f);
                    ew[e] = fmaf(num[q] / den, 0.5f, 0.5f);
                }
            }
        }
    }
}

// =================== CSR build ===================
__global__ void hist_kernel(const int* __restrict__ row, int* __restrict__ cnt, int E) {
    int e = blockIdx.x * blockDim.x + threadIdx.x;
    if (e < E) atomicAdd(&cnt[row[e]], 1);
}

__global__ void scan_kernel(const int* __restrict__ cnt, int N,
                            int* __restrict__ rowptr, int* __restrict__ cursor) {
    __shared__ int part[1024];
    int t = threadIdx.x;
    int chunk = (N + 1023) / 1024;
    int b = t * chunk, e = min(b + chunk, N);
    int s = 0;
    for (int i = b; i < e; i++) s += cnt[i];
    part[t] = s;
    __syncthreads();
    for (int off = 1; off < 1024; off <<= 1) {
        int v = (t >= off) ? part[t - off] : 0;
        __syncthreads();
        part[t] += v;
        __syncthreads();
    }
    int run = t ? part[t - 1] : 0;
    for (int i = b; i < e; i++) {
        rowptr[i] = run;
        cursor[i] = run;
        run += cnt[i];
    }
    if (t == 1023) rowptr[N] = run;
}

__global__ void scatter_kernel(const int* __restrict__ row, const int* __restrict__ col,
                               int* __restrict__ cursor, int* __restrict__ ecol,
                               int* __restrict__ eidx, int E) {
    int e = blockIdx.x * blockDim.x + threadIdx.x;
    if (e >= E) return;
    int pos = atomicAdd(&cursor[row[e]], 1);
    ecol[pos] = col[e];
    eidx[pos] = e;
}

__global__ void dis_csr_kernel(const float* __restrict__ ew, const int* __restrict__ rowptr,
                               const int* __restrict__ eidx, float* __restrict__ dis, int N) {
    int warp = (blockIdx.x * blockDim.x + threadIdx.x) >> 5;
    int lane = threadIdx.x & 31;
    if (warp >= N) return;
    int beg = rowptr[warp], end = rowptr[warp + 1];
    float s = 0.f;
    for (int i = beg + lane; i < end; i += 32) s += __ldg(ew + __ldg(eidx + i));
#pragma unroll
    for (int off = 16; off; off >>= 1) s += __shfl_xor_sync(0xffffffffu, s, off);
    if (lane == 0) dis[warp] = (s > 0.f) ? rsqrtf(s) : 0.f;
}

__global__ void wp_kernel(const float* __restrict__ ew, const int* __restrict__ eidx,
                          const int* __restrict__ ecol, const float* __restrict__ dis,
                          float* __restrict__ wp, int E) {
    int i = blockIdx.x * blockDim.x + threadIdx.x;
    if (i < E) wp[i] = __ldg(ew + eidx[i]) * __ldg(dis + ecol[i]);
}

// =================== fused CSR SpMM pass 1: v = u1 + 2*(-dis)*L'(u2) ===================
__global__ __launch_bounds__(256)
void spmm_v(const float* __restrict__ u,
            const int* __restrict__ rowptr, const int* __restrict__ ecol,
            const float* __restrict__ wp, const float* __restrict__ dis,
            float* __restrict__ v, int N) {
    int warp = (blockIdx.x * blockDim.x + threadIdx.x) >> 5;
    int lane = threadIdx.x & 31;
    if (warp >= N) return;
    int beg = rowptr[warp], end = rowptr[warp + 1];
    int half = lane >> 4;
    int cl = lane & 15;
    float4 acc = {0.f, 0.f, 0.f, 0.f};
#pragma unroll 4
    for (int i = beg + half; i < end; i += 2) {
        int c = __ldg(ecol + i);
        float w = __ldg(wp + i);
        float4 xv = *(const float4*)(u + (size_t)c * 192 + 128 + cl * 4);
        acc.x = fmaf(w, xv.x, acc.x);
        acc.y = fmaf(w, xv.y, acc.y);
        acc.z = fmaf(w, xv.z, acc.z);
        acc.w = fmaf(w, xv.w, acc.w);
    }
    acc.x += __shfl_down_sync(0xffffffffu, acc.x, 16);
    acc.y += __shfl_down_sync(0xffffffffu, acc.y, 16);
    acc.z += __shfl_down_sync(0xffffffffu, acc.z, 16);
    acc.w += __shfl_down_sync(0xffffffffu, acc.w, 16);
    if (half == 0) {
        float sc = -2.f * __ldg(dis + warp);
        float4 u1 = *(const float4*)(u + (size_t)warp * 192 + 64 + cl * 4);
        float4 o;
        o.x = fmaf(sc, acc.x, u1.x);
        o.y = fmaf(sc, acc.y, u1.y);
        o.z = fmaf(sc, acc.z, u1.z);
        o.w = fmaf(sc, acc.w, u1.w);
        *(float4*)(v + (size_t)warp * 64 + cl * 4) = o;
    }
}

// =================== fused CSR SpMM pass 2: h = relu(u0 + (-dis)*L'(v)) -> hbuf, jk ===================
__global__ __launch_bounds__(256)
void spmm_h(const float* __restrict__ v, const float* __restrict__ u,
            const int* __restrict__ rowptr, const int* __restrict__ ecol,
            const float* __restrict__ wp, const float* __restrict__ dis,
            float* __restrict__ hbuf, float* __restrict__ jk, int N) {
    int warp = (blockIdx.x * blockDim.x + threadIdx.x) >> 5;
    int lane = threadIdx.x & 31;
    if (warp >= N) return;
    int beg = rowptr[warp], end = rowptr[warp + 1];
    int half = lane >> 4;
    int cl = lane & 15;
    float4 acc = {0.f, 0.f, 0.f, 0.f};
#pragma unroll 4
    for (int i = beg + half; i < end; i += 2) {
        int c = __ldg(ecol + i);
        float w = __ldg(wp + i);
        float4 xv = *(const float4*)(v + (size_t)c * 64 + cl * 4);
        acc.x = fmaf(w, xv.x, acc.x);
        acc.y = fmaf(w, xv.y, acc.y);
        acc.z = fmaf(w, xv.z, acc.z);
        acc.w = fmaf(w, xv.w, acc.w);
    }
    acc.x += __shfl_down_sync(0xffffffffu, acc.x, 16);
    acc.y += __shfl_down_sync(0xffffffffu, acc.y, 16);
    acc.z += __shfl_down_sync(0xffffffffu, acc.z, 16);
    acc.w += __shfl_down_sync(0xffffffffu, acc.w, 16);
    if (half == 0) {
        float sc = -__ldg(dis + warp);
        float4 u0 = *(const float4*)(u + (size_t)warp * 192 + cl * 4);
        float4 o;
        o.x = fmaxf(fmaf(sc, acc.x, u0.x), 0.f);
        o.y = fmaxf(fmaf(sc, acc.y, u0.y), 0.f);
        o.z = fmaxf(fmaf(sc, acc.z, u0.z), 0.f);
        o.w = fmaxf(fmaf(sc, acc.w, u0.w), 0.f);
        *(float4*)(hbuf + (size_t)warp * 64 + cl * 4) = o;
        *(float4*)(jk + (size_t)warp * 256 + cl * 4) = o;
    }
}

// =================== launcher ===================
extern "C" void kernel_launch(void* const* d_in, const int* in_sizes, int n_in,
                              void* d_out, int out_size) {
    const float* features = (const float*)d_in[0];
    const int* edge_index = (const int*)d_in[1];
    const float* edgenet  = (const float*)d_in[2];
    const float* pae_w1 = (const float*)d_in[3];
    const float* pae_b1 = (const float*)d_in[4];
    const float* pae_bn_g = (const float*)d_in[5];
    const float* pae_bn_b = (const float*)d_in[6];
    const float* pae_bn_rm = (const float*)d_in[7];
    const float* pae_bn_rv = (const float*)d_in[8];
    const float* pae_w2 = (const float*)d_in[9];
    const float* pae_b2 = (const float*)d_in[10];
    const float* cheb_w[4] = {(const float*)d_in[11], (const float*)d_in[12],
                              (const float*)d_in[13], (const float*)d_in[14]};
    const float* cls_w1 = (const float*)d_in[15];
    const float* cls_b1 = (const float*)d_in[16];
    const float* cls_bn_g = (const float*)d_in[17];
    const float* cls_bn_b = (const float*)d_in[18];
    const float* cls_bn_rm = (const float*)d_in[19];
    const float* cls_bn_rv = (const float*)d_in[20];
    const float* cls_w2 = (const float*)d_in[21];
    const float* cls_b2 = (const float*)d_in[22];

    int N = in_sizes[0] / 128;
    int E = in_sizes[1] / 2;
    const int* row = edge_index;
    const int* col = edge_index + E;

    float* out = (float*)d_out;
    float* jk = out;
    float* logit = out + (size_t)N * 256;
    float* ew = logit + (size_t)N * 2;

    float *vbuf, *ubuf, *ha, *hb, *wp, *dis, *b2f, *cw2, *cb2;
    int *rowptr, *cursor, *cnt, *ecol, *eidx;
    __nv_bfloat16 *wt_hi, *wt_lo;
    uint4 *frag_cheb[4], *frag_cls;
    cudaGetSymbolAddress((void**)&vbuf, g_v);
    cudaGetSymbolAddress((void**)&ubuf, g_u);
    cudaGetSymbolAddress((void**)&ha, g_ha);
    cudaGetSymbolAddress((void**)&hb, g_hb);
    cudaGetSymbolAddress((void**)&wp, g_wp);
    cudaGetSymbolAddress((void**)&dis, g_dis);
    cudaGetSymbolAddress((void**)&rowptr, g_rowptr);
    cudaGetSymbolAddress((void**)&cursor, g_cursor);
    cudaGetSymbolAddress((void**)&cnt, g_cnt);
    cudaGetSymbolAddress((void**)&ecol, g_ecol);
    cudaGetSymbolAddress((void**)&eidx, g_eidx);
    cudaGetSymbolAddress((void**)&wt_hi, g_w2t_hi);
    cudaGetSymbolAddress((void**)&wt_lo, g_w2t_lo);
    cudaGetSymbolAddress((void**)&b2f, g_b2f);
    cudaGetSymbolAddress((void**)&cw2, g_cw2);
    cudaGetSymbolAddress((void**)&cb2, g_cb2);
    cudaGetSymbolAddress((void**)&frag_cheb[0], g_frag_cheb0);
    cudaGetSymbolAddress((void**)&frag_cheb[1], g_frag_cheb1);
    cudaGetSymbolAddress((void**)&frag_cheb[2], g_frag_cheb2);
    cudaGetSymbolAddress((void**)&frag_cheb[3], g_frag_cheb3);
    cudaGetSymbolAddress((void**)&frag_cls, g_frag_cls);

    cudaFuncSetAttribute(pae_mma_kernel, cudaFuncAttributeMaxDynamicSharedMemorySize, PAE_SMEM);
    cudaFuncSetAttribute(gemm_mma, cudaFuncAttributeMaxDynamicSharedMemorySize, 65536);
    cudaFuncSetAttribute(gemm_mma_cls, cudaFuncAttributeMaxDynamicSharedMemorySize, 65536);

    int rowTiles = (N + 127) / 128;
    int rowWarpBlocks = (N * 32 + 255) / 256;

    // ---- fork: side stream does CSR build + weight prep + layer-0 GEMM ----
    cudaEventRecord(g_evF, 0);
    cudaStreamWaitEvent(g_s2, g_evF, 0);

    cudaMemsetAsync(cnt, 0, (size_t)N * sizeof(int), g_s2);
    hist_kernel<<<(E + 255) / 256, 256, 0, g_s2>>>(row, cnt, E);
    scan_kernel<<<1, 1024, 0, g_s2>>>(cnt, N, rowptr, cursor);
    scatter_kernel<<<(E + 255) / 256, 256, 0, g_s2>>>(row, col, cursor, ecol, eidx, E);
    fold_cls_kernel<<<1, 256, 0, g_s2>>>(cls_bn_g, cls_bn_b, cls_bn_rm, cls_bn_rv,
                                         cls_w2, cls_b2, cw2, cb2);
    prep_cheb_frag128<<<24, 256, 0, g_s2>>>(cheb_w[0], frag_cheb[0]);
    prep_cheb_frag64x3<<<dim3(12, 3), 256, 0, g_s2>>>(cheb_w[1], cheb_w[2], cheb_w[3],
                                                      frag_cheb[1], frag_cheb[2], frag_cheb[3]);
    prep_frag<<<64, 256, 0, g_s2>>>(cls_w1, 256, 256, frag_cls);
    logit_init_kernel<<<(N + 255) / 256, 256, 0, g_s2>>>(cb2, logit, N);
    // layer-0 GEMM is graph-independent: u = features @ [W0-W2 | W1 | W2]
    gemm_mma<<<dim3(rowTiles, 3), 256, 8 * 4096, g_s2>>>(
        features, 128, N, frag_cheb[0], 8, 192, ubuf);

    // ---- main stream: PAE ----
    fold_pae_kernel<<<129, 128>>>(pae_bn_g, pae_bn_b, pae_bn_rm, pae_bn_rv, pae_w2, pae_b2,
                                  wt_hi, wt_lo, b2f);
    pae_mma_kernel<<<148, 256, PAE_SMEM>>>(edgenet, pae_w1, pae_b1, wt_hi, wt_lo, b2f, ew, E);

    // ---- join ----
    cudaEventRecord(g_evJ, g_s2);
    cudaStreamWaitEvent(0, g_evJ, 0);

    // ---- graph normalization via CSR ----
    dis_csr_kernel<<<rowWarpBlocks, 256>>>(ew, rowptr, eidx, dis, N);
    wp_kernel<<<(E + 255) / 256, 256>>>(ew, eidx, ecol, dis, wp, E);

    // ---- GCN layers (layer 0's GEMM already done on side stream) ----
    float* hbufs[2] = {ha, hb};
    for (int l = 0; l < 4; l++) {
        if (l > 0) {
            gemm_mma<<<dim3(rowTiles, 3), 256, 4 * 4096>>>(
                hbufs[(l - 1) & 1], 64, N, frag_cheb[l], 4, 192, ubuf);
        }
        spmm_v<<<rowWarpBlocks, 256>>>(ubuf, rowptr, ecol, wp, dis, vbuf, N);
        spmm_h<<<rowWarpBlocks, 256>>>(vbuf, ubuf, rowptr, ecol, wp, dis,
                                       hbufs[l & 1], jk + (size_t)l * 64, N);
    }

    // ---- classifier fused with logit ----
    gemm_mma_cls<<<dim3(rowTiles, 4), 256, 16 * 4096>>>(
        jk, 256, N, frag_cls, 16, cls_b1, cw2, logit);
}

// round 9
// speedup vs baseline: 3.1379x; 1.0651x over previous
#include <cuda_runtime.h>
#include <cuda_bf16.h>
#include <math.h>
#include <stdint.h>

typedef unsigned long long ull;
typedef unsigned int uint;

#define NMAX 50000
#define EMAX 1600000

// ---------------- device scratch (no allocations allowed) ----------------
__device__ float g_v[(size_t)NMAX * 64];        // v = u1 + 2*L(u2)
__device__ float g_u[(size_t)NMAX * 192];       // [u0 | u1 | u2]
__device__ float g_ha[(size_t)NMAX * 64];
__device__ float g_hb[(size_t)NMAX * 64];
__device__ uint2 g_ewp[EMAX];                   // {col, ew*dis[col]} in CSR order
__device__ float g_dis[NMAX];                   // rsqrt(deg) or 0
__device__ int   g_rowptr[NMAX + 1];
__device__ int   g_cursor[NMAX];
__device__ int   g_cnt[NMAX];
__device__ int   g_ecol[EMAX];                  // col in CSR order
__device__ int   g_eidx[EMAX];                  // original edge id in CSR order
__device__ __nv_bfloat16 g_w2t_hi[128 * 128];   // PAE W2fT hi, [n][k]
__device__ __nv_bfloat16 g_w2t_lo[128 * 128];   // PAE W2fT lo
__device__ float g_b2f[128];
__device__ float g_cw2[256 * 2];
__device__ float g_cb2[2];
// B fragments for mma GEMMs (uint4 = {hi_b0, hi_b1, lo_b0, lo_b1})
__device__ uint4 g_frag_cheb0[3 * 8 * 256];     // K=128, 192 cols
__device__ uint4 g_frag_cheb1[3 * 4 * 256];     // K=64
__device__ uint4 g_frag_cheb2[3 * 4 * 256];
__device__ uint4 g_frag_cheb3[3 * 4 * 256];
__device__ uint4 g_frag_cls[4 * 16 * 256];      // K=256, 256 cols

// ---------------- side stream + fork/join events (created pre-main, reused) ----------------
static cudaStream_t g_s2 = []() {
    cudaStream_t s; cudaStreamCreateWithFlags(&s, cudaStreamNonBlocking); return s;
}();
static cudaEvent_t g_evF = []() {
    cudaEvent_t e; cudaEventCreateWithFlags(&e, cudaEventDisableTiming); return e;
}();
static cudaEvent_t g_evJ = []() {
    cudaEvent_t e; cudaEventCreateWithFlags(&e, cudaEventDisableTiming); return e;
}();

// =================== warp-level bf16 MMA ===================
__device__ __forceinline__ void mma16816(float* d,
                                         uint a0, uint a1, uint a2, uint a3,
                                         uint b0, uint b1) {
    asm volatile(
        "mma.sync.aligned.m16n8k16.row.col.f32.bf16.bf16.f32 "
        "{%0,%1,%2,%3}, {%4,%5,%6,%7}, {%8,%9}, {%0,%1,%2,%3};"
        : "+f"(d[0]), "+f"(d[1]), "+f"(d[2]), "+f"(d[3])
        : "r"(a0), "r"(a1), "r"(a2), "r"(a3), "r"(b0), "r"(b1));
}

__device__ __forceinline__ void mma16816s(float& d0, float& d1, float& d2, float& d3,
                                          uint a0, uint a1, uint a2, uint a3,
                                          uint b0, uint b1) {
    asm volatile(
        "mma.sync.aligned.m16n8k16.row.col.f32.bf16.bf16.f32 "
        "{%0,%1,%2,%3}, {%4,%5,%6,%7}, {%8,%9}, {%0,%1,%2,%3};"
        : "+f"(d0), "+f"(d1), "+f"(d2), "+f"(d3)
        : "r"(a0), "r"(a1), "r"(a2), "r"(a3), "r"(b0), "r"(b1));
}

__device__ __forceinline__ void mma16808(float* d, uint a0, uint a1, uint b0) {
    asm volatile(
        "mma.sync.aligned.m16n8k8.row.col.f32.bf16.bf16.f32 "
        "{%0,%1,%2,%3}, {%4,%5}, {%6}, {%0,%1,%2,%3};"
        : "+f"(d[0]), "+f"(d[1]), "+f"(d[2]), "+f"(d[3])
        : "r"(a0), "r"(a1), "r"(b0));
}

__device__ __forceinline__ void split2(float a, float b, uint& hi, uint& lo) {
    __nv_bfloat162 h = __floats2bfloat162_rn(a, b);
    float2 f = __bfloat1622float2(h);
    __nv_bfloat162 l = __floats2bfloat162_rn(a - f.x, b - f.y);
    hi = *(uint*)&h;
    lo = *(uint*)&l;
}

// =================== BN folding kernels ===================
__global__ void fold_pae_kernel(const float* __restrict__ g, const float* __restrict__ b,
                                const float* __restrict__ rm, const float* __restrict__ rv,
                                const float* __restrict__ w2, const float* __restrict__ b2,
                                __nv_bfloat16* __restrict__ wt_hi, __nv_bfloat16* __restrict__ wt_lo,
                                float* __restrict__ b2f) {
    int j = threadIdx.x;  // 128 threads
    int blk = blockIdx.x;
    if (blk < 128) {
        float sj = g[j] * rsqrtf(rv[j] + 1e-5f);
        int jj = blk;
        float v = sj * __ldg(w2 + (size_t)j * 128 + jj);
        __nv_bfloat16 hi = __float2bfloat16(v);
        wt_hi[jj * 128 + j] = hi;
        wt_lo[jj * 128 + j] = __float2bfloat16(v - __bfloat162float(hi));
    } else {
        __shared__ float t[128];
        float si = g[j] * rsqrtf(rv[j] + 1e-5f);
        t[j] = b[j] - rm[j] * si;
        __syncthreads();
        float acc = b2[j];
#pragma unroll 8
        for (int i = 0; i < 128; i++) acc += t[i] * __ldg(w2 + i * 128 + j);
        b2f[j] = acc;
    }
}

__global__ void fold_cls_kernel(const float* __restrict__ g, const float* __restrict__ b,
                                const float* __restrict__ rm, const float* __restrict__ rv,
                                const float* __restrict__ w2, const float* __restrict__ b2,
                                float* __restrict__ cw2, float* __restrict__ cb2) {
    __shared__ float p0[256], p1[256];
    int i = threadIdx.x;  // 256 threads
    float si = g[i] * rsqrtf(rv[i] + 1e-5f);
    float ti = b[i] - rm[i] * si;
    float w0 = w2[2 * i], w1 = w2[2 * i + 1];
    cw2[2 * i]     = si * w0;
    cw2[2 * i + 1] = si * w1;
    p0[i] = ti * w0;
    p1[i] = ti * w1;
    __syncthreads();
    for (int off = 128; off; off >>= 1) {
        if (i < off) { p0[i] += p0[i + off]; p1[i] += p1[i + off]; }
        __syncthreads();
    }
    if (i == 0) { cb2[0] = b2[0] + p0[0]; cb2[1] = b2[1] + p1[0]; }
}

__global__ void logit_init_kernel(const float* __restrict__ cb2, float* __restrict__ logit, int N) {
    int i = blockIdx.x * blockDim.x + threadIdx.x;
    if (i < N) {
        logit[2 * i]     = cb2[0];
        logit[2 * i + 1] = cb2[1];
    }
}

// =================== fragment prep kernels ===================
__global__ void prep_frag(const float* __restrict__ W, int K, int Ncols, uint4* __restrict__ out) {
    int ktiles = K >> 4;
    int total = (Ncols >> 6) * ktiles * 256;
    int idx = blockIdx.x * 256 + threadIdx.x;
    if (idx >= total) return;
    int lane = idx & 31;
    int nt = (idx >> 5) & 7;
    int rest = idx >> 8;
    int kt = rest % ktiles;
    int chunk = rest / ktiles;
    int n = chunk * 64 + nt * 8 + (lane >> 2);
    int k0 = kt * 16 + (lane & 3) * 2;
    float w00 = W[(size_t)k0 * Ncols + n];
    float w01 = W[(size_t)(k0 + 1) * Ncols + n];
    float w10 = W[(size_t)(k0 + 8) * Ncols + n];
    float w11 = W[(size_t)(k0 + 9) * Ncols + n];
    uint4 v;
    split2(w00, w01, v.x, v.z);
    split2(w10, w11, v.y, v.w);
    out[idx] = v;
}

// Cheb composite Wc[k][n]: n<64: W0-W2 ; 64<=n<128: W1 ; n>=128: W2.  W: [3][K][64]
__device__ __forceinline__ void cheb_frag_body(const float* __restrict__ W, int K,
                                               uint4* __restrict__ out, int idx) {
    int ktiles = K >> 4;
    int lane = idx & 31;
    int nt = (idx >> 5) & 7;
    int rest = idx >> 8;
    int kt = rest % ktiles;
    int chunk = rest / ktiles;
    int n = chunk * 64 + nt * 8 + (lane >> 2);
    int k0 = kt * 16 + (lane & 3) * 2;
    int part = n >> 6, nn = n & 63;
    float w[4];
#pragma unroll
    for (int q = 0; q < 4; q++) {
        int k = k0 + (q >> 1) * 8 + (q & 1);
        float v;
        if (part == 0)      v = W[(size_t)k * 64 + nn] - W[(size_t)(2 * K + k) * 64 + nn];
        else if (part == 1) v = W[(size_t)(K + k) * 64 + nn];
        else                v = W[(size_t)(2 * K + k) * 64 + nn];
        w[q] = v;
    }
    uint4 v;
    split2(w[0], w[1], v.x, v.z);
    split2(w[2], w[3], v.y, v.w);
    out[idx] = v;
}

__global__ void prep_cheb_frag128(const float* __restrict__ W, uint4* __restrict__ out) {
    int idx = blockIdx.x * 256 + threadIdx.x;
    if (idx < 3 * 8 * 256) cheb_frag_body(W, 128, out, idx);
}

__global__ void prep_cheb_frag64x3(const float* __restrict__ W1, const float* __restrict__ W2,
                                   const float* __restrict__ W3,
                                   uint4* __restrict__ o1, uint4* __restrict__ o2,
                                   uint4* __restrict__ o3) {
    int idx = blockIdx.x * 256 + threadIdx.x;
    if (idx >= 3 * 4 * 256) return;
    const float* W = (blockIdx.y == 0) ? W1 : (blockIdx.y == 1) ? W2 : W3;
    uint4* out = (blockIdx.y == 0) ? o1 : (blockIdx.y == 1) ? o2 : o3;
    cheb_frag_body(W, 64, out, idx);
}

// =================== generic split-bf16 mma GEMM (C-writing variant) ===================
__global__ __launch_bounds__(256)
void gemm_mma(const float* __restrict__ A, int lda, int M,
              const uint4* __restrict__ bfrag, int ktiles,
              int ldc, float* __restrict__ C) {
    extern __shared__ uint4 sB[];   // [ktiles][8][32]
    int tid = threadIdx.x, lane = tid & 31, wid = tid >> 5;
    const uint4* src = bfrag + (size_t)blockIdx.y * ktiles * 256;
    for (int i = tid; i < ktiles * 256; i += 256) sB[i] = src[i];
    __syncthreads();

    int r1 = blockIdx.x * 128 + wid * 16 + (lane >> 2);
    int r2 = r1 + 8;
    int rl1 = min(r1, M - 1), rl2 = min(r2, M - 1);
    int cq = (lane & 3) * 2;
    const float* A1 = A + (size_t)rl1 * lda;
    const float* A2 = A + (size_t)rl2 * lda;

    float acc[8][4];
#pragma unroll
    for (int i = 0; i < 8; i++) { acc[i][0] = acc[i][1] = acc[i][2] = acc[i][3] = 0.f; }

    for (int kt = 0; kt < ktiles; kt++) {
        int k0 = kt * 16 + cq;
        float2 xa = *(const float2*)(A1 + k0);
        float2 xb = *(const float2*)(A2 + k0);
        float2 xc = *(const float2*)(A1 + k0 + 8);
        float2 xd = *(const float2*)(A2 + k0 + 8);
        uint ahi[4], alo[4];
        split2(xa.x, xa.y, ahi[0], alo[0]);
        split2(xb.x, xb.y, ahi[1], alo[1]);
        split2(xc.x, xc.y, ahi[2], alo[2]);
        split2(xd.x, xd.y, ahi[3], alo[3]);

        const uint4* bp = sB + kt * 256 + lane;
        uint4 b[8];
#pragma unroll
        for (int nt = 0; nt < 8; nt++) b[nt] = bp[nt * 32];
#pragma unroll
        for (int nt = 0; nt < 8; nt++)
            mma16816(acc[nt], ahi[0], ahi[1], ahi[2], ahi[3], b[nt].x, b[nt].y);
#pragma unroll
        for (int nt = 0; nt < 8; nt++)
            mma16816(acc[nt], alo[0], alo[1], alo[2], alo[3], b[nt].x, b[nt].y);
#pragma unroll
        for (int nt = 0; nt < 8; nt++)
            mma16816(acc[nt], ahi[0], ahi[1], ahi[2], ahi[3], b[nt].z, b[nt].w);
    }

#pragma unroll
    for (int nt = 0; nt < 8; nt++) {
        int cc = blockIdx.y * 64 + nt * 8 + cq;
        if (r1 < M) { float2 o = {acc[nt][0], acc[nt][1]}; *(float2*)(C + (size_t)r1 * ldc + cc) = o; }
        if (r2 < M) { float2 o = {acc[nt][2], acc[nt][3]}; *(float2*)(C + (size_t)r2 * ldc + cc) = o; }
    }
}

// =================== classifier GEMM fused with logit ===================
__global__ __launch_bounds__(256)
void gemm_mma_cls(const float* __restrict__ A, int lda, int M,
                  const uint4* __restrict__ bfrag, int ktiles,
                  const float* __restrict__ bias, const float* __restrict__ cw2,
                  float* __restrict__ logit) {
    extern __shared__ uint4 sB[];
    int tid = threadIdx.x, lane = tid & 31, wid = tid >> 5;
    const uint4* src = bfrag + (size_t)blockIdx.y * ktiles * 256;
    for (int i = tid; i < ktiles * 256; i += 256) sB[i] = src[i];
    __syncthreads();

    int r1 = blockIdx.x * 128 + wid * 16 + (lane >> 2);
    int r2 = r1 + 8;
    int rl1 = min(r1, M - 1), rl2 = min(r2, M - 1);
    int cq = (lane & 3) * 2;
    const float* A1 = A + (size_t)rl1 * lda;
    const float* A2 = A + (size_t)rl2 * lda;

    float acc[8][4];
#pragma unroll
    for (int i = 0; i < 8; i++) { acc[i][0] = acc[i][1] = acc[i][2] = acc[i][3] = 0.f; }

    for (int kt = 0; kt < ktiles; kt++) {
        int k0 = kt * 16 + cq;
        float2 xa = *(const float2*)(A1 + k0);
        float2 xb = *(const float2*)(A2 + k0);
        float2 xc = *(const float2*)(A1 + k0 + 8);
        float2 xd = *(const float2*)(A2 + k0 + 8);
        uint ahi[4], alo[4];
        split2(xa.x, xa.y, ahi[0], alo[0]);
        split2(xb.x, xb.y, ahi[1], alo[1]);
        split2(xc.x, xc.y, ahi[2], alo[2]);
        split2(xd.x, xd.y, ahi[3], alo[3]);

        const uint4* bp = sB + kt * 256 + lane;
        uint4 b[8];
#pragma unroll
        for (int nt = 0; nt < 8; nt++) b[nt] = bp[nt * 32];
#pragma unroll
        for (int nt = 0; nt < 8; nt++)
            mma16816(acc[nt], ahi[0], ahi[1], ahi[2], ahi[3], b[nt].x, b[nt].y);
#pragma unroll
        for (int nt = 0; nt < 8; nt++)
            mma16816(acc[nt], alo[0], alo[1], alo[2], alo[3], b[nt].x, b[nt].y);
#pragma unroll
        for (int nt = 0; nt < 8; nt++)
            mma16816(acc[nt], ahi[0], ahi[1], ahi[2], ahi[3], b[nt].z, b[nt].w);
    }

    float l0a = 0.f, l1a = 0.f, l0b = 0.f, l1b = 0.f;
#pragma unroll
    for (int nt = 0; nt < 8; nt++) {
        int cc = blockIdx.y * 64 + nt * 8 + cq;
        float b0 = bias[cc], b1 = bias[cc + 1];
        float v0 = fmaxf(acc[nt][0] + b0, 0.f);
        float v1 = fmaxf(acc[nt][1] + b1, 0.f);
        float v2 = fmaxf(acc[nt][2] + b0, 0.f);
        float v3 = fmaxf(acc[nt][3] + b1, 0.f);
        float c00 = cw2[2 * cc], c01 = cw2[2 * cc + 1];
        float c10 = cw2[2 * cc + 2], c11 = cw2[2 * cc + 3];
        l0a = fmaf(v0, c00, fmaf(v1, c10, l0a));
        l1a = fmaf(v0, c01, fmaf(v1, c11, l1a));
        l0b = fmaf(v2, c00, fmaf(v3, c10, l0b));
        l1b = fmaf(v2, c01, fmaf(v3, c11, l1b));
    }
#pragma unroll
    for (int off = 1; off <= 2; off <<= 1) {
        l0a += __shfl_xor_sync(0xffffffffu, l0a, off);
        l1a += __shfl_xor_sync(0xffffffffu, l1a, off);
        l0b += __shfl_xor_sync(0xffffffffu, l0b, off);
        l1b += __shfl_xor_sync(0xffffffffu, l1b, off);
    }
    if ((lane & 3) == 0) {
        if (r1 < M) {
            atomicAdd(&logit[2 * r1], l0a);
            atomicAdd(&logit[2 * r1 + 1], l1a);
        }
        if (r2 < M) {
            atomicAdd(&logit[2 * r2], l0b);
            atomicAdd(&logit[2 * r2 + 1], l1b);
        }
    }
}

// =================== PAE mma.sync kernel ===================
// Edge e's two halves occupy rows r and r+8 of the M=16 tile -> both halves of an edge
// live in the SAME thread's D slots (o0,o1 | o2,o3): cosine needs no per-nt shuffles.
// h-stage corrections (zlo*Whi + zhi*Wlo) merged into ONE k16 MMA (virtual-k packing).
// M=32 per warp-iter (2 tiles share B-fragment loads).
// SMEM: [0,65536) W2fT fragments; [65536,69632) W1 k8 B-fragments (uint2 {hi,lo});
//       [69632,70144) b2f.
#define PAE_SMEM 70144

__global__ __launch_bounds__(256, 1)
void pae_mma_kernel(const float* __restrict__ edgenet,
                    const float* __restrict__ w1, const float* __restrict__ b1,
                    const __nv_bfloat16* __restrict__ wt_hi, const __nv_bfloat16* __restrict__ wt_lo,
                    const float* __restrict__ b2f,
                    float* __restrict__ ew, int E) {
    extern __shared__ char smraw[];
    uint4* s_bfrag = (uint4*)smraw;
    uint2* s_w1f = (uint2*)(smraw + 65536);   // [16 ntiles][32 lanes]
    float* s_b2f = (float*)(smraw + 69632);

    int tid = threadIdx.x, lane = tid & 31, wid = tid >> 5;

    if (tid < 128) s_b2f[tid] = b2f[tid];
    for (int idx = tid; idx < 512; idx += 256) {
        int nt = idx >> 5, ln = idx & 31;
        int n = nt * 8 + (ln >> 2);
        int k0 = (ln & 3) * 2;
        float v0, v1;
        if (k0 < 6) { v0 = __ldg(w1 + k0 * 128 + n); v1 = __ldg(w1 + (k0 + 1) * 128 + n); }
        else        { v0 = __ldg(b1 + n); v1 = 0.f; }
        uint hi, lo;
        split2(v0, v1, hi, lo);
        s_w1f[idx] = make_uint2(hi, lo);
    }
    for (int idx = tid; idx < 4096; idx += 256) {
        int ln = idx & 31;
        int k2 = (idx >> 5) & 3;
        int nt = (idx >> 7) & 15;
        int hl = idx >> 11;
        const __nv_bfloat16* src = hl ? wt_lo : wt_hi;
        int n = nt * 8 + (ln >> 2);
        int kg0 = (2 * k2) * 16 + (ln & 3) * 2;
        const __nv_bfloat16* base = src + n * 128;
        uint4 v;
        v.x = *(const uint*)(base + kg0);
        v.y = *(const uint*)(base + kg0 + 8);
        v.z = *(const uint*)(base + kg0 + 16);
        v.w = *(const uint*)(base + kg0 + 24);
        s_bfrag[idx] = v;
    }
    __syncthreads();

    int r1 = lane >> 2;
    int cq = (lane & 3) * 2;
    int nT = (E + 15) >> 4;   // 16 edges per warp-iter

    // builds one M=16 tile's A fragments. Rows r1 = half0 of edge ebase+r1,
    // rows r1+8 = half1 of the SAME edge.
    auto build_tile = [&](int ebase, uint Ahi[8][4], uint Alo[8][4]) {
        int e = min(ebase + r1, E - 1);
        uint zhi0, zlo0, zhi1, zlo1;
        if (cq < 6) {
            const float* zp = edgenet + (size_t)e * 12 + cq;
            float za0 = __ldg(zp);          // half0
            float za1 = __ldg(zp + 1);
            float zb0 = __ldg(zp + 6);      // half1
            float zb1 = __ldg(zp + 7);
            split2(za0, za1, zhi0, zlo0);
            split2(zb0, zb1, zhi1, zlo1);
        } else {
            zhi0 = 0x00003f80u;  // (1.0, 0) bf16x2: bias row selector
            zhi1 = 0x00003f80u;
            zlo0 = 0u; zlo1 = 0u;
        }
#pragma unroll
        for (int j = 0; j < 8; j++) {
            uint2 we = s_w1f[(2 * j) * 32 + lane];
            uint2 wo = s_w1f[(2 * j + 1) * 32 + lane];
            float De[4] = {0.f, 0.f, 0.f, 0.f};
            float Do[4] = {0.f, 0.f, 0.f, 0.f};
            mma16808(De, zhi0, zhi1, we.x);
            mma16816(De, zlo0, zlo1, zhi0, zhi1, we.x, we.y);   // zlo*Whi + zhi*Wlo
            mma16808(Do, zhi0, zhi1, wo.x);
            mma16816(Do, zlo0, zlo1, zhi0, zhi1, wo.x, wo.y);
            float v0 = fmaxf(De[0], 0.f), v1 = fmaxf(De[1], 0.f);
            float v2 = fmaxf(De[2], 0.f), v3 = fmaxf(De[3], 0.f);
            split2(v0, v1, Ahi[j][0], Alo[j][0]);
            split2(v2, v3, Ahi[j][1], Alo[j][1]);
            v0 = fmaxf(Do[0], 0.f); v1 = fmaxf(Do[1], 0.f);
            v2 = fmaxf(Do[2], 0.f); v3 = fmaxf(Do[3], 0.f);
            split2(v0, v1, Ahi[j][2], Alo[j][2]);
            split2(v2, v3, Ahi[j][3], Alo[j][3]);
        }
    };

    for (int t = blockIdx.x * 8 + wid; t < nT; t += gridDim.x * 8) {
        int e0 = t << 4;

        uint Ahi0[8][4], Alo0[8][4], Ahi1[8][4], Alo1[8][4];
        build_tile(e0, Ahi0, Alo0);        // edges e0   .. e0+7
        build_tile(e0 + 8, Ahi1, Alo1);    // edges e0+8 .. e0+15

        // per tile: num = o_half0 . o_half1, p1 = |o_half0|^2, p2 = |o_half1|^2
        float num0 = 0.f, p10 = 0.f, p20 = 0.f;
        float num1 = 0.f, p11 = 0.f, p21 = 0.f;

#pragma unroll 1
        for (int nt = 0; nt < 16; nt++) {
            const uint4* ph = s_bfrag + (nt * 4) * 32 + lane;
            const uint4* pl = ph + 16 * 4 * 32;
            uint4 bh0 = ph[0], bh1 = ph[32], bh2 = ph[64], bh3 = ph[96];
            uint4 bl0 = pl[0], bl1 = pl[32], bl2 = pl[64], bl3 = pl[96];
            uint bh[16] = {bh0.x, bh0.y, bh0.z, bh0.w, bh1.x, bh1.y, bh1.z, bh1.w,
                           bh2.x, bh2.y, bh2.z, bh2.w, bh3.x, bh3.y, bh3.z, bh3.w};
            uint bl[16] = {bl0.x, bl0.y, bl0.z, bl0.w, bl1.x, bl1.y, bl1.z, bl1.w,
                           bl2.x, bl2.y, bl2.z, bl2.w, bl3.x, bl3.y, bl3.z, bl3.w};
            float2 bb = *(const float2*)(s_b2f + nt * 8 + cq);

            // ---- tile 0 ----
            {
                float dA0 = 0.f, dA1 = 0.f, dA2 = 0.f, dA3 = 0.f;
                float dB0 = 0.f, dB1 = 0.f, dB2 = 0.f, dB3 = 0.f;
                float dC0 = 0.f, dC1 = 0.f, dC2 = 0.f, dC3 = 0.f;
#pragma unroll
                for (int k = 0; k < 8; k++) {
                    mma16816s(dA0, dA1, dA2, dA3, Ahi0[k][0], Ahi0[k][1], Ahi0[k][2], Ahi0[k][3],
                              bh[2 * k], bh[2 * k + 1]);
                    mma16816s(dB0, dB1, dB2, dB3, Ahi0[k][0], Ahi0[k][1], Ahi0[k][2], Ahi0[k][3],
                              bl[2 * k], bl[2 * k + 1]);
                    mma16816s(dC0, dC1, dC2, dC3, Alo0[k][0], Alo0[k][1], Alo0[k][2], Alo0[k][3],
                              bh[2 * k], bh[2 * k + 1]);
                }
                float o0 = dA0 + dB0 + dC0 + bb.x;   // half0, col cq
                float o1 = dA1 + dB1 + dC1 + bb.y;   // half0, col cq+1
                float o2 = dA2 + dB2 + dC2 + bb.x;   // half1, col cq
                float o3 = dA3 + dB3 + dC3 + bb.y;   // half1, col cq+1
                num0 = fmaf(o0, o2, fmaf(o1, o3, num0));
                p10  = fmaf(o0, o0, fmaf(o1, o1, p10));
                p20  = fmaf(o2, o2, fmaf(o3, o3, p20));
            }
            // ---- tile 1 (same B regs) ----
            {
                float dA0 = 0.f, dA1 = 0.f, dA2 = 0.f, dA3 = 0.f;
                float dB0 = 0.f, dB1 = 0.f, dB2 = 0.f, dB3 = 0.f;
                float dC0 = 0.f, dC1 = 0.f, dC2 = 0.f, dC3 = 0.f;
#pragma unroll
                for (int k = 0; k < 8; k++) {
                    mma16816s(dA0, dA1, dA2, dA3, Ahi1[k][0], Ahi1[k][1], Ahi1[k][2], Ahi1[k][3],
                              bh[2 * k], bh[2 * k + 1]);
                    mma16816s(dB0, dB1, dB2, dB3, Ahi1[k][0], Ahi1[k][1], Ahi1[k][2], Ahi1[k][3],
                              bl[2 * k], bl[2 * k + 1]);
                    mma16816s(dC0, dC1, dC2, dC3, Alo1[k][0], Alo1[k][1], Alo1[k][2], Alo1[k][3],
                              bh[2 * k], bh[2 * k + 1]);
                }
                float o0 = dA0 + dB0 + dC0 + bb.x;
                float o1 = dA1 + dB1 + dC1 + bb.y;
                float o2 = dA2 + dB2 + dC2 + bb.x;
                float o3 = dA3 + dB3 + dC3 + bb.y;
                num1 = fmaf(o0, o2, fmaf(o1, o3, num1));
                p11  = fmaf(o0, o0, fmaf(o1, o1, p11));
                p21  = fmaf(o2, o2, fmaf(o3, o3, p21));
            }
        }

        // reduce over the 4 lanes sharing a row (cols partition)
#pragma unroll
        for (int off = 1; off <= 2; off <<= 1) {
            num0 += __shfl_xor_sync(0xffffffffu, num0, off);
            p10  += __shfl_xor_sync(0xffffffffu, p10, off);
            p20  += __shfl_xor_sync(0xffffffffu, p20, off);
            num1 += __shfl_xor_sync(0xffffffffu, num1, off);
            p11  += __shfl_xor_sync(0xffffffffu, p11, off);
            p21  += __shfl_xor_sync(0xffffffffu, p21, off);
        }

        if ((lane & 3) == 0) {
            int eA = e0 + r1;
            int eB = e0 + 8 + r1;
            if (eA < E) {
                float den = fmaxf(sqrtf(p10) * sqrtf(p20), 1e-8f);
                ew[eA] = fmaf(num0 / den, 0.5f, 0.5f);
            }
            if (eB < E) {
                float den = fmaxf(sqrtf(p11) * sqrtf(p21), 1e-8f);
                ew[eB] = fmaf(num1 / den, 0.5f, 0.5f);
            }
        }
    }
}

// =================== CSR build ===================
__global__ void hist_kernel(const int* __restrict__ row, int* __restrict__ cnt, int E) {
    int e = blockIdx.x * blockDim.x + threadIdx.x;
    if (e < E) atomicAdd(&cnt[row[e]], 1);
}

__global__ void scan_kernel(const int* __restrict__ cnt, int N,
                            int* __restrict__ rowptr, int* __restrict__ cursor) {
    __shared__ int part[1024];
    int t = threadIdx.x;
    int chunk = (N + 1023) / 1024;
    int b = t * chunk, e = min(b + chunk, N);
    int s = 0;
    for (int i = b; i < e; i++) s += cnt[i];
    part[t] = s;
    __syncthreads();
    for (int off = 1; off < 1024; off <<= 1) {
        int v = (t >= off) ? part[t - off] : 0;
        __syncthreads();
        part[t] += v;
        __syncthreads();
    }
    int run = t ? part[t - 1] : 0;
    for (int i = b; i < e; i++) {
        rowptr[i] = run;
        cursor[i] = run;
        run += cnt[i];
    }
    if (t == 1023) rowptr[N] = run;
}

__global__ void scatter_kernel(const int* __restrict__ row, const int* __restrict__ col,
                               int* __restrict__ cursor, int* __restrict__ ecol,
                               int* __restrict__ eidx, int E) {
    int e = blockIdx.x * blockDim.x + threadIdx.x;
    if (e >= E) return;
    int pos = atomicAdd(&cursor[row[e]], 1);
    ecol[pos] = col[e];
    eidx[pos] = e;
}

__global__ void dis_csr_kernel(const float* __restrict__ ew, const int* __restrict__ rowptr,
                               const int* __restrict__ eidx, float* __restrict__ dis, int N) {
    int warp = (blockIdx.x * blockDim.x + threadIdx.x) >> 5;
    int lane = threadIdx.x & 31;
    if (warp >= N) return;
    int beg = rowptr[warp], end = rowptr[warp + 1];
    float s = 0.f;
    for (int i = beg + lane; i < end; i += 32) s += __ldg(ew + __ldg(eidx + i));
#pragma unroll
    for (int off = 16; off; off >>= 1) s += __shfl_xor_sync(0xffffffffu, s, off);
    if (lane == 0) dis[warp] = (s > 0.f) ? rsqrtf(s) : 0.f;
}

// ewp[i] = {col, ew[eidx[i]] * dis[col]}
__global__ void ewp_kernel(const float* __restrict__ ew, const int* __restrict__ eidx,
                           const int* __restrict__ ecol, const float* __restrict__ dis,
                           uint2* __restrict__ ewp, int E) {
    int i = blockIdx.x * blockDim.x + threadIdx.x;
    if (i >= E) return;
    int c = __ldg(ecol + i);
    float w = __ldg(ew + __ldg(eidx + i)) * __ldg(dis + c);
    ewp[i] = make_uint2((uint)c, __float_as_uint(w));
}

// =================== fused CSR SpMM pass 1: v = u1 + 2*(-dis)*L'(u2) ===================
// 4 edges in flight per warp; 8 lanes cover a 64-float row as 2x float4.
__global__ __launch_bounds__(256)
void spmm_v(const float* __restrict__ u,
            const int* __restrict__ rowptr, const uint2* __restrict__ ewp,
            const float* __restrict__ dis,
            float* __restrict__ v, int N) {
    int warp = (blockIdx.x * blockDim.x + threadIdx.x) >> 5;
    int lane = threadIdx.x & 31;
    if (warp >= N) return;
    int beg = rowptr[warp], end = rowptr[warp + 1];
    int qe = lane >> 3;      // edge slot 0..3
    int cl = lane & 7;       // col group
    float4 a0 = {0.f, 0.f, 0.f, 0.f};
    float4 a1 = {0.f, 0.f, 0.f, 0.f};
#pragma unroll 2
    for (int i = beg + qe; i < end; i += 4) {
        uint2 p = __ldg(ewp + i);
        float w = __uint_as_float(p.y);
        const float* xp = u + (size_t)p.x * 192 + 128;
        float4 x0 = *(const float4*)(xp + cl * 4);
        float4 x1 = *(const float4*)(xp + 32 + cl * 4);
        a0.x = fmaf(w, x0.x, a0.x); a0.y = fmaf(w, x0.y, a0.y);
        a0.z = fmaf(w, x0.z, a0.z); a0.w = fmaf(w, x0.w, a0.w);
        a1.x = fmaf(w, x1.x, a1.x); a1.y = fmaf(w, x1.y, a1.y);
        a1.z = fmaf(w, x1.z, a1.z); a1.w = fmaf(w, x1.w, a1.w);
    }
#pragma unroll
    for (int off = 16; off >= 8; off >>= 1) {
        a0.x += __shfl_down_sync(0xffffffffu, a0.x, off);
        a0.y += __shfl_down_sync(0xffffffffu, a0.y, off);
        a0.z += __shfl_down_sync(0xffffffffu, a0.z, off);
        a0.w += __shfl_down_sync(0xffffffffu, a0.w, off);
        a1.x += __shfl_down_sync(0xffffffffu, a1.x, off);
        a1.y += __shfl_down_sync(0xffffffffu, a1.y, off);
        a1.z += __shfl_down_sync(0xffffffffu, a1.z, off);
        a1.w += __shfl_down_sync(0xffffffffu, a1.w, off);
    }
    if (lane < 8) {
        float sc = -2.f * __ldg(dis + warp);
        const float* up = u + (size_t)warp * 192 + 64;
        float4 u1a = *(const float4*)(up + cl * 4);
        float4 u1b = *(const float4*)(up + 32 + cl * 4);
        float4 o0, o1;
        o0.x = fmaf(sc, a0.x, u1a.x); o0.y = fmaf(sc, a0.y, u1a.y);
        o0.z = fmaf(sc, a0.z, u1a.z); o0.w = fmaf(sc, a0.w, u1a.w);
        o1.x = fmaf(sc, a1.x, u1b.x); o1.y = fmaf(sc, a1.y, u1b.y);
        o1.z = fmaf(sc, a1.z, u1b.z); o1.w = fmaf(sc, a1.w, u1b.w);
        float* vp = v + (size_t)warp * 64;
        *(float4*)(vp + cl * 4) = o0;
        *(float4*)(vp + 32 + cl * 4) = o1;
    }
}

// =================== fused CSR SpMM pass 2: h = relu(u0 + (-dis)*L'(v)) -> hbuf, jk ===================
__global__ __launch_bounds__(256)
void spmm_h(const float* __restrict__ v, const float* __restrict__ u,
            const int* __restrict__ rowptr, const uint2* __restrict__ ewp,
            const float* __restrict__ dis,
            float* __restrict__ hbuf, float* __restrict__ jk, int N) {
    int warp = (blockIdx.x * blockDim.x + threadIdx.x) >> 5;
    int lane = threadIdx.x & 31;
    if (warp >= N) return;
    int beg = rowptr[warp], end = rowptr[warp + 1];
    int qe = lane >> 3;
    int cl = lane & 7;
    float4 a0 = {0.f, 0.f, 0.f, 0.f};
    float4 a1 = {0.f, 0.f, 0.f, 0.f};
#pragma unroll 2
    for (int i = beg + qe; i < end; i += 4) {
        uint2 p = __ldg(ewp + i);
        float w = __uint_as_float(p.y);
        const float* xp = v + (size_t)p.x * 64;
        float4 x0 = *(const float4*)(xp + cl * 4);
        float4 x1 = *(const float4*)(xp + 32 + cl * 4);
        a0.x = fmaf(w, x0.x, a0.x); a0.y = fmaf(w, x0.y, a0.y);
        a0.z = fmaf(w, x0.z, a0.z); a0.w = fmaf(w, x0.w, a0.w);
        a1.x = fmaf(w, x1.x, a1.x); a1.y = fmaf(w, x1.y, a1.y);
        a1.z = fmaf(w, x1.z, a1.z); a1.w = fmaf(w, x1.w, a1.w);
    }
#pragma unroll
    for (int off = 16; off >= 8; off >>= 1) {
        a0.x += __shfl_down_sync(0xffffffffu, a0.x, off);
        a0.y += __shfl_down_sync(0xffffffffu, a0.y, off);
        a0.z += __shfl_down_sync(0xffffffffu, a0.z, off);
        a0.w += __shfl_down_sync(0xffffffffu, a0.w, off);
        a1.x += __shfl_down_sync(0xffffffffu, a1.x, off);
        a1.y += __shfl_down_sync(0xffffffffu, a1.y, off);
        a1.z += __shfl_down_sync(0xffffffffu, a1.z, off);
        a1.w += __shfl_down_sync(0xffffffffu, a1.w, off);
    }
    if (lane < 8) {
        float sc = -__ldg(dis + warp);
        const float* up = u + (size_t)warp * 192;
        float4 u0a = *(const float4*)(up + cl * 4);
        float4 u0b = *(const float4*)(up + 32 + cl * 4);
        float4 o0, o1;
        o0.x = fmaxf(fmaf(sc, a0.x, u0a.x), 0.f); o0.y = fmaxf(fmaf(sc, a0.y, u0a.y), 0.f);
        o0.z = fmaxf(fmaf(sc, a0.z, u0a.z), 0.f); o0.w = fmaxf(fmaf(sc, a0.w, u0a.w), 0.f);
        o1.x = fmaxf(fmaf(sc, a1.x, u0b.x), 0.f); o1.y = fmaxf(fmaf(sc, a1.y, u0b.y), 0.f);
        o1.z = fmaxf(fmaf(sc, a1.z, u0b.z), 0.f); o1.w = fmaxf(fmaf(sc, a1.w, u0b.w), 0.f);
        float* hp = hbuf + (size_t)warp * 64;
        float* jp = jk + (size_t)warp * 256;
        *(float4*)(hp + cl * 4) = o0;
        *(float4*)(hp + 32 + cl * 4) = o1;
        *(float4*)(jp + cl * 4) = o0;
        *(float4*)(jp + 32 + cl * 4) = o1;
    }
}

// =================== launcher ===================
extern "C" void kernel_launch(void* const* d_in, const int* in_sizes, int n_in,
                              void* d_out, int out_size) {
    const float* features = (const float*)d_in[0];
    const int* edge_index = (const int*)d_in[1];
    const float* edgenet  = (const float*)d_in[2];
    const float* pae_w1 = (const float*)d_in[3];
    const float* pae_b1 = (const float*)d_in[4];
    const float* pae_bn_g = (const float*)d_in[5];
    const float* pae_bn_b = (const float*)d_in[6];
    const float* pae_bn_rm = (const float*)d_in[7];
    const float* pae_bn_rv = (const float*)d_in[8];
    const float* pae_w2 = (const float*)d_in[9];
    const float* pae_b2 = (const float*)d_in[10];
    const float* cheb_w[4] = {(const float*)d_in[11], (const float*)d_in[12],
                              (const float*)d_in[13], (const float*)d_in[14]};
    const float* cls_w1 = (const float*)d_in[15];
    const float* cls_b1 = (const float*)d_in[16];
    const float* cls_bn_g = (const float*)d_in[17];
    const float* cls_bn_b = (const float*)d_in[18];
    const float* cls_bn_rm = (const float*)d_in[19];
    const float* cls_bn_rv = (const float*)d_in[20];
    const float* cls_w2 = (const float*)d_in[21];
    const float* cls_b2 = (const float*)d_in[22];

    int N = in_sizes[0] / 128;
    int E = in_sizes[1] / 2;
    const int* row = edge_index;
    const int* col = edge_index + E;

    float* out = (float*)d_out;
    float* jk = out;
    float* logit = out + (size_t)N * 256;
    float* ew = logit + (size_t)N * 2;

    float *vbuf, *ubuf, *ha, *hb, *dis, *b2f, *cw2, *cb2;
    uint2* ewp;
    int *rowptr, *cursor, *cnt, *ecol, *eidx;
    __nv_bfloat16 *wt_hi, *wt_lo;
    uint4 *frag_cheb[4], *frag_cls;
    cudaGetSymbolAddress((void**)&vbuf, g_v);
    cudaGetSymbolAddress((void**)&ubuf, g_u);
    cudaGetSymbolAddress((void**)&ha, g_ha);
    cudaGetSymbolAddress((void**)&hb, g_hb);
    cudaGetSymbolAddress((void**)&ewp, g_ewp);
    cudaGetSymbolAddress((void**)&dis, g_dis);
    cudaGetSymbolAddress((void**)&rowptr, g_rowptr);
    cudaGetSymbolAddress((void**)&cursor, g_cursor);
    cudaGetSymbolAddress((void**)&cnt, g_cnt);
    cudaGetSymbolAddress((void**)&ecol, g_ecol);
    cudaGetSymbolAddress((void**)&eidx, g_eidx);
    cudaGetSymbolAddress((void**)&wt_hi, g_w2t_hi);
    cudaGetSymbolAddress((void**)&wt_lo, g_w2t_lo);
    cudaGetSymbolAddress((void**)&b2f, g_b2f);
    cudaGetSymbolAddress((void**)&cw2, g_cw2);
    cudaGetSymbolAddress((void**)&cb2, g_cb2);
    cudaGetSymbolAddress((void**)&frag_cheb[0], g_frag_cheb0);
    cudaGetSymbolAddress((void**)&frag_cheb[1], g_frag_cheb1);
    cudaGetSymbolAddress((void**)&frag_cheb[2], g_frag_cheb2);
    cudaGetSymbolAddress((void**)&frag_cheb[3], g_frag_cheb3);
    cudaGetSymbolAddress((void**)&frag_cls, g_frag_cls);

    cudaFuncSetAttribute(pae_mma_kernel, cudaFuncAttributeMaxDynamicSharedMemorySize, PAE_SMEM);
    cudaFuncSetAttribute(gemm_mma, cudaFuncAttributeMaxDynamicSharedMemorySize, 65536);
    cudaFuncSetAttribute(gemm_mma_cls, cudaFuncAttributeMaxDynamicSharedMemorySize, 65536);

    int rowTiles = (N + 127) / 128;
    int rowWarpBlocks = (N * 32 + 255) / 256;

    // ---- fork: side stream does CSR build + weight prep + layer-0 GEMM ----
    cudaEventRecord(g_evF, 0);
    cudaStreamWaitEvent(g_s2, g_evF, 0);

    cudaMemsetAsync(cnt, 0, (size_t)N * sizeof(int), g_s2);
    hist_kernel<<<(E + 255) / 256, 256, 0, g_s2>>>(row, cnt, E);
    scan_kernel<<<1, 1024, 0, g_s2>>>(cnt, N, rowptr, cursor);
    scatter_kernel<<<(E + 255) / 256, 256, 0, g_s2>>>(row, col, cursor, ecol, eidx, E);
    fold_cls_kernel<<<1, 256, 0, g_s2>>>(cls_bn_g, cls_bn_b, cls_bn_rm, cls_bn_rv,
                                         cls_w2, cls_b2, cw2, cb2);
    prep_cheb_frag128<<<24, 256, 0, g_s2>>>(cheb_w[0], frag_cheb[0]);
    prep_cheb_frag64x3<<<dim3(12, 3), 256, 0, g_s2>>>(cheb_w[1], cheb_w[2], cheb_w[3],
                                                      frag_cheb[1], frag_cheb[2], frag_cheb[3]);
    prep_frag<<<64, 256, 0, g_s2>>>(cls_w1, 256, 256, frag_cls);
    logit_init_kernel<<<(N + 255) / 256, 256, 0, g_s2>>>(cb2, logit, N);
    // layer-0 GEMM is graph-independent: u = features @ [W0-W2 | W1 | W2]
    gemm_mma<<<dim3(rowTiles, 3), 256, 8 * 4096, g_s2>>>(
        features, 128, N, frag_cheb[0], 8, 192, ubuf);

    // ---- main stream: PAE ----
    fold_pae_kernel<<<129, 128>>>(pae_bn_g, pae_bn_b, pae_bn_rm, pae_bn_rv, pae_w2, pae_b2,
                                  wt_hi, wt_lo, b2f);
    pae_mma_kernel<<<148, 256, PAE_SMEM>>>(edgenet, pae_w1, pae_b1, wt_hi, wt_lo, b2f, ew, E);

    // ---- join ----
    cudaEventRecord(g_evJ, g_s2);
    cudaStreamWaitEvent(0, g_evJ, 0);

    // ---- graph normalization via CSR ----
    dis_csr_kernel<<<rowWarpBlocks, 256>>>(ew, rowptr, eidx, dis, N);
    ewp_kernel<<<(E + 255) / 256, 256>>>(ew, eidx, ecol, dis, ewp, E);

    // ---- GCN layers (layer 0's GEMM already done on side stream) ----
    float* hbufs[2] = {ha, hb};
    for (int l = 0; l < 4; l++) {
        if (l > 0) {
            gemm_mma<<<dim3(rowTiles, 3), 256, 4 * 4096>>>(
                hbufs[(l - 1) & 1], 64, N, frag_cheb[l], 4, 192, ubuf);
        }
        spmm_v<<<rowWarpBlocks, 256>>>(ubuf, rowptr, ewp, dis, vbuf, N);
        spmm_h<<<rowWarpBlocks, 256>>>(vbuf, ubuf, rowptr, ewp, dis,
                                       hbufs[l & 1], jk + (size_t)l * 64, N);
    }

    // ---- classifier fused with logit ----
    gemm_mma_cls<<<dim3(rowTiles, 4), 256, 16 * 4096>>>(
        jk, 256, N, frag_cls, 16, cls_b1, cw2, logit);
}

// round 10
// speedup vs baseline: 3.1849x; 1.0150x over previous
#include <cuda_runtime.h>
#include <cuda_bf16.h>
#include <math.h>
#include <stdint.h>

typedef unsigned long long ull;
typedef unsigned int uint;

#define NMAX 50000
#define EMAX 1600000

// ---------------- device scratch (no allocations allowed) ----------------
__device__ float g_v[(size_t)NMAX * 64];        // v = u1 + 2*L(u2)
__device__ float g_u[(size_t)NMAX * 192];       // [u0 | u1 | u2]
__device__ float g_ha[(size_t)NMAX * 64];
__device__ float g_hb[(size_t)NMAX * 64];
__device__ uint2 g_ewp[EMAX];                   // {col, ew*dis[col]} in CSR order
__device__ float g_dis[NMAX];                   // rsqrt(deg) or 0
__device__ float g_deg[NMAX];
__device__ int   g_rowptr[NMAX + 1];
__device__ int   g_cursor[NMAX];
__device__ int   g_cnt[NMAX];
__device__ int   g_ecol[EMAX];                  // col in CSR order
__device__ int   g_eidx[EMAX];                  // original edge id in CSR order
__device__ __nv_bfloat16 g_w2t_hi[128 * 128];   // PAE W2fT hi, [n][k]
__device__ __nv_bfloat16 g_w2t_lo[128 * 128];   // PAE W2fT lo
__device__ float g_b2f[128];
__device__ float g_cw2[256 * 2];
__device__ float g_cb2[2];
// B fragments for mma GEMMs (uint4 = {hi_b0, hi_b1, lo_b0, lo_b1})
__device__ uint4 g_frag_cheb0[3 * 8 * 256];     // K=128, 192 cols
__device__ uint4 g_frag_cheb1[3 * 4 * 256];     // K=64
__device__ uint4 g_frag_cheb2[3 * 4 * 256];
__device__ uint4 g_frag_cheb3[3 * 4 * 256];
__device__ uint4 g_frag_cls[4 * 16 * 256];      // K=256, 256 cols

// ---------------- side stream + fork/join events (created pre-main, reused) ----------------
static cudaStream_t g_s2 = []() {
    cudaStream_t s; cudaStreamCreateWithFlags(&s, cudaStreamNonBlocking); return s;
}();
static cudaEvent_t g_evF = []() {
    cudaEvent_t e; cudaEventCreateWithFlags(&e, cudaEventDisableTiming); return e;
}();
static cudaEvent_t g_evJ = []() {
    cudaEvent_t e; cudaEventCreateWithFlags(&e, cudaEventDisableTiming); return e;
}();

// =================== warp-level bf16 MMA ===================
__device__ __forceinline__ void mma16816(float* d,
                                         uint a0, uint a1, uint a2, uint a3,
                                         uint b0, uint b1) {
    asm volatile(
        "mma.sync.aligned.m16n8k16.row.col.f32.bf16.bf16.f32 "
        "{%0,%1,%2,%3}, {%4,%5,%6,%7}, {%8,%9}, {%0,%1,%2,%3};"
        : "+f"(d[0]), "+f"(d[1]), "+f"(d[2]), "+f"(d[3])
        : "r"(a0), "r"(a1), "r"(a2), "r"(a3), "r"(b0), "r"(b1));
}

__device__ __forceinline__ void mma16816s(float& d0, float& d1, float& d2, float& d3,
                                          uint a0, uint a1, uint a2, uint a3,
                                          uint b0, uint b1) {
    asm volatile(
        "mma.sync.aligned.m16n8k16.row.col.f32.bf16.bf16.f32 "
        "{%0,%1,%2,%3}, {%4,%5,%6,%7}, {%8,%9}, {%0,%1,%2,%3};"
        : "+f"(d0), "+f"(d1), "+f"(d2), "+f"(d3)
        : "r"(a0), "r"(a1), "r"(a2), "r"(a3), "r"(b0), "r"(b1));
}

__device__ __forceinline__ void mma16808(float* d, uint a0, uint a1, uint b0) {
    asm volatile(
        "mma.sync.aligned.m16n8k8.row.col.f32.bf16.bf16.f32 "
        "{%0,%1,%2,%3}, {%4,%5}, {%6}, {%0,%1,%2,%3};"
        : "+f"(d[0]), "+f"(d[1]), "+f"(d[2]), "+f"(d[3])
        : "r"(a0), "r"(a1), "r"(b0));
}

__device__ __forceinline__ void split2(float a, float b, uint& hi, uint& lo) {
    __nv_bfloat162 h = __floats2bfloat162_rn(a, b);
    float2 f = __bfloat1622float2(h);
    __nv_bfloat162 l = __floats2bfloat162_rn(a - f.x, b - f.y);
    hi = *(uint*)&h;
    lo = *(uint*)&l;
}

// =================== BN folding kernels ===================
__global__ void fold_pae_kernel(const float* __restrict__ g, const float* __restrict__ b,
                                const float* __restrict__ rm, const float* __restrict__ rv,
                                const float* __restrict__ w2, const float* __restrict__ b2,
                                __nv_bfloat16* __restrict__ wt_hi, __nv_bfloat16* __restrict__ wt_lo,
                                float* __restrict__ b2f) {
    int j = threadIdx.x;  // 128 threads
    int blk = blockIdx.x;
    if (blk < 128) {
        float sj = g[j] * rsqrtf(rv[j] + 1e-5f);
        int jj = blk;
        float v = sj * __ldg(w2 + (size_t)j * 128 + jj);
        __nv_bfloat16 hi = __float2bfloat16(v);
        wt_hi[jj * 128 + j] = hi;
        wt_lo[jj * 128 + j] = __float2bfloat16(v - __bfloat162float(hi));
    } else {
        __shared__ float t[128];
        float si = g[j] * rsqrtf(rv[j] + 1e-5f);
        t[j] = b[j] - rm[j] * si;
        __syncthreads();
        float acc = b2[j];
#pragma unroll 8
        for (int i = 0; i < 128; i++) acc += t[i] * __ldg(w2 + i * 128 + j);
        b2f[j] = acc;
    }
}

__global__ void fold_cls_kernel(const float* __restrict__ g, const float* __restrict__ b,
                                const float* __restrict__ rm, const float* __restrict__ rv,
                                const float* __restrict__ w2, const float* __restrict__ b2,
                                float* __restrict__ cw2, float* __restrict__ cb2) {
    __shared__ float p0[256], p1[256];
    int i = threadIdx.x;  // 256 threads
    float si = g[i] * rsqrtf(rv[i] + 1e-5f);
    float ti = b[i] - rm[i] * si;
    float w0 = w2[2 * i], w1 = w2[2 * i + 1];
    cw2[2 * i]     = si * w0;
    cw2[2 * i + 1] = si * w1;
    p0[i] = ti * w0;
    p1[i] = ti * w1;
    __syncthreads();
    for (int off = 128; off; off >>= 1) {
        if (i < off) { p0[i] += p0[i + off]; p1[i] += p1[i + off]; }
        __syncthreads();
    }
    if (i == 0) { cb2[0] = b2[0] + p0[0]; cb2[1] = b2[1] + p1[0]; }
}

__global__ void logit_init_kernel(const float* __restrict__ cb2, float* __restrict__ logit, int N) {
    int i = blockIdx.x * blockDim.x + threadIdx.x;
    if (i < N) {
        logit[2 * i]     = cb2[0];
        logit[2 * i + 1] = cb2[1];
    }
}

// =================== fragment prep kernels ===================
__global__ void prep_frag(const float* __restrict__ W, int K, int Ncols, uint4* __restrict__ out) {
    int ktiles = K >> 4;
    int total = (Ncols >> 6) * ktiles * 256;
    int idx = blockIdx.x * 256 + threadIdx.x;
    if (idx >= total) return;
    int lane = idx & 31;
    int nt = (idx >> 5) & 7;
    int rest = idx >> 8;
    int kt = rest % ktiles;
    int chunk = rest / ktiles;
    int n = chunk * 64 + nt * 8 + (lane >> 2);
    int k0 = kt * 16 + (lane & 3) * 2;
    float w00 = W[(size_t)k0 * Ncols + n];
    float w01 = W[(size_t)(k0 + 1) * Ncols + n];
    float w10 = W[(size_t)(k0 + 8) * Ncols + n];
    float w11 = W[(size_t)(k0 + 9) * Ncols + n];
    uint4 v;
    split2(w00, w01, v.x, v.z);
    split2(w10, w11, v.y, v.w);
    out[idx] = v;
}

// Cheb composite Wc[k][n]: n<64: W0-W2 ; 64<=n<128: W1 ; n>=128: W2.  W: [3][K][64]
__device__ __forceinline__ void cheb_frag_body(const float* __restrict__ W, int K,
                                               uint4* __restrict__ out, int idx) {
    int ktiles = K >> 4;
    int lane = idx & 31;
    int nt = (idx >> 5) & 7;
    int rest = idx >> 8;
    int kt = rest % ktiles;
    int chunk = rest / ktiles;
    int n = chunk * 64 + nt * 8 + (lane >> 2);
    int k0 = kt * 16 + (lane & 3) * 2;
    int part = n >> 6, nn = n & 63;
    float w[4];
#pragma unroll
    for (int q = 0; q < 4; q++) {
        int k = k0 + (q >> 1) * 8 + (q & 1);
        float v;
        if (part == 0)      v = W[(size_t)k * 64 + nn] - W[(size_t)(2 * K + k) * 64 + nn];
        else if (part == 1) v = W[(size_t)(K + k) * 64 + nn];
        else                v = W[(size_t)(2 * K + k) * 64 + nn];
        w[q] = v;
    }
    uint4 v;
    split2(w[0], w[1], v.x, v.z);
    split2(w[2], w[3], v.y, v.w);
    out[idx] = v;
}

__global__ void prep_cheb_frag128(const float* __restrict__ W, uint4* __restrict__ out) {
    int idx = blockIdx.x * 256 + threadIdx.x;
    if (idx < 3 * 8 * 256) cheb_frag_body(W, 128, out, idx);
}

__global__ void prep_cheb_frag64x3(const float* __restrict__ W1, const float* __restrict__ W2,
                                   const float* __restrict__ W3,
                                   uint4* __restrict__ o1, uint4* __restrict__ o2,
                                   uint4* __restrict__ o3) {
    int idx = blockIdx.x * 256 + threadIdx.x;
    if (idx >= 3 * 4 * 256) return;
    const float* W = (blockIdx.y == 0) ? W1 : (blockIdx.y == 1) ? W2 : W3;
    uint4* out = (blockIdx.y == 0) ? o1 : (blockIdx.y == 1) ? o2 : o3;
    cheb_frag_body(W, 64, out, idx);
}

// =================== generic split-bf16 mma GEMM (per-chunk; used for layer 0 + cls path) ===================
__global__ __launch_bounds__(256)
void gemm_mma(const float* __restrict__ A, int lda, int M,
              const uint4* __restrict__ bfrag, int ktiles,
              int ldc, float* __restrict__ C) {
    extern __shared__ uint4 sB[];   // [ktiles][8][32]
    int tid = threadIdx.x, lane = tid & 31, wid = tid >> 5;
    const uint4* src = bfrag + (size_t)blockIdx.y * ktiles * 256;
    for (int i = tid; i < ktiles * 256; i += 256) sB[i] = src[i];
    __syncthreads();

    int r1 = blockIdx.x * 128 + wid * 16 + (lane >> 2);
    int r2 = r1 + 8;
    int rl1 = min(r1, M - 1), rl2 = min(r2, M - 1);
    int cq = (lane & 3) * 2;
    const float* A1 = A + (size_t)rl1 * lda;
    const float* A2 = A + (size_t)rl2 * lda;

    float acc[8][4];
#pragma unroll
    for (int i = 0; i < 8; i++) { acc[i][0] = acc[i][1] = acc[i][2] = acc[i][3] = 0.f; }

    for (int kt = 0; kt < ktiles; kt++) {
        int k0 = kt * 16 + cq;
        float2 xa = *(const float2*)(A1 + k0);
        float2 xb = *(const float2*)(A2 + k0);
        float2 xc = *(const float2*)(A1 + k0 + 8);
        float2 xd = *(const float2*)(A2 + k0 + 8);
        uint ahi[4], alo[4];
        split2(xa.x, xa.y, ahi[0], alo[0]);
        split2(xb.x, xb.y, ahi[1], alo[1]);
        split2(xc.x, xc.y, ahi[2], alo[2]);
        split2(xd.x, xd.y, ahi[3], alo[3]);

        const uint4* bp = sB + kt * 256 + lane;
        uint4 b[8];
#pragma unroll
        for (int nt = 0; nt < 8; nt++) b[nt] = bp[nt * 32];
#pragma unroll
        for (int nt = 0; nt < 8; nt++)
            mma16816(acc[nt], ahi[0], ahi[1], ahi[2], ahi[3], b[nt].x, b[nt].y);
#pragma unroll
        for (int nt = 0; nt < 8; nt++)
            mma16816(acc[nt], alo[0], alo[1], alo[2], alo[3], b[nt].x, b[nt].y);
#pragma unroll
        for (int nt = 0; nt < 8; nt++)
            mma16816(acc[nt], ahi[0], ahi[1], ahi[2], ahi[3], b[nt].z, b[nt].w);
    }

#pragma unroll
    for (int nt = 0; nt < 8; nt++) {
        int cc = blockIdx.y * 64 + nt * 8 + cq;
        if (r1 < M) { float2 o = {acc[nt][0], acc[nt][1]}; *(float2*)(C + (size_t)r1 * ldc + cc) = o; }
        if (r2 < M) { float2 o = {acc[nt][2], acc[nt][3]}; *(float2*)(C + (size_t)r2 * ldc + cc) = o; }
    }
}

// =================== merged 3-chunk GEMM for K=64 layers: A read once, 192 cols ===================
__global__ __launch_bounds__(256)
void gemm_mma3(const float* __restrict__ A, int M,
               const uint4* __restrict__ bfrag, float* __restrict__ C) {
    extern __shared__ uint4 sB[];   // [3][4][8][32] = 48KB
    int tid = threadIdx.x, lane = tid & 31, wid = tid >> 5;
    for (int i = tid; i < 3 * 4 * 256; i += 256) sB[i] = bfrag[i];
    __syncthreads();

    int r1 = blockIdx.x * 128 + wid * 16 + (lane >> 2);
    int r2 = r1 + 8;
    int rl1 = min(r1, M - 1), rl2 = min(r2, M - 1);
    int cq = (lane & 3) * 2;
    const float* A1 = A + (size_t)rl1 * 64;
    const float* A2 = A + (size_t)rl2 * 64;

    float acc[24][4];
#pragma unroll
    for (int i = 0; i < 24; i++) { acc[i][0] = acc[i][1] = acc[i][2] = acc[i][3] = 0.f; }

#pragma unroll
    for (int kt = 0; kt < 4; kt++) {
        int k0 = kt * 16 + cq;
        float2 xa = *(const float2*)(A1 + k0);
        float2 xb = *(const float2*)(A2 + k0);
        float2 xc = *(const float2*)(A1 + k0 + 8);
        float2 xd = *(const float2*)(A2 + k0 + 8);
        uint ahi[4], alo[4];
        split2(xa.x, xa.y, ahi[0], alo[0]);
        split2(xb.x, xb.y, ahi[1], alo[1]);
        split2(xc.x, xc.y, ahi[2], alo[2]);
        split2(xd.x, xd.y, ahi[3], alo[3]);

#pragma unroll
        for (int c = 0; c < 3; c++) {
            const uint4* bp = sB + (c * 4 + kt) * 256 + lane;
#pragma unroll
            for (int nt = 0; nt < 8; nt++) {
                uint4 b = bp[nt * 32];
                float* d = acc[c * 8 + nt];
                mma16816(d, ahi[0], ahi[1], ahi[2], ahi[3], b.x, b.y);
                mma16816(d, alo[0], alo[1], alo[2], alo[3], b.x, b.y);
                mma16816(d, ahi[0], ahi[1], ahi[2], ahi[3], b.z, b.w);
            }
        }
    }

#pragma unroll
    for (int c = 0; c < 3; c++) {
#pragma unroll
        for (int nt = 0; nt < 8; nt++) {
            int cc = c * 64 + nt * 8 + cq;
            const float* d = acc[c * 8 + nt];
            if (r1 < M) { float2 o = {d[0], d[1]}; *(float2*)(C + (size_t)r1 * 192 + cc) = o; }
            if (r2 < M) { float2 o = {d[2], d[3]}; *(float2*)(C + (size_t)r2 * 192 + cc) = o; }
        }
    }
}

// =================== classifier GEMM fused with logit ===================
__global__ __launch_bounds__(256)
void gemm_mma_cls(const float* __restrict__ A, int lda, int M,
                  const uint4* __restrict__ bfrag, int ktiles,
                  const float* __restrict__ bias, const float* __restrict__ cw2,
                  float* __restrict__ logit) {
    extern __shared__ uint4 sB[];
    int tid = threadIdx.x, lane = tid & 31, wid = tid >> 5;
    const uint4* src = bfrag + (size_t)blockIdx.y * ktiles * 256;
    for (int i = tid; i < ktiles * 256; i += 256) sB[i] = src[i];
    __syncthreads();

    int r1 = blockIdx.x * 128 + wid * 16 + (lane >> 2);
    int r2 = r1 + 8;
    int rl1 = min(r1, M - 1), rl2 = min(r2, M - 1);
    int cq = (lane & 3) * 2;
    const float* A1 = A + (size_t)rl1 * lda;
    const float* A2 = A + (size_t)rl2 * lda;

    float acc[8][4];
#pragma unroll
    for (int i = 0; i < 8; i++) { acc[i][0] = acc[i][1] = acc[i][2] = acc[i][3] = 0.f; }

    for (int kt = 0; kt < ktiles; kt++) {
        int k0 = kt * 16 + cq;
        float2 xa = *(const float2*)(A1 + k0);
        float2 xb = *(const float2*)(A2 + k0);
        float2 xc = *(const float2*)(A1 + k0 + 8);
        float2 xd = *(const float2*)(A2 + k0 + 8);
        uint ahi[4], alo[4];
        split2(xa.x, xa.y, ahi[0], alo[0]);
        split2(xb.x, xb.y, ahi[1], alo[1]);
        split2(xc.x, xc.y, ahi[2], alo[2]);
        split2(xd.x, xd.y, ahi[3], alo[3]);

        const uint4* bp = sB + kt * 256 + lane;
        uint4 b[8];
#pragma unroll
        for (int nt = 0; nt < 8; nt++) b[nt] = bp[nt * 32];
#pragma unroll
        for (int nt = 0; nt < 8; nt++)
            mma16816(acc[nt], ahi[0], ahi[1], ahi[2], ahi[3], b[nt].x, b[nt].y);
#pragma unroll
        for (int nt = 0; nt < 8; nt++)
            mma16816(acc[nt], alo[0], alo[1], alo[2], alo[3], b[nt].x, b[nt].y);
#pragma unroll
        for (int nt = 0; nt < 8; nt++)
            mma16816(acc[nt], ahi[0], ahi[1], ahi[2], ahi[3], b[nt].z, b[nt].w);
    }

    float l0a = 0.f, l1a = 0.f, l0b = 0.f, l1b = 0.f;
#pragma unroll
    for (int nt = 0; nt < 8; nt++) {
        int cc = blockIdx.y * 64 + nt * 8 + cq;
        float b0 = bias[cc], b1 = bias[cc + 1];
        float v0 = fmaxf(acc[nt][0] + b0, 0.f);
        float v1 = fmaxf(acc[nt][1] + b1, 0.f);
        float v2 = fmaxf(acc[nt][2] + b0, 0.f);
        float v3 = fmaxf(acc[nt][3] + b1, 0.f);
        float c00 = cw2[2 * cc], c01 = cw2[2 * cc + 1];
        float c10 = cw2[2 * cc + 2], c11 = cw2[2 * cc + 3];
        l0a = fmaf(v0, c00, fmaf(v1, c10, l0a));
        l1a = fmaf(v0, c01, fmaf(v1, c11, l1a));
        l0b = fmaf(v2, c00, fmaf(v3, c10, l0b));
        l1b = fmaf(v2, c01, fmaf(v3, c11, l1b));
    }
#pragma unroll
    for (int off = 1; off <= 2; off <<= 1) {
        l0a += __shfl_xor_sync(0xffffffffu, l0a, off);
        l1a += __shfl_xor_sync(0xffffffffu, l1a, off);
        l0b += __shfl_xor_sync(0xffffffffu, l0b, off);
        l1b += __shfl_xor_sync(0xffffffffu, l1b, off);
    }
    if ((lane & 3) == 0) {
        if (r1 < M) {
            atomicAdd(&logit[2 * r1], l0a);
            atomicAdd(&logit[2 * r1 + 1], l1a);
        }
        if (r2 < M) {
            atomicAdd(&logit[2 * r2], l0b);
            atomicAdd(&logit[2 * r2 + 1], l1b);
        }
    }
}

// =================== PAE mma.sync kernel (deg accumulation fused into epilogue) ===================
#define PAE_SMEM 70144

__global__ __launch_bounds__(256, 1)
void pae_mma_kernel(const float* __restrict__ edgenet,
                    const float* __restrict__ w1, const float* __restrict__ b1,
                    const __nv_bfloat16* __restrict__ wt_hi, const __nv_bfloat16* __restrict__ wt_lo,
                    const float* __restrict__ b2f, const int* __restrict__ rowidx,
                    float* __restrict__ ew, float* __restrict__ deg, int E) {
    extern __shared__ char smraw[];
    uint4* s_bfrag = (uint4*)smraw;
    uint2* s_w1f = (uint2*)(smraw + 65536);   // [16 ntiles][32 lanes]
    float* s_b2f = (float*)(smraw + 69632);

    int tid = threadIdx.x, lane = tid & 31, wid = tid >> 5;

    if (tid < 128) s_b2f[tid] = b2f[tid];
    for (int idx = tid; idx < 512; idx += 256) {
        int nt = idx >> 5, ln = idx & 31;
        int n = nt * 8 + (ln >> 2);
        int k0 = (ln & 3) * 2;
        float v0, v1;
        if (k0 < 6) { v0 = __ldg(w1 + k0 * 128 + n); v1 = __ldg(w1 + (k0 + 1) * 128 + n); }
        else        { v0 = __ldg(b1 + n); v1 = 0.f; }
        uint hi, lo;
        split2(v0, v1, hi, lo);
        s_w1f[idx] = make_uint2(hi, lo);
    }
    for (int idx = tid; idx < 4096; idx += 256) {
        int ln = idx & 31;
        int k2 = (idx >> 5) & 3;
        int nt = (idx >> 7) & 15;
        int hl = idx >> 11;
        const __nv_bfloat16* src = hl ? wt_lo : wt_hi;
        int n = nt * 8 + (ln >> 2);
        int kg0 = (2 * k2) * 16 + (ln & 3) * 2;
        const __nv_bfloat16* base = src + n * 128;
        uint4 v;
        v.x = *(const uint*)(base + kg0);
        v.y = *(const uint*)(base + kg0 + 8);
        v.z = *(const uint*)(base + kg0 + 16);
        v.w = *(const uint*)(base + kg0 + 24);
        s_bfrag[idx] = v;
    }
    __syncthreads();

    int r1 = lane >> 2;
    int cq = (lane & 3) * 2;
    int nT = (E + 15) >> 4;   // 16 edges per warp-iter

    // Rows r1 = half0 of edge ebase+r1, rows r1+8 = half1 of the SAME edge.
    auto build_tile = [&](int ebase, uint Ahi[8][4], uint Alo[8][4]) {
        int e = min(ebase + r1, E - 1);
        uint zhi0, zlo0, zhi1, zlo1;
        if (cq < 6) {
            const float* zp = edgenet + (size_t)e * 12 + cq;
            float2 za = __ldg((const float2*)zp);        // half0 (8B aligned)
            float2 zb = __ldg((const float2*)(zp + 6));  // half1
            split2(za.x, za.y, zhi0, zlo0);
            split2(zb.x, zb.y, zhi1, zlo1);
        } else {
            zhi0 = 0x00003f80u;  // (1.0, 0) bf16x2: bias row selector
            zhi1 = 0x00003f80u;
            zlo0 = 0u; zlo1 = 0u;
        }
#pragma unroll
        for (int j = 0; j < 8; j++) {
            uint2 we = s_w1f[(2 * j) * 32 + lane];
            uint2 wo = s_w1f[(2 * j + 1) * 32 + lane];
            float De[4] = {0.f, 0.f, 0.f, 0.f};
            float Do[4] = {0.f, 0.f, 0.f, 0.f};
            mma16808(De, zhi0, zhi1, we.x);
            mma16816(De, zlo0, zlo1, zhi0, zhi1, we.x, we.y);   // zlo*Whi + zhi*Wlo
            mma16808(Do, zhi0, zhi1, wo.x);
            mma16816(Do, zlo0, zlo1, zhi0, zhi1, wo.x, wo.y);
            float v0 = fmaxf(De[0], 0.f), v1 = fmaxf(De[1], 0.f);
            float v2 = fmaxf(De[2], 0.f), v3 = fmaxf(De[3], 0.f);
            split2(v0, v1, Ahi[j][0], Alo[j][0]);
            split2(v2, v3, Ahi[j][1], Alo[j][1]);
            v0 = fmaxf(Do[0], 0.f); v1 = fmaxf(Do[1], 0.f);
            v2 = fmaxf(Do[2], 0.f); v3 = fmaxf(Do[3], 0.f);
            split2(v0, v1, Ahi[j][2], Alo[j][2]);
            split2(v2, v3, Ahi[j][3], Alo[j][3]);
        }
    };

    for (int t = blockIdx.x * 8 + wid; t < nT; t += gridDim.x * 8) {
        int e0 = t << 4;

        uint Ahi0[8][4], Alo0[8][4], Ahi1[8][4], Alo1[8][4];
        build_tile(e0, Ahi0, Alo0);        // edges e0   .. e0+7
        build_tile(e0 + 8, Ahi1, Alo1);    // edges e0+8 .. e0+15

        float num0 = 0.f, p10 = 0.f, p20 = 0.f;
        float num1 = 0.f, p11 = 0.f, p21 = 0.f;

#pragma unroll 1
        for (int nt = 0; nt < 16; nt++) {
            const uint4* ph = s_bfrag + (nt * 4) * 32 + lane;
            const uint4* pl = ph + 16 * 4 * 32;
            uint4 bh0 = ph[0], bh1 = ph[32], bh2 = ph[64], bh3 = ph[96];
            uint4 bl0 = pl[0], bl1 = pl[32], bl2 = pl[64], bl3 = pl[96];
            uint bh[16] = {bh0.x, bh0.y, bh0.z, bh0.w, bh1.x, bh1.y, bh1.z, bh1.w,
                           bh2.x, bh2.y, bh2.z, bh2.w, bh3.x, bh3.y, bh3.z, bh3.w};
            uint bl[16] = {bl0.x, bl0.y, bl0.z, bl0.w, bl1.x, bl1.y, bl1.z, bl1.w,
                           bl2.x, bl2.y, bl2.z, bl2.w, bl3.x, bl3.y, bl3.z, bl3.w};
            float2 bb = *(const float2*)(s_b2f + nt * 8 + cq);

            {
                float dA0 = 0.f, dA1 = 0.f, dA2 = 0.f, dA3 = 0.f;
                float dB0 = 0.f, dB1 = 0.f, dB2 = 0.f, dB3 = 0.f;
                float dC0 = 0.f, dC1 = 0.f, dC2 = 0.f, dC3 = 0.f;
#pragma unroll
                for (int k = 0; k < 8; k++) {
                    mma16816s(dA0, dA1, dA2, dA3, Ahi0[k][0], Ahi0[k][1], Ahi0[k][2], Ahi0[k][3],
                              bh[2 * k], bh[2 * k + 1]);
                    mma16816s(dB0, dB1, dB2, dB3, Ahi0[k][0], Ahi0[k][1], Ahi0[k][2], Ahi0[k][3],
                              bl[2 * k], bl[2 * k + 1]);
                    mma16816s(dC0, dC1, dC2, dC3, Alo0[k][0], Alo0[k][1], Alo0[k][2], Alo0[k][3],
                              bh[2 * k], bh[2 * k + 1]);
                }
                float o0 = dA0 + dB0 + dC0 + bb.x;
                float o1 = dA1 + dB1 + dC1 + bb.y;
                float o2 = dA2 + dB2 + dC2 + bb.x;
                float o3 = dA3 + dB3 + dC3 + bb.y;
                num0 = fmaf(o0, o2, fmaf(o1, o3, num0));
                p10  = fmaf(o0, o0, fmaf(o1, o1, p10));
                p20  = fmaf(o2, o2, fmaf(o3, o3, p20));
            }
            {
                float dA0 = 0.f, dA1 = 0.f, dA2 = 0.f, dA3 = 0.f;
                float dB0 = 0.f, dB1 = 0.f, dB2 = 0.f, dB3 = 0.f;
                float dC0 = 0.f, dC1 = 0.f, dC2 = 0.f, dC3 = 0.f;
#pragma unroll
                for (int k = 0; k < 8; k++) {
                    mma16816s(dA0, dA1, dA2, dA3, Ahi1[k][0], Ahi1[k][1], Ahi1[k][2], Ahi1[k][3],
                              bh[2 * k], bh[2 * k + 1]);
                    mma16816s(dB0, dB1, dB2, dB3, Ahi1[k][0], Ahi1[k][1], Ahi1[k][2], Ahi1[k][3],
                              bl[2 * k], bl[2 * k + 1]);
                    mma16816s(dC0, dC1, dC2, dC3, Alo1[k][0], Alo1[k][1], Alo1[k][2], Alo1[k][3],
                              bh[2 * k], bh[2 * k + 1]);
                }
                float o0 = dA0 + dB0 + dC0 + bb.x;
                float o1 = dA1 + dB1 + dC1 + bb.y;
                float o2 = dA2 + dB2 + dC2 + bb.x;
                float o3 = dA3 + dB3 + dC3 + bb.y;
                num1 = fmaf(o0, o2, fmaf(o1, o3, num1));
                p11  = fmaf(o0, o0, fmaf(o1, o1, p11));
                p21  = fmaf(o2, o2, fmaf(o3, o3, p21));
            }
        }

#pragma unroll
        for (int off = 1; off <= 2; off <<= 1) {
            num0 += __shfl_xor_sync(0xffffffffu, num0, off);
            p10  += __shfl_xor_sync(0xffffffffu, p10, off);
            p20  += __shfl_xor_sync(0xffffffffu, p20, off);
            num1 += __shfl_xor_sync(0xffffffffu, num1, off);
            p11  += __shfl_xor_sync(0xffffffffu, p11, off);
            p21  += __shfl_xor_sync(0xffffffffu, p21, off);
        }

        if ((lane & 3) == 0) {
            int eA = e0 + r1;
            int eB = e0 + 8 + r1;
            if (eA < E) {
                float den = fmaxf(sqrtf(p10) * sqrtf(p20), 1e-8f);
                float w = fmaf(num0 / den, 0.5f, 0.5f);
                ew[eA] = w;
                atomicAdd(&deg[__ldg(rowidx + eA)], w);
            }
            if (eB < E) {
                float den = fmaxf(sqrtf(p11) * sqrtf(p21), 1e-8f);
                float w = fmaf(num1 / den, 0.5f, 0.5f);
                ew[eB] = w;
                atomicAdd(&deg[__ldg(rowidx + eB)], w);
            }
        }
    }
}

// =================== CSR build ===================
__global__ void hist_kernel(const int* __restrict__ row, int* __restrict__ cnt, int E) {
    int e = blockIdx.x * blockDim.x + threadIdx.x;
    if (e < E) atomicAdd(&cnt[row[e]], 1);
}

__global__ void scan_kernel(const int* __restrict__ cnt, int N,
                            int* __restrict__ rowptr, int* __restrict__ cursor) {
    __shared__ int part[1024];
    int t = threadIdx.x;
    int chunk = (N + 1023) / 1024;
    int b = t * chunk, e = min(b + chunk, N);
    int s = 0;
    for (int i = b; i < e; i++) s += cnt[i];
    part[t] = s;
    __syncthreads();
    for (int off = 1; off < 1024; off <<= 1) {
        int v = (t >= off) ? part[t - off] : 0;
        __syncthreads();
        part[t] += v;
        __syncthreads();
    }
    int run = t ? part[t - 1] : 0;
    for (int i = b; i < e; i++) {
        rowptr[i] = run;
        cursor[i] = run;
        run += cnt[i];
    }
    if (t == 1023) rowptr[N] = run;
}

__global__ void scatter_kernel(const int* __restrict__ row, const int* __restrict__ col,
                               int* __restrict__ cursor, int* __restrict__ ecol,
                               int* __restrict__ eidx, int E) {
    int e = blockIdx.x * blockDim.x + threadIdx.x;
    if (e >= E) return;
    int pos = atomicAdd(&cursor[row[e]], 1);
    ecol[pos] = col[e];
    eidx[pos] = e;
}

// dis[i] = deg>0 ? rsqrt(deg) : 0  (deg accumulated inside PAE)
__global__ void dis_kernel(const float* __restrict__ deg, float* __restrict__ dis, int N) {
    int i = blockIdx.x * blockDim.x + threadIdx.x;
    if (i < N) {
        float d = deg[i];
        dis[i] = (d > 0.f) ? rsqrtf(d) : 0.f;
    }
}

// ewp[i] = {col, ew[eidx[i]] * dis[col]}
__global__ void ewp_kernel(const float* __restrict__ ew, const int* __restrict__ eidx,
                           const int* __restrict__ ecol, const float* __restrict__ dis,
                           uint2* __restrict__ ewp, int E) {
    int i = blockIdx.x * blockDim.x + threadIdx.x;
    if (i >= E) return;
    int c = __ldg(ecol + i);
    float w = __ldg(ew + __ldg(eidx + i)) * __ldg(dis + c);
    ewp[i] = make_uint2((uint)c, __float_as_uint(w));
}

// =================== fused CSR SpMM pass 1: v = u1 + 2*(-dis)*L'(u2) ===================
__global__ __launch_bounds__(256)
void spmm_v(const float* __restrict__ u,
            const int* __restrict__ rowptr, const uint2* __restrict__ ewp,
            const float* __restrict__ dis,
            float* __restrict__ v, int N) {
    int warp = (blockIdx.x * blockDim.x + threadIdx.x) >> 5;
    int lane = threadIdx.x & 31;
    if (warp >= N) return;
    int beg = rowptr[warp], end = rowptr[warp + 1];
    int qe = lane >> 3;      // edge slot 0..3
    int cl = lane & 7;       // col group
    float4 a0 = {0.f, 0.f, 0.f, 0.f};
    float4 a1 = {0.f, 0.f, 0.f, 0.f};
#pragma unroll 2
    for (int i = beg + qe; i < end; i += 4) {
        uint2 p = __ldg(ewp + i);
        float w = __uint_as_float(p.y);
        const float* xp = u + (size_t)p.x * 192 + 128;
        float4 x0 = *(const float4*)(xp + cl * 4);
        float4 x1 = *(const float4*)(xp + 32 + cl * 4);
        a0.x = fmaf(w, x0.x, a0.x); a0.y = fmaf(w, x0.y, a0.y);
        a0.z = fmaf(w, x0.z, a0.z); a0.w = fmaf(w, x0.w, a0.w);
        a1.x = fmaf(w, x1.x, a1.x); a1.y = fmaf(w, x1.y, a1.y);
        a1.z = fmaf(w, x1.z, a1.z); a1.w = fmaf(w, x1.w, a1.w);
    }
#pragma unroll
    for (int off = 16; off >= 8; off >>= 1) {
        a0.x += __shfl_down_sync(0xffffffffu, a0.x, off);
        a0.y += __shfl_down_sync(0xffffffffu, a0.y, off);
        a0.z += __shfl_down_sync(0xffffffffu, a0.z, off);
        a0.w += __shfl_down_sync(0xffffffffu, a0.w, off);
        a1.x += __shfl_down_sync(0xffffffffu, a1.x, off);
        a1.y += __shfl_down_sync(0xffffffffu, a1.y, off);
        a1.z += __shfl_down_sync(0xffffffffu, a1.z, off);
        a1.w += __shfl_down_sync(0xffffffffu, a1.w, off);
    }
    if (lane < 8) {
        float sc = -2.f * __ldg(dis + warp);
        const float* up = u + (size_t)warp * 192 + 64;
        float4 u1a = *(const float4*)(up + cl * 4);
        float4 u1b = *(const float4*)(up + 32 + cl * 4);
        float4 o0, o1;
        o0.x = fmaf(sc, a0.x, u1a.x); o0.y = fmaf(sc, a0.y, u1a.y);
        o0.z = fmaf(sc, a0.z, u1a.z); o0.w = fmaf(sc, a0.w, u1a.w);
        o1.x = fmaf(sc, a1.x, u1b.x); o1.y = fmaf(sc, a1.y, u1b.y);
        o1.z = fmaf(sc, a1.z, u1b.z); o1.w = fmaf(sc, a1.w, u1b.w);
        float* vp = v + (size_t)warp * 64;
        *(float4*)(vp + cl * 4) = o0;
        *(float4*)(vp + 32 + cl * 4) = o1;
    }
}

// =================== fused CSR SpMM pass 2: h = relu(u0 + (-dis)*L'(v)) -> hbuf, jk ===================
__global__ __launch_bounds__(256)
void spmm_h(const float* __restrict__ v, const float* __restrict__ u,
            const int* __restrict__ rowptr, const uint2* __restrict__ ewp,
            const float* __restrict__ dis,
            float* __restrict__ hbuf, float* __restrict__ jk, int N) {
    int warp = (blockIdx.x * blockDim.x + threadIdx.x) >> 5;
    int lane = threadIdx.x & 31;
    if (warp >= N) return;
    int beg = rowptr[warp], end = rowptr[warp + 1];
    int qe = lane >> 3;
    int cl = lane & 7;
    float4 a0 = {0.f, 0.f, 0.f, 0.f};
    float4 a1 = {0.f, 0.f, 0.f, 0.f};
#pragma unroll 2
    for (int i = beg + qe; i < end; i += 4) {
        uint2 p = __ldg(ewp + i);
        float w = __uint_as_float(p.y);
        const float* xp = v + (size_t)p.x * 64;
        float4 x0 = *(const float4*)(xp + cl * 4);
        float4 x1 = *(const float4*)(xp + 32 + cl * 4);
        a0.x = fmaf(w, x0.x, a0.x); a0.y = fmaf(w, x0.y, a0.y);
        a0.z = fmaf(w, x0.z, a0.z); a0.w = fmaf(w, x0.w, a0.w);
        a1.x = fmaf(w, x1.x, a1.x); a1.y = fmaf(w, x1.y, a1.y);
        a1.z = fmaf(w, x1.z, a1.z); a1.w = fmaf(w, x1.w, a1.w);
    }
#pragma unroll
    for (int off = 16; off >= 8; off >>= 1) {
        a0.x += __shfl_down_sync(0xffffffffu, a0.x, off);
        a0.y += __shfl_down_sync(0xffffffffu, a0.y, off);
        a0.z += __shfl_down_sync(0xffffffffu, a0.z, off);
        a0.w += __shfl_down_sync(0xffffffffu, a0.w, off);
        a1.x += __shfl_down_sync(0xffffffffu, a1.x, off);
        a1.y += __shfl_down_sync(0xffffffffu, a1.y, off);
        a1.z += __shfl_down_sync(0xffffffffu, a1.z, off);
        a1.w += __shfl_down_sync(0xffffffffu, a1.w, off);
    }
    if (lane < 8) {
        float sc = -__ldg(dis + warp);
        const float* up = u + (size_t)warp * 192;
        float4 u0a = *(const float4*)(up + cl * 4);
        float4 u0b = *(const float4*)(up + 32 + cl * 4);
        float4 o0, o1;
        o0.x = fmaxf(fmaf(sc, a0.x, u0a.x), 0.f); o0.y = fmaxf(fmaf(sc, a0.y, u0a.y), 0.f);
        o0.z = fmaxf(fmaf(sc, a0.z, u0a.z), 0.f); o0.w = fmaxf(fmaf(sc, a0.w, u0a.w), 0.f);
        o1.x = fmaxf(fmaf(sc, a1.x, u0b.x), 0.f); o1.y = fmaxf(fmaf(sc, a1.y, u0b.y), 0.f);
        o1.z = fmaxf(fmaf(sc, a1.z, u0b.z), 0.f); o1.w = fmaxf(fmaf(sc, a1.w, u0b.w), 0.f);
        float* hp = hbuf + (size_t)warp * 64;
        float* jp = jk + (size_t)warp * 256;
        *(float4*)(hp + cl * 4) = o0;
        *(float4*)(hp + 32 + cl * 4) = o1;
        *(float4*)(jp + cl * 4) = o0;
        *(float4*)(jp + 32 + cl * 4) = o1;
    }
}

// =================== launcher ===================
extern "C" void kernel_launch(void* const* d_in, const int* in_sizes, int n_in,
                              void* d_out, int out_size) {
    const float* features = (const float*)d_in[0];
    const int* edge_index = (const int*)d_in[1];
    const float* edgenet  = (const float*)d_in[2];
    const float* pae_w1 = (const float*)d_in[3];
    const float* pae_b1 = (const float*)d_in[4];
    const float* pae_bn_g = (const float*)d_in[5];
    const float* pae_bn_b = (const float*)d_in[6];
    const float* pae_bn_rm = (const float*)d_in[7];
    const float* pae_bn_rv = (const float*)d_in[8];
    const float* pae_w2 = (const float*)d_in[9];
    const float* pae_b2 = (const float*)d_in[10];
    const float* cheb_w[4] = {(const float*)d_in[11], (const float*)d_in[12],
                              (const float*)d_in[13], (const float*)d_in[14]};
    const float* cls_w1 = (const float*)d_in[15];
    const float* cls_b1 = (const float*)d_in[16];
    const float* cls_bn_g = (const float*)d_in[17];
    const float* cls_bn_b = (const float*)d_in[18];
    const float* cls_bn_rm = (const float*)d_in[19];
    const float* cls_bn_rv = (const float*)d_in[20];
    const float* cls_w2 = (const float*)d_in[21];
    const float* cls_b2 = (const float*)d_in[22];

    int N = in_sizes[0] / 128;
    int E = in_sizes[1] / 2;
    const int* row = edge_index;
    const int* col = edge_index + E;

    float* out = (float*)d_out;
    float* jk = out;
    float* logit = out + (size_t)N * 256;
    float* ew = logit + (size_t)N * 2;

    float *vbuf, *ubuf, *ha, *hb, *dis, *deg, *b2f, *cw2, *cb2;
    uint2* ewp;
    int *rowptr, *cursor, *cnt, *ecol, *eidx;
    __nv_bfloat16 *wt_hi, *wt_lo;
    uint4 *frag_cheb[4], *frag_cls;
    cudaGetSymbolAddress((void**)&vbuf, g_v);
    cudaGetSymbolAddress((void**)&ubuf, g_u);
    cudaGetSymbolAddress((void**)&ha, g_ha);
    cudaGetSymbolAddress((void**)&hb, g_hb);
    cudaGetSymbolAddress((void**)&ewp, g_ewp);
    cudaGetSymbolAddress((void**)&dis, g_dis);
    cudaGetSymbolAddress((void**)&deg, g_deg);
    cudaGetSymbolAddress((void**)&rowptr, g_rowptr);
    cudaGetSymbolAddress((void**)&cursor, g_cursor);
    cudaGetSymbolAddress((void**)&cnt, g_cnt);
    cudaGetSymbolAddress((void**)&ecol, g_ecol);
    cudaGetSymbolAddress((void**)&eidx, g_eidx);
    cudaGetSymbolAddress((void**)&wt_hi, g_w2t_hi);
    cudaGetSymbolAddress((void**)&wt_lo, g_w2t_lo);
    cudaGetSymbolAddress((void**)&b2f, g_b2f);
    cudaGetSymbolAddress((void**)&cw2, g_cw2);
    cudaGetSymbolAddress((void**)&cb2, g_cb2);
    cudaGetSymbolAddress((void**)&frag_cheb[0], g_frag_cheb0);
    cudaGetSymbolAddress((void**)&frag_cheb[1], g_frag_cheb1);
    cudaGetSymbolAddress((void**)&frag_cheb[2], g_frag_cheb2);
    cudaGetSymbolAddress((void**)&frag_cheb[3], g_frag_cheb3);
    cudaGetSymbolAddress((void**)&frag_cls, g_frag_cls);

    cudaFuncSetAttribute(pae_mma_kernel, cudaFuncAttributeMaxDynamicSharedMemorySize, PAE_SMEM);
    cudaFuncSetAttribute(gemm_mma, cudaFuncAttributeMaxDynamicSharedMemorySize, 65536);
    cudaFuncSetAttribute(gemm_mma3, cudaFuncAttributeMaxDynamicSharedMemorySize, 49152);
    cudaFuncSetAttribute(gemm_mma_cls, cudaFuncAttributeMaxDynamicSharedMemorySize, 65536);

    int rowTiles = (N + 127) / 128;
    int rowWarpBlocks = (N * 32 + 255) / 256;

    // ---- fork: side stream does CSR build + weight prep + layer-0 GEMM ----
    cudaEventRecord(g_evF, 0);
    cudaStreamWaitEvent(g_s2, g_evF, 0);

    cudaMemsetAsync(cnt, 0, (size_t)N * sizeof(int), g_s2);
    hist_kernel<<<(E + 255) / 256, 256, 0, g_s2>>>(row, cnt, E);
    scan_kernel<<<1, 1024, 0, g_s2>>>(cnt, N, rowptr, cursor);
    scatter_kernel<<<(E + 255) / 256, 256, 0, g_s2>>>(row, col, cursor, ecol, eidx, E);
    fold_cls_kernel<<<1, 256, 0, g_s2>>>(cls_bn_g, cls_bn_b, cls_bn_rm, cls_bn_rv,
                                         cls_w2, cls_b2, cw2, cb2);
    prep_cheb_frag128<<<24, 256, 0, g_s2>>>(cheb_w[0], frag_cheb[0]);
    prep_cheb_frag64x3<<<dim3(12, 3), 256, 0, g_s2>>>(cheb_w[1], cheb_w[2], cheb_w[3],
                                                      frag_cheb[1], frag_cheb[2], frag_cheb[3]);
    prep_frag<<<64, 256, 0, g_s2>>>(cls_w1, 256, 256, frag_cls);
    logit_init_kernel<<<(N + 255) / 256, 256, 0, g_s2>>>(cb2, logit, N);
    // layer-0 GEMM is graph-independent: u = features @ [W0-W2 | W1 | W2]
    gemm_mma<<<dim3(rowTiles, 3), 256, 8 * 4096, g_s2>>>(
        features, 128, N, frag_cheb[0], 8, 192, ubuf);

    // ---- main stream: PAE (deg accumulated inside) ----
    cudaMemsetAsync(deg, 0, (size_t)N * sizeof(float));
    fold_pae_kernel<<<129, 128>>>(pae_bn_g, pae_bn_b, pae_bn_rm, pae_bn_rv, pae_w2, pae_b2,
                                  wt_hi, wt_lo, b2f);
    pae_mma_kernel<<<148, 256, PAE_SMEM>>>(edgenet, pae_w1, pae_b1, wt_hi, wt_lo, b2f,
                                           row, ew, deg, E);

    // ---- join ----
    cudaEventRecord(g_evJ, g_s2);
    cudaStreamWaitEvent(0, g_evJ, 0);

    // ---- graph normalization ----
    dis_kernel<<<(N + 255) / 256, 256>>>(deg, dis, N);
    ewp_kernel<<<(E + 255) / 256, 256>>>(ew, eidx, ecol, dis, ewp, E);

    // ---- GCN layers (layer 0's GEMM already done on side stream) ----
    float* hbufs[2] = {ha, hb};
    for (int l = 0; l < 4; l++) {
        if (l > 0) {
            gemm_mma3<<<rowTiles, 256, 48 * 1024>>>(
                hbufs[(l - 1) & 1], N, frag_cheb[l], ubuf);
        }
        spmm_v<<<rowWarpBlocks, 256>>>(ubuf, rowptr, ewp, dis, vbuf, N);
        spmm_h<<<rowWarpBlocks, 256>>>(vbuf, ubuf, rowptr, ewp, dis,
                                       hbufs[l & 1], jk + (size_t)l * 64, N);
    }

    // ---- classifier fused with logit ----
    gemm_mma_cls<<<dim3(rowTiles, 4), 256, 16 * 4096>>>(
        jk, 256, N, frag_cls, 16, cls_b1, cw2, logit);
}